// round 4
// baseline (speedup 1.0000x reference)
#include <cuda_runtime.h>
#include <cuda_bf16.h>
#include <cstdint>
#include <math.h>

#define Bn   2
#define Cc   64
#define Hh   224
#define Ww   224
#define HW   (Hh*Ww)
#define NOFF 27
#define COUT 64
#define Jdim 576
#define CH   64
#define NCH  9
#define TILE 128
#define NT   (HW/TILE)     // 392
#define VSTR 72            // padded k-stride (bf16 elems) -> conflict-free LDS
#define OSTR 132           // padded pos-stride for f32 epilogue staging

// ---------------- device globals (no allocation allowed) -------------------
__device__ float g_offmask[Bn*NOFF*HW];                     // conv1 out (mask sigmoided)
__device__ __align__(16) __nv_bfloat16 g_wd[NCH][2][COUT*64]; // deform W [chunk][hi/lo][co][k]
__device__ __align__(16) __nv_bfloat16 g_wo[NCH][2][32*64];   // off/mask W (padded to 32 ch)

// ---------------- mma.sync helper (generic PTX, works on compute_103) ------
__device__ __forceinline__ void mma_bf16(float* c, const uint32_t* a,
                                         uint32_t b0, uint32_t b1) {
    asm volatile("mma.sync.aligned.m16n8k16.row.col.f32.bf16.bf16.f32 "
        "{%0,%1,%2,%3},{%4,%5,%6,%7},{%8,%9},{%0,%1,%2,%3};"
        : "+f"(c[0]), "+f"(c[1]), "+f"(c[2]), "+f"(c[3])
        : "r"(a[0]), "r"(a[1]), "r"(a[2]), "r"(a[3]), "r"(b0), "r"(b1));
}

__device__ __forceinline__ void split_bf16(float v, __nv_bfloat16& hi, __nv_bfloat16& lo) {
    hi = __float2bfloat16(v);
    lo = __float2bfloat16(v - __bfloat162float(hi));
}

// ---------------- prep: split weights to bf16 hi/lo ------------------------
__global__ void prep_weights(const float* __restrict__ w_off,
                             const float* __restrict__ w_mask,
                             const float* __restrict__ w_def) {
    int idx = blockIdx.x * 256 + threadIdx.x;
    if (idx < NCH*COUT*64) {
        int kc = idx / (COUT*64), r = idx % (COUT*64);
        int co = r >> 6, k = r & 63;
        float v = w_def[co*Jdim + kc*CH + k];
        __nv_bfloat16 hi, lo; split_bf16(v, hi, lo);
        g_wd[kc][0][r] = hi;
        g_wd[kc][1][r] = lo;
    } else {
        int i2 = idx - NCH*COUT*64;
        if (i2 < NCH*32*64) {
            int kc = i2 / (32*64), r = i2 % (32*64);
            int co = r >> 6, k = r & 63;
            int j = kc*CH + k;
            float v = 0.f;
            if (co < 18)      v = w_off[co*Jdim + j];
            else if (co < 27) v = w_mask[(co-18)*Jdim + j];
            __nv_bfloat16 hi, lo; split_bf16(v, hi, lo);
            g_wo[kc][0][r] = hi;
            g_wo[kc][1][r] = lo;
        }
    }
}

// ============================================================================
// Kernel 1: offset+mask conv (27ch, padded 32) via mma.sync.  128pos x 32co.
// ============================================================================
#define S1_HO 0
#define S1_WO 512
#define S1_V  1024                       // [2buf][2split][128][VSTR] bf16 = 73728
#define S1_W  (S1_V + 73728)             // [2buf][2split][32][VSTR] bf16 = 18432
#define S1_TOT (S1_W + 18432)            // 93184

__global__ void __launch_bounds__(512, 2) offmask_conv(
        const float* __restrict__ x,
        const float* __restrict__ b_off,
        const float* __restrict__ b_mask) {
    extern __shared__ char smem[];
    const int tid = threadIdx.x, lane = tid & 31, wid = tid >> 5;
    const int hw0 = blockIdx.x * TILE;
    const int b   = blockIdx.y;
    const float* xb = x + (size_t)b * Cc * HW;

    int* sHO = (int*)(smem + S1_HO);
    int* sWO = (int*)(smem + S1_WO);
    if (tid < TILE) {
        int hw = hw0 + tid, ho = hw / Ww;
        sHO[tid] = ho; sWO[tid] = hw - ho*Ww;
    }
    __syncthreads();

    auto stage = [&](int kc, int buf) {
        __nv_bfloat16* vh = (__nv_bfloat16*)(smem + S1_V) + buf*(2*TILE*VSTR);
        __nv_bfloat16* vl = vh + TILE*VSTR;
        #pragma unroll
        for (int p = 0; p < 8; p++) {
            int pos = (wid << 3) + p;
            int ho = sHO[pos], wo = sWO[pos];
            float v[2];
            #pragma unroll
            for (int u = 0; u < 2; u++) {
                int jl = 2*lane + u;
                int j = kc*CH + jl;
                int c = j / 9, k = j - c*9;
                int ky = k / 3, kx = k - ky*3;
                int iy = ho + ky - 1, ix = wo + kx - 1;
                float val = 0.f;
                if ((unsigned)iy < Hh && (unsigned)ix < Ww)
                    val = xb[c*HW + iy*Ww + ix];
                v[u] = val;
            }
            __nv_bfloat162 hp, lp;
            split_bf16(v[0], hp.x, lp.x);
            split_bf16(v[1], hp.y, lp.y);
            *(__nv_bfloat162*)(vh + pos*VSTR + 2*lane) = hp;
            *(__nv_bfloat162*)(vl + pos*VSTR + 2*lane) = lp;
        }
        const uint32_t* src = (const uint32_t*)(&g_wo[kc][0][0]);   // 2048 b32
        uint32_t* wd = (uint32_t*)(smem + S1_W) + buf*(2*32*VSTR/2);
        #pragma unroll
        for (int i = 0; i < 4; i++) {
            int idx = tid + i*512;
            int s = idx >> 10, r = (idx >> 5) & 31, w = idx & 31;
            wd[(s*32 + r)*(VSTR/2) + w] = src[idx];
        }
    };

    const int g = lane >> 2, tig = lane & 3;
    const int R  = (wid >> 1) * 16;
    const int NB = (wid & 1) * 16;
    float acc[2][4] = {};

    stage(0, 0);
    __syncthreads();

    for (int kc = 0; kc < NCH; kc++) {
        int cb = kc & 1;
        if (kc < NCH-1) stage(kc+1, cb ^ 1);
        const __nv_bfloat16* vb = (const __nv_bfloat16*)(smem + S1_V) + cb*(2*TILE*VSTR);
        const __nv_bfloat16* wb = (const __nv_bfloat16*)(smem + S1_W) + cb*(2*32*VSTR);
        #pragma unroll
        for (int ks = 0; ks < 4; ks++) {
            const __nv_bfloat16* ar = vb + (R+g)*VSTR + ks*16 + 2*tig;
            uint32_t ah[4], al[4];
            ah[0] = *(const uint32_t*)ar;
            ah[1] = *(const uint32_t*)(ar + 8*VSTR);
            ah[2] = *(const uint32_t*)(ar + 8);
            ah[3] = *(const uint32_t*)(ar + 8*VSTR + 8);
            const __nv_bfloat16* arl = ar + TILE*VSTR;
            al[0] = *(const uint32_t*)arl;
            al[1] = *(const uint32_t*)(arl + 8*VSTR);
            al[2] = *(const uint32_t*)(arl + 8);
            al[3] = *(const uint32_t*)(arl + 8*VSTR + 8);
            #pragma unroll
            for (int t = 0; t < 2; t++) {
                const __nv_bfloat16* br = wb + (NB + t*8 + g)*VSTR + ks*16 + 2*tig;
                uint32_t bh0 = *(const uint32_t*)br;
                uint32_t bh1 = *(const uint32_t*)(br + 8);
                uint32_t bl0 = *(const uint32_t*)(br + 32*VSTR);
                uint32_t bl1 = *(const uint32_t*)(br + 32*VSTR + 8);
                mma_bf16(acc[t], ah, bh0, bh1);
                mma_bf16(acc[t], ah, bl0, bl1);
                mma_bf16(acc[t], al, bh0, bh1);
            }
        }
        __syncthreads();
    }

    // epilogue: stage [32][pos] f32, then bias+sigmoid, coalesced store
    float* obuf = (float*)(smem + S1_V);
    #pragma unroll
    for (int t = 0; t < 2; t++) {
        int n0 = NB + t*8 + 2*tig;
        obuf[(n0    )*OSTR + R+g    ] = acc[t][0];
        obuf[(n0 + 1)*OSTR + R+g    ] = acc[t][1];
        obuf[(n0    )*OSTR + R+g + 8] = acc[t][2];
        obuf[(n0 + 1)*OSTR + R+g + 8] = acc[t][3];
    }
    __syncthreads();
    float* ob = g_offmask + (size_t)b*NOFF*HW + hw0;
    for (int i = tid; i < NOFF*TILE; i += 512) {
        int co = i >> 7, pos = i & 127;
        float v = obuf[co*OSTR + pos] + (co < 18 ? b_off[co] : b_mask[co-18]);
        if (co >= 18) v = 1.f / (1.f + __expf(-v));
        ob[co*HW + pos] = v;
    }
}

// ============================================================================
// Kernel 2: bilinear gather + main GEMM via mma.sync. 128pos x 64co, K=576.
// ============================================================================
#define S2_PY 0
#define S2_PX 4608
#define S2_PW 9216
#define S2_V  27648                      // [2buf][2split][128][VSTR] = 73728
#define S2_W  (S2_V + 73728)             // [2buf][2split][64][VSTR] = 36864
#define S2_TOT (S2_W + 36864)            // 138240

__global__ void __launch_bounds__(512, 1) deform_main(
        const float* __restrict__ x,
        float* __restrict__ out) {
    extern __shared__ char smem[];
    const int tid = threadIdx.x, lane = tid & 31, wid = tid >> 5;
    const int hw0 = blockIdx.x * TILE;
    const int b   = blockIdx.y;
    const float* xb = x + (size_t)b * Cc * HW;

    int*    pY = (int*)   (smem + S2_PY);
    int*    pX = (int*)   (smem + S2_PX);
    float4* pW = (float4*)(smem + S2_PW);

    // phase 0: bilinear params for 9 x 128 (k2, pos)
    for (int i = tid; i < 9*TILE; i += 512) {
        int pos = i & 127;
        int k2  = i >> 7;
        int hw  = hw0 + pos;
        int ho  = hw / Ww;
        int wo  = hw - ho*Ww;
        const float* om = g_offmask + (size_t)b*NOFF*HW + hw;
        float dy = om[(2*k2    )*HW];
        float dx = om[(2*k2 + 1)*HW];
        float m  = om[(18 + k2 )*HW];
        int ky = k2 / 3, kx = k2 - ky*3;
        float py = dy + (float)(ho - 1 + ky);
        float px = dx + (float)(wo - 1 + kx);
        float fy = floorf(py), fx = floorf(px);
        float wy1 = py - fy, wx1 = px - fx;
        float wy0 = 1.f - wy1, wx0 = 1.f - wx1;
        pY[i] = (int)fy;
        pX[i] = (int)fx;
        pW[i] = make_float4(wy0*wx0*m, wy0*wx1*m, wy1*wx0*m, wy1*wx1*m);
    }
    __syncthreads();

    auto stage = [&](int kc, int buf) {
        __nv_bfloat16* vh = (__nv_bfloat16*)(smem + S2_V) + buf*(2*TILE*VSTR);
        __nv_bfloat16* vl = vh + TILE*VSTR;
        #pragma unroll
        for (int p = 0; p < 8; p++) {
            int pos = (wid << 3) + p;
            float v[2];
            #pragma unroll
            for (int u = 0; u < 2; u++) {
                int jl = 2*lane + u;
                int j = kc*CH + jl;
                int c = j / 9, k2 = j - c*9;
                int pk = (k2 << 7) | pos;
                int y0 = pY[pk], x0 = pX[pk];
                float4 w = pW[pk];
                const float* xc = xb + c*HW;
                bool vy0 = (unsigned)y0     < Hh;
                bool vy1 = (unsigned)(y0+1) < Hh;
                bool vx0 = (unsigned)x0     < Ww;
                bool vx1 = (unsigned)(x0+1) < Ww;
                float val = 0.f;
                if (vy0) { const float* r = xc + y0*Ww;
                    if (vx0) val = fmaf(w.x, r[x0],   val);
                    if (vx1) val = fmaf(w.y, r[x0+1], val); }
                if (vy1) { const float* r = xc + (y0+1)*Ww;
                    if (vx0) val = fmaf(w.z, r[x0],   val);
                    if (vx1) val = fmaf(w.w, r[x0+1], val); }
                v[u] = val;
            }
            __nv_bfloat162 hp, lp;
            split_bf16(v[0], hp.x, lp.x);
            split_bf16(v[1], hp.y, lp.y);
            *(__nv_bfloat162*)(vh + pos*VSTR + 2*lane) = hp;
            *(__nv_bfloat162*)(vl + pos*VSTR + 2*lane) = lp;
        }
        const uint32_t* src = (const uint32_t*)(&g_wd[kc][0][0]);   // 4096 b32
        uint32_t* wd = (uint32_t*)(smem + S2_W) + buf*(2*64*VSTR/2);
        #pragma unroll
        for (int i = 0; i < 8; i++) {
            int idx = tid + i*512;
            int s = idx >> 11, r = (idx >> 5) & 63, w = idx & 31;
            wd[(s*64 + r)*(VSTR/2) + w] = src[idx];
        }
    };

    const int g = lane >> 2, tig = lane & 3;
    const int R  = (wid >> 1) * 16;
    const int NB = (wid & 1) * 32;
    float acc[4][4] = {};

    stage(0, 0);
    __syncthreads();

    for (int kc = 0; kc < NCH; kc++) {
        int cb = kc & 1;
        if (kc < NCH-1) stage(kc+1, cb ^ 1);
        const __nv_bfloat16* vb = (const __nv_bfloat16*)(smem + S2_V) + cb*(2*TILE*VSTR);
        const __nv_bfloat16* wb = (const __nv_bfloat16*)(smem + S2_W) + cb*(2*64*VSTR);
        #pragma unroll
        for (int ks = 0; ks < 4; ks++) {
            const __nv_bfloat16* ar = vb + (R+g)*VSTR + ks*16 + 2*tig;
            uint32_t ah[4], al[4];
            ah[0] = *(const uint32_t*)ar;
            ah[1] = *(const uint32_t*)(ar + 8*VSTR);
            ah[2] = *(const uint32_t*)(ar + 8);
            ah[3] = *(const uint32_t*)(ar + 8*VSTR + 8);
            const __nv_bfloat16* arl = ar + TILE*VSTR;
            al[0] = *(const uint32_t*)arl;
            al[1] = *(const uint32_t*)(arl + 8*VSTR);
            al[2] = *(const uint32_t*)(arl + 8);
            al[3] = *(const uint32_t*)(arl + 8*VSTR + 8);
            #pragma unroll
            for (int t = 0; t < 4; t++) {
                const __nv_bfloat16* br = wb + (NB + t*8 + g)*VSTR + ks*16 + 2*tig;
                uint32_t bh0 = *(const uint32_t*)br;
                uint32_t bh1 = *(const uint32_t*)(br + 8);
                uint32_t bl0 = *(const uint32_t*)(br + 64*VSTR);
                uint32_t bl1 = *(const uint32_t*)(br + 64*VSTR + 8);
                mma_bf16(acc[t], ah, bh0, bh1);
                mma_bf16(acc[t], ah, bl0, bl1);
                mma_bf16(acc[t], al, bh0, bh1);
            }
        }
        __syncthreads();
    }

    // epilogue: stage [64][pos] f32 in smem, then coalesced float4 stores
    float* obuf = (float*)(smem + S2_V);
    #pragma unroll
    for (int t = 0; t < 4; t++) {
        int n0 = NB + t*8 + 2*tig;
        obuf[(n0    )*OSTR + R+g    ] = acc[t][0];
        obuf[(n0 + 1)*OSTR + R+g    ] = acc[t][1];
        obuf[(n0    )*OSTR + R+g + 8] = acc[t][2];
        obuf[(n0 + 1)*OSTR + R+g + 8] = acc[t][3];
    }
    __syncthreads();
    float* ob = out + (size_t)b*COUT*HW + hw0;
    for (int i = tid; i < COUT*32; i += 512) {
        int co = i >> 5, q = i & 31;
        float4 v = *(float4*)&obuf[co*OSTR + q*4];
        *(float4*)&ob[co*HW + q*4] = v;
    }
}

// ---------------------------------------------------------------------------
extern "C" void kernel_launch(void* const* d_in, const int* in_sizes, int n_in,
                              void* d_out, int out_size) {
    const float* x      = (const float*)d_in[0];
    const float* w_off  = (const float*)d_in[1];
    const float* b_off  = (const float*)d_in[2];
    const float* w_mask = (const float*)d_in[3];
    const float* b_mask = (const float*)d_in[4];
    const float* w_def  = (const float*)d_in[5];
    float* out = (float*)d_out;

    cudaFuncSetAttribute(offmask_conv, cudaFuncAttributeMaxDynamicSharedMemorySize, S1_TOT);
    cudaFuncSetAttribute(deform_main,  cudaFuncAttributeMaxDynamicSharedMemorySize, S2_TOT);

    prep_weights<<<216, 256>>>(w_off, w_mask, w_def);
    offmask_conv<<<dim3(NT, Bn), 512, S1_TOT>>>(x, b_off, b_mask);
    deform_main <<<dim3(NT, Bn), 512, S2_TOT>>>(x, out);
}

// round 5
// speedup vs baseline: 2.3724x; 2.3724x over previous
#include <cuda_runtime.h>
#include <cuda_bf16.h>
#include <cstdint>
#include <math.h>

#define Bn   2
#define Cc   64
#define Hh   224
#define Ww   224
#define HW   (Hh*Ww)
#define NOFF 27
#define COUT 64
#define Jdim 576
#define CH   64
#define NCH  9
#define TILE 128
#define NT   (HW/TILE)     // 392
#define VSTR 72            // padded k-stride (bf16 elems) -> conflict-free
#define OSTR 132           // padded pos-stride for f32 epilogue staging

// ---------------- device globals (no allocation allowed) -------------------
__device__ float g_offmask[Bn*NOFF*HW];                     // conv1 out (mask sigmoided)
__device__ __align__(16) __nv_bfloat16 g_wd[NCH][2][COUT*64]; // deform W [chunk][hi/lo][co][k]
__device__ __align__(16) __nv_bfloat16 g_wo[NCH][2][32*64];   // off/mask W (padded to 32 ch)

// ---------------- mma.sync helper (generic PTX, works on compute_103) ------
__device__ __forceinline__ void mma_bf16(float* c, const uint32_t* a,
                                         uint32_t b0, uint32_t b1) {
    asm volatile("mma.sync.aligned.m16n8k16.row.col.f32.bf16.bf16.f32 "
        "{%0,%1,%2,%3},{%4,%5,%6,%7},{%8,%9},{%0,%1,%2,%3};"
        : "+f"(c[0]), "+f"(c[1]), "+f"(c[2]), "+f"(c[3])
        : "r"(a[0]), "r"(a[1]), "r"(a[2]), "r"(a[3]), "r"(b0), "r"(b1));
}

__device__ __forceinline__ void split_bf16(float v, __nv_bfloat16& hi, __nv_bfloat16& lo) {
    hi = __float2bfloat16(v);
    lo = __float2bfloat16(v - __bfloat162float(hi));
}

// ---------------- prep: split weights to bf16 hi/lo ------------------------
__global__ void prep_weights(const float* __restrict__ w_off,
                             const float* __restrict__ w_mask,
                             const float* __restrict__ w_def) {
    int idx = blockIdx.x * 256 + threadIdx.x;
    if (idx < NCH*COUT*64) {
        int kc = idx / (COUT*64), r = idx % (COUT*64);
        int co = r >> 6, k = r & 63;
        float v = w_def[co*Jdim + kc*CH + k];
        __nv_bfloat16 hi, lo; split_bf16(v, hi, lo);
        g_wd[kc][0][r] = hi;
        g_wd[kc][1][r] = lo;
    } else {
        int i2 = idx - NCH*COUT*64;
        if (i2 < NCH*32*64) {
            int kc = i2 / (32*64), r = i2 % (32*64);
            int co = r >> 6, k = r & 63;
            int j = kc*CH + k;
            float v = 0.f;
            if (co < 18)      v = w_off[co*Jdim + j];
            else if (co < 27) v = w_mask[(co-18)*Jdim + j];
            __nv_bfloat16 hi, lo; split_bf16(v, hi, lo);
            g_wo[kc][0][r] = hi;
            g_wo[kc][1][r] = lo;
        }
    }
}

// ============================================================================
// Kernel 1: offset+mask conv (27ch, padded 32) via mma.sync.  128pos x 32co.
// ============================================================================
#define S1_HO 0
#define S1_WO 512
#define S1_V  1024                       // [2buf][2split][128][VSTR] bf16 = 73728
#define S1_W  (S1_V + 73728)             // [2buf][2split][32][VSTR] bf16 = 18432
#define S1_TOT (S1_W + 18432)            // 93184

__global__ void __launch_bounds__(512, 2) offmask_conv(
        const float* __restrict__ x,
        const float* __restrict__ b_off,
        const float* __restrict__ b_mask) {
    extern __shared__ char smem[];
    const int tid = threadIdx.x, lane = tid & 31, wid = tid >> 5;
    const int hw0 = blockIdx.x * TILE;
    const int b   = blockIdx.y;
    const float* xb = x + (size_t)b * Cc * HW;

    int* sHO = (int*)(smem + S1_HO);
    int* sWO = (int*)(smem + S1_WO);
    if (tid < TILE) {
        int hw = hw0 + tid, ho = hw / Ww;
        sHO[tid] = ho; sWO[tid] = hw - ho*Ww;
    }
    __syncthreads();

    // pos across lanes (coalesced LDG), 8 consecutive j per thread (STS.128)
    auto stage = [&](int kc, int buf) {
        __nv_bfloat16* vh = (__nv_bfloat16*)(smem + S1_V) + buf*(2*TILE*VSTR);
        __nv_bfloat16* vl = vh + TILE*VSTR;
        #pragma unroll
        for (int t = 0; t < 2; t++) {
            int task = tid + t*512;
            int pos = task & 127;
            int jg  = task >> 7;           // 0..7
            int ho = sHO[pos], wo = sWO[pos];
            float v[8];
            #pragma unroll
            for (int u = 0; u < 8; u++) {
                int j = kc*CH + jg*8 + u;
                int c = j / 9, k = j - c*9;
                int ky = k / 3, kx = k - ky*3;
                int iy = ho + ky - 1, ix = wo + kx - 1;
                float val = 0.f;
                if ((unsigned)iy < Hh && (unsigned)ix < Ww)
                    val = xb[c*HW + iy*Ww + ix];
                v[u] = val;
            }
            __nv_bfloat16 h8[8], l8[8];
            #pragma unroll
            for (int u = 0; u < 8; u++) split_bf16(v[u], h8[u], l8[u]);
            *(uint4*)(vh + pos*VSTR + jg*8) = *(uint4*)h8;
            *(uint4*)(vl + pos*VSTR + jg*8) = *(uint4*)l8;
        }
        const uint32_t* src = (const uint32_t*)(&g_wo[kc][0][0]);   // 2048 b32
        uint32_t* wd = (uint32_t*)(smem + S1_W) + buf*(2*32*VSTR/2);
        #pragma unroll
        for (int i = 0; i < 4; i++) {
            int idx = tid + i*512;
            int s = idx >> 10, r = (idx >> 5) & 31, w = idx & 31;
            wd[(s*32 + r)*(VSTR/2) + w] = src[idx];
        }
    };

    const int g = lane >> 2, tig = lane & 3;
    const int R  = (wid >> 1) * 16;
    const int NB = (wid & 1) * 16;
    float acc[2][4] = {};

    stage(0, 0);
    __syncthreads();

    for (int kc = 0; kc < NCH; kc++) {
        int cb = kc & 1;
        if (kc < NCH-1) stage(kc+1, cb ^ 1);
        const __nv_bfloat16* vb = (const __nv_bfloat16*)(smem + S1_V) + cb*(2*TILE*VSTR);
        const __nv_bfloat16* wb = (const __nv_bfloat16*)(smem + S1_W) + cb*(2*32*VSTR);
        #pragma unroll
        for (int ks = 0; ks < 4; ks++) {
            const __nv_bfloat16* ar = vb + (R+g)*VSTR + ks*16 + 2*tig;
            uint32_t ah[4], al[4];
            ah[0] = *(const uint32_t*)ar;
            ah[1] = *(const uint32_t*)(ar + 8*VSTR);
            ah[2] = *(const uint32_t*)(ar + 8);
            ah[3] = *(const uint32_t*)(ar + 8*VSTR + 8);
            const __nv_bfloat16* arl = ar + TILE*VSTR;
            al[0] = *(const uint32_t*)arl;
            al[1] = *(const uint32_t*)(arl + 8*VSTR);
            al[2] = *(const uint32_t*)(arl + 8);
            al[3] = *(const uint32_t*)(arl + 8*VSTR + 8);
            #pragma unroll
            for (int t = 0; t < 2; t++) {
                const __nv_bfloat16* br = wb + (NB + t*8 + g)*VSTR + ks*16 + 2*tig;
                uint32_t bh0 = *(const uint32_t*)br;
                uint32_t bh1 = *(const uint32_t*)(br + 8);
                uint32_t bl0 = *(const uint32_t*)(br + 32*VSTR);
                uint32_t bl1 = *(const uint32_t*)(br + 32*VSTR + 8);
                mma_bf16(acc[t], ah, bh0, bh1);
                mma_bf16(acc[t], ah, bl0, bl1);
                mma_bf16(acc[t], al, bh0, bh1);
            }
        }
        __syncthreads();
    }

    // epilogue: stage [32][pos] f32, then bias+sigmoid, coalesced store
    float* obuf = (float*)(smem + S1_V);
    #pragma unroll
    for (int t = 0; t < 2; t++) {
        int n0 = NB + t*8 + 2*tig;
        obuf[(n0    )*OSTR + R+g    ] = acc[t][0];
        obuf[(n0 + 1)*OSTR + R+g    ] = acc[t][1];
        obuf[(n0    )*OSTR + R+g + 8] = acc[t][2];
        obuf[(n0 + 1)*OSTR + R+g + 8] = acc[t][3];
    }
    __syncthreads();
    float* ob = g_offmask + (size_t)b*NOFF*HW + hw0;
    for (int i = tid; i < NOFF*TILE; i += 512) {
        int co = i >> 7, pos = i & 127;
        float v = obuf[co*OSTR + pos] + (co < 18 ? b_off[co] : b_mask[co-18]);
        if (co >= 18) v = 1.f / (1.f + __expf(-v));
        ob[co*HW + pos] = v;
    }
}

// ============================================================================
// Kernel 2: bilinear gather + main GEMM via mma.sync. 128pos x 64co, K=576.
// ============================================================================
#define S2_PY 0
#define S2_PX 4608
#define S2_PW 9216
#define S2_V  27648                      // [2buf][2split][128][VSTR] = 73728
#define S2_W  (S2_V + 73728)             // [2buf][2split][64][VSTR] = 36864
#define S2_TOT (S2_W + 36864)            // 138240

__global__ void __launch_bounds__(512, 1) deform_main(
        const float* __restrict__ x,
        float* __restrict__ out) {
    extern __shared__ char smem[];
    const int tid = threadIdx.x, lane = tid & 31, wid = tid >> 5;
    const int hw0 = blockIdx.x * TILE;
    const int b   = blockIdx.y;
    const float* xb = x + (size_t)b * Cc * HW;

    int*    pY = (int*)   (smem + S2_PY);
    int*    pX = (int*)   (smem + S2_PX);
    float4* pW = (float4*)(smem + S2_PW);

    // phase 0: bilinear params for 9 x 128 (k2, pos)
    for (int i = tid; i < 9*TILE; i += 512) {
        int pos = i & 127;
        int k2  = i >> 7;
        int hw  = hw0 + pos;
        int ho  = hw / Ww;
        int wo  = hw - ho*Ww;
        const float* om = g_offmask + (size_t)b*NOFF*HW + hw;
        float dy = om[(2*k2    )*HW];
        float dx = om[(2*k2 + 1)*HW];
        float m  = om[(18 + k2 )*HW];
        int ky = k2 / 3, kx = k2 - ky*3;
        float py = dy + (float)(ho - 1 + ky);
        float px = dx + (float)(wo - 1 + kx);
        float fy = floorf(py), fx = floorf(px);
        float wy1 = py - fy, wx1 = px - fx;
        float wy0 = 1.f - wy1, wx0 = 1.f - wx1;
        pY[i] = (int)fy;
        pX[i] = (int)fx;
        pW[i] = make_float4(wy0*wx0*m, wy0*wx1*m, wy1*wx0*m, wy1*wx1*m);
    }
    __syncthreads();

    // pos across lanes (coalesced LDG), 8 consecutive j per thread (STS.128)
    auto stage = [&](int kc, int buf) {
        __nv_bfloat16* vh = (__nv_bfloat16*)(smem + S2_V) + buf*(2*TILE*VSTR);
        __nv_bfloat16* vl = vh + TILE*VSTR;
        #pragma unroll
        for (int t = 0; t < 2; t++) {
            int task = tid + t*512;
            int pos = task & 127;
            int jg  = task >> 7;           // 0..7
            float v[8];
            #pragma unroll
            for (int u = 0; u < 8; u++) {
                int j = kc*CH + jg*8 + u;
                int c = j / 9, k2 = j - c*9;
                int pk = (k2 << 7) | pos;
                int y0 = pY[pk], x0 = pX[pk];
                float4 w = pW[pk];
                const float* xc = xb + c*HW;
                bool vy0 = (unsigned)y0     < Hh;
                bool vy1 = (unsigned)(y0+1) < Hh;
                bool vx0 = (unsigned)x0     < Ww;
                bool vx1 = (unsigned)(x0+1) < Ww;
                float val = 0.f;
                if (vy0) { const float* r = xc + y0*Ww;
                    if (vx0) val = fmaf(w.x, r[x0],   val);
                    if (vx1) val = fmaf(w.y, r[x0+1], val); }
                if (vy1) { const float* r = xc + (y0+1)*Ww;
                    if (vx0) val = fmaf(w.z, r[x0],   val);
                    if (vx1) val = fmaf(w.w, r[x0+1], val); }
                v[u] = val;
            }
            __nv_bfloat16 h8[8], l8[8];
            #pragma unroll
            for (int u = 0; u < 8; u++) split_bf16(v[u], h8[u], l8[u]);
            *(uint4*)(vh + pos*VSTR + jg*8) = *(uint4*)h8;
            *(uint4*)(vl + pos*VSTR + jg*8) = *(uint4*)l8;
        }
        const uint32_t* src = (const uint32_t*)(&g_wd[kc][0][0]);   // 4096 b32
        uint32_t* wd = (uint32_t*)(smem + S2_W) + buf*(2*64*VSTR/2);
        #pragma unroll
        for (int i = 0; i < 8; i++) {
            int idx = tid + i*512;
            int s = idx >> 11, r = (idx >> 5) & 63, w = idx & 31;
            wd[(s*64 + r)*(VSTR/2) + w] = src[idx];
        }
    };

    const int g = lane >> 2, tig = lane & 3;
    const int R  = (wid >> 1) * 16;
    const int NB = (wid & 1) * 32;
    float acc[4][4] = {};

    stage(0, 0);
    __syncthreads();

    for (int kc = 0; kc < NCH; kc++) {
        int cb = kc & 1;
        if (kc < NCH-1) stage(kc+1, cb ^ 1);
        const __nv_bfloat16* vb = (const __nv_bfloat16*)(smem + S2_V) + cb*(2*TILE*VSTR);
        const __nv_bfloat16* wb = (const __nv_bfloat16*)(smem + S2_W) + cb*(2*64*VSTR);
        #pragma unroll
        for (int ks = 0; ks < 4; ks++) {
            const __nv_bfloat16* ar = vb + (R+g)*VSTR + ks*16 + 2*tig;
            uint32_t ah[4], al[4];
            ah[0] = *(const uint32_t*)ar;
            ah[1] = *(const uint32_t*)(ar + 8*VSTR);
            ah[2] = *(const uint32_t*)(ar + 8);
            ah[3] = *(const uint32_t*)(ar + 8*VSTR + 8);
            const __nv_bfloat16* arl = ar + TILE*VSTR;
            al[0] = *(const uint32_t*)arl;
            al[1] = *(const uint32_t*)(arl + 8*VSTR);
            al[2] = *(const uint32_t*)(arl + 8);
            al[3] = *(const uint32_t*)(arl + 8*VSTR + 8);
            #pragma unroll
            for (int t = 0; t < 4; t++) {
                const __nv_bfloat16* br = wb + (NB + t*8 + g)*VSTR + ks*16 + 2*tig;
                uint32_t bh0 = *(const uint32_t*)br;
                uint32_t bh1 = *(const uint32_t*)(br + 8);
                uint32_t bl0 = *(const uint32_t*)(br + 64*VSTR);
                uint32_t bl1 = *(const uint32_t*)(br + 64*VSTR + 8);
                mma_bf16(acc[t], ah, bh0, bh1);
                mma_bf16(acc[t], ah, bl0, bl1);
                mma_bf16(acc[t], al, bh0, bh1);
            }
        }
        __syncthreads();
    }

    // epilogue: stage [64][pos] f32 in smem, then coalesced float4 stores
    float* obuf = (float*)(smem + S2_V);
    #pragma unroll
    for (int t = 0; t < 4; t++) {
        int n0 = NB + t*8 + 2*tig;
        obuf[(n0    )*OSTR + R+g    ] = acc[t][0];
        obuf[(n0 + 1)*OSTR + R+g    ] = acc[t][1];
        obuf[(n0    )*OSTR + R+g + 8] = acc[t][2];
        obuf[(n0 + 1)*OSTR + R+g + 8] = acc[t][3];
    }
    __syncthreads();
    float* ob = out + (size_t)b*COUT*HW + hw0;
    for (int i = tid; i < COUT*32; i += 512) {
        int co = i >> 5, q = i & 31;
        float4 v = *(float4*)&obuf[co*OSTR + q*4];
        *(float4*)&ob[co*HW + q*4] = v;
    }
}

// ---------------------------------------------------------------------------
extern "C" void kernel_launch(void* const* d_in, const int* in_sizes, int n_in,
                              void* d_out, int out_size) {
    const float* x      = (const float*)d_in[0];
    const float* w_off  = (const float*)d_in[1];
    const float* b_off  = (const float*)d_in[2];
    const float* w_mask = (const float*)d_in[3];
    const float* b_mask = (const float*)d_in[4];
    const float* w_def  = (const float*)d_in[5];
    float* out = (float*)d_out;

    cudaFuncSetAttribute(offmask_conv, cudaFuncAttributeMaxDynamicSharedMemorySize, S1_TOT);
    cudaFuncSetAttribute(deform_main,  cudaFuncAttributeMaxDynamicSharedMemorySize, S2_TOT);

    prep_weights<<<216, 256>>>(w_off, w_mask, w_def);
    offmask_conv<<<dim3(NT, Bn), 512, S1_TOT>>>(x, b_off, b_mask);
    deform_main <<<dim3(NT, Bn), 512, S2_TOT>>>(x, out);
}

// round 6
// speedup vs baseline: 3.1627x; 1.3331x over previous
#include <cuda_runtime.h>
#include <cuda_bf16.h>
#include <cstdint>
#include <math.h>

#define Bn   2
#define Cc   64
#define Hh   224
#define Ww   224
#define HW   (Hh*Ww)
#define NOFF 27
#define COUT 64
#define Jdim 576
#define CH   64
#define NCH  9
#define TILE 128
#define NT   (HW/TILE)     // 392
#define VSTR 72            // padded k-stride (bf16 elems) -> conflict-free
#define OSTR 132           // padded pos-stride for f32 epilogue staging

// ---------------- device globals (no allocation allowed) -------------------
__device__ float g_offmask[Bn*NOFF*HW];                     // conv1 out (mask sigmoided)
__device__ __align__(16) __nv_bfloat16 g_wd[NCH][2][COUT*64]; // deform W [chunk][hi/lo][co][k]
__device__ __align__(16) __nv_bfloat16 g_wo[NCH][2][32*64];   // off/mask W (padded to 32 ch)

// ---------------- mma.sync helper (generic PTX, works on compute_103) ------
__device__ __forceinline__ void mma_bf16(float* c, const uint32_t* a,
                                         uint32_t b0, uint32_t b1) {
    asm volatile("mma.sync.aligned.m16n8k16.row.col.f32.bf16.bf16.f32 "
        "{%0,%1,%2,%3},{%4,%5,%6,%7},{%8,%9},{%0,%1,%2,%3};"
        : "+f"(c[0]), "+f"(c[1]), "+f"(c[2]), "+f"(c[3])
        : "r"(a[0]), "r"(a[1]), "r"(a[2]), "r"(a[3]), "r"(b0), "r"(b1));
}

__device__ __forceinline__ void split_bf16(float v, __nv_bfloat16& hi, __nv_bfloat16& lo) {
    hi = __float2bfloat16(v);
    lo = __float2bfloat16(v - __bfloat162float(hi));
}

// pack two floats -> bf16x2 (hi), and residual bf16x2 (lo) in few instrs
__device__ __forceinline__ void split2_bf16(float v0, float v1,
                                            uint32_t& hp, uint32_t& lp) {
    asm("cvt.rn.bf16x2.f32 %0, %1, %2;" : "=r"(hp) : "f"(v1), "f"(v0));
    float f0 = __uint_as_float(hp << 16);
    float f1 = __uint_as_float(hp & 0xffff0000u);
    float r0 = v0 - f0, r1 = v1 - f1;
    asm("cvt.rn.bf16x2.f32 %0, %1, %2;" : "=r"(lp) : "f"(r1), "f"(r0));
}

// ---------------- prep: split weights to bf16 hi/lo ------------------------
__global__ void prep_weights(const float* __restrict__ w_off,
                             const float* __restrict__ w_mask,
                             const float* __restrict__ w_def) {
    int idx = blockIdx.x * 256 + threadIdx.x;
    if (idx < NCH*COUT*64) {
        int kc = idx / (COUT*64), r = idx % (COUT*64);
        int co = r >> 6, k = r & 63;
        float v = w_def[co*Jdim + kc*CH + k];
        __nv_bfloat16 hi, lo; split_bf16(v, hi, lo);
        g_wd[kc][0][r] = hi;
        g_wd[kc][1][r] = lo;
    } else {
        int i2 = idx - NCH*COUT*64;
        if (i2 < NCH*32*64) {
            int kc = i2 / (32*64), r = i2 % (32*64);
            int co = r >> 6, k = r & 63;
            int j = kc*CH + k;
            float v = 0.f;
            if (co < 18)      v = w_off[co*Jdim + j];
            else if (co < 27) v = w_mask[(co-18)*Jdim + j];
            __nv_bfloat16 hi, lo; split_bf16(v, hi, lo);
            g_wo[kc][0][r] = hi;
            g_wo[kc][1][r] = lo;
        }
    }
}

// ============================================================================
// Kernel 1: offset+mask conv (27ch, padded 32) via mma.sync.  128pos x 32co.
// ============================================================================
#define S1_HO 0
#define S1_WO 512
#define S1_V  1024                       // [2buf][2split][128][VSTR] bf16 = 73728
#define S1_W  (S1_V + 73728)             // [2buf][2split][32][VSTR] bf16 = 18432
#define S1_TOT (S1_W + 18432)            // 93184

__global__ void __launch_bounds__(512, 2) offmask_conv(
        const float* __restrict__ x,
        const float* __restrict__ b_off,
        const float* __restrict__ b_mask) {
    extern __shared__ char smem[];
    const int tid = threadIdx.x, lane = tid & 31, wid = tid >> 5;
    const int hw0 = blockIdx.x * TILE;
    const int b   = blockIdx.y;
    const float* xb = x + (size_t)b * Cc * HW;

    int* sHO = (int*)(smem + S1_HO);
    int* sWO = (int*)(smem + S1_WO);
    if (tid < TILE) {
        int hw = hw0 + tid, ho = hw / Ww;
        sHO[tid] = ho; sWO[tid] = hw - ho*Ww;
    }
    __syncthreads();

    // pos across lanes (coalesced LDG), 8 consecutive j per thread (STS.128)
    auto stage = [&](int kc, int buf) {
        __nv_bfloat16* vh = (__nv_bfloat16*)(smem + S1_V) + buf*(2*TILE*VSTR);
        __nv_bfloat16* vl = vh + TILE*VSTR;
        #pragma unroll
        for (int t = 0; t < 2; t++) {
            int task = tid + t*512;
            int pos = task & 127;
            int jg  = task >> 7;           // 0..7
            int ho = sHO[pos], wo = sWO[pos];
            int jb = kc*CH + jg*8;
            int c  = jb / 9, k = jb - c*9;
            const float* xc = xb + c*HW;
            float v[8];
            #pragma unroll
            for (int u = 0; u < 8; u++) {
                int ky = k / 3, kx = k - ky*3;
                int iy = ho + ky - 1, ix = wo + kx - 1;
                float val = 0.f;
                if ((unsigned)iy < Hh && (unsigned)ix < Ww)
                    val = xc[iy*Ww + ix];
                v[u] = val;
                if (++k == 9) { k = 0; xc += HW; }
            }
            uint32_t h4[4], l4[4];
            #pragma unroll
            for (int u = 0; u < 4; u++)
                split2_bf16(v[2*u], v[2*u+1], h4[u], l4[u]);
            *(uint4*)(vh + pos*VSTR + jg*8) = *(uint4*)h4;
            *(uint4*)(vl + pos*VSTR + jg*8) = *(uint4*)l4;
        }
        const uint32_t* src = (const uint32_t*)(&g_wo[kc][0][0]);   // 2048 b32
        uint32_t* wd = (uint32_t*)(smem + S1_W) + buf*(2*32*VSTR/2);
        #pragma unroll
        for (int i = 0; i < 4; i++) {
            int idx = tid + i*512;
            int s = idx >> 10, r = (idx >> 5) & 31, w = idx & 31;
            wd[(s*32 + r)*(VSTR/2) + w] = src[idx];
        }
    };

    const int g = lane >> 2, tig = lane & 3;
    const int R  = (wid >> 1) * 16;
    const int NB = (wid & 1) * 16;
    float acc[2][4] = {};

    stage(0, 0);
    __syncthreads();

    for (int kc = 0; kc < NCH; kc++) {
        int cb = kc & 1;
        if (kc < NCH-1) stage(kc+1, cb ^ 1);
        const __nv_bfloat16* vb = (const __nv_bfloat16*)(smem + S1_V) + cb*(2*TILE*VSTR);
        const __nv_bfloat16* wb = (const __nv_bfloat16*)(smem + S1_W) + cb*(2*32*VSTR);
        #pragma unroll
        for (int ks = 0; ks < 4; ks++) {
            const __nv_bfloat16* ar = vb + (R+g)*VSTR + ks*16 + 2*tig;
            uint32_t ah[4], al[4];
            ah[0] = *(const uint32_t*)ar;
            ah[1] = *(const uint32_t*)(ar + 8*VSTR);
            ah[2] = *(const uint32_t*)(ar + 8);
            ah[3] = *(const uint32_t*)(ar + 8*VSTR + 8);
            const __nv_bfloat16* arl = ar + TILE*VSTR;
            al[0] = *(const uint32_t*)arl;
            al[1] = *(const uint32_t*)(arl + 8*VSTR);
            al[2] = *(const uint32_t*)(arl + 8);
            al[3] = *(const uint32_t*)(arl + 8*VSTR + 8);
            #pragma unroll
            for (int t = 0; t < 2; t++) {
                const __nv_bfloat16* br = wb + (NB + t*8 + g)*VSTR + ks*16 + 2*tig;
                uint32_t bh0 = *(const uint32_t*)br;
                uint32_t bh1 = *(const uint32_t*)(br + 8);
                uint32_t bl0 = *(const uint32_t*)(br + 32*VSTR);
                uint32_t bl1 = *(const uint32_t*)(br + 32*VSTR + 8);
                mma_bf16(acc[t], ah, bh0, bh1);
                mma_bf16(acc[t], ah, bl0, bl1);
                mma_bf16(acc[t], al, bh0, bh1);
            }
        }
        __syncthreads();
    }

    // epilogue: stage [32][pos] f32, then bias+sigmoid, coalesced store
    float* obuf = (float*)(smem + S1_V);
    #pragma unroll
    for (int t = 0; t < 2; t++) {
        int n0 = NB + t*8 + 2*tig;
        obuf[(n0    )*OSTR + R+g    ] = acc[t][0];
        obuf[(n0 + 1)*OSTR + R+g    ] = acc[t][1];
        obuf[(n0    )*OSTR + R+g + 8] = acc[t][2];
        obuf[(n0 + 1)*OSTR + R+g + 8] = acc[t][3];
    }
    __syncthreads();
    float* ob = g_offmask + (size_t)b*NOFF*HW + hw0;
    for (int i = tid; i < NOFF*TILE; i += 512) {
        int co = i >> 7, pos = i & 127;
        float v = obuf[co*OSTR + pos] + (co < 18 ? b_off[co] : b_mask[co-18]);
        if (co >= 18) v = 1.f / (1.f + __expf(-v));
        ob[co*HW + pos] = v;
    }
}

// ============================================================================
// Kernel 2: bilinear gather + main GEMM via mma.sync. 128pos x 64co, K=576.
// Branch-free gather: per (k2,pos) precomputed clamped corner indices (int4)
// and validity/mask-folded corner weights (float4).
// ============================================================================
#define S2_PI 0                          // int4 [9*128] = 18432
#define S2_PW 18432                      // float4[9*128] = 18432
#define S2_V  36864                      // [2buf][2split][128][VSTR] = 73728
#define S2_W  (S2_V + 73728)             // [2buf][2split][64][VSTR] = 36864
#define S2_TOT (S2_W + 36864)            // 147456

__global__ void __launch_bounds__(512, 1) deform_main(
        const float* __restrict__ x,
        float* __restrict__ out) {
    extern __shared__ char smem[];
    const int tid = threadIdx.x, lane = tid & 31, wid = tid >> 5;
    const int hw0 = blockIdx.x * TILE;
    const int b   = blockIdx.y;
    const float* xb = x + (size_t)b * Cc * HW;

    int4*   pI = (int4*)  (smem + S2_PI);
    float4* pW = (float4*)(smem + S2_PW);

    // phase 0: clamped corner indices + validity/mask-folded weights
    for (int i = tid; i < 9*TILE; i += 512) {
        int pos = i & 127;
        int k2  = i >> 7;
        int hw  = hw0 + pos;
        int ho  = hw / Ww;
        int wo  = hw - ho*Ww;
        const float* om = g_offmask + (size_t)b*NOFF*HW + hw;
        float dy = om[(2*k2    )*HW];
        float dx = om[(2*k2 + 1)*HW];
        float m  = om[(18 + k2 )*HW];
        int ky = k2 / 3, kx = k2 - ky*3;
        float py = dy + (float)(ho - 1 + ky);
        float px = dx + (float)(wo - 1 + kx);
        float fy = floorf(py), fx = floorf(px);
        float wy1 = py - fy, wx1 = px - fx;
        float wy0 = 1.f - wy1, wx0 = 1.f - wx1;
        int y0 = (int)fy, x0 = (int)fx;
        int y1 = y0 + 1,  x1 = x0 + 1;
        float vy0 = ((unsigned)y0 < Hh) ? 1.f : 0.f;
        float vy1 = ((unsigned)y1 < Hh) ? 1.f : 0.f;
        float vx0 = ((unsigned)x0 < Ww) ? 1.f : 0.f;
        float vx1 = ((unsigned)x1 < Ww) ? 1.f : 0.f;
        int y0c = min(max(y0, 0), Hh-1), y1c = min(max(y1, 0), Hh-1);
        int x0c = min(max(x0, 0), Ww-1), x1c = min(max(x1, 0), Ww-1);
        pI[i] = make_int4(y0c*Ww + x0c, y0c*Ww + x1c,
                          y1c*Ww + x0c, y1c*Ww + x1c);
        pW[i] = make_float4(wy0*wx0*m*vy0*vx0, wy0*wx1*m*vy0*vx1,
                            wy1*wx0*m*vy1*vx0, wy1*wx1*m*vy1*vx1);
    }
    __syncthreads();

    // pos across lanes (coalesced LDG), 8 consecutive j per thread (STS.128)
    auto stage = [&](int kc, int buf) {
        __nv_bfloat16* vh = (__nv_bfloat16*)(smem + S2_V) + buf*(2*TILE*VSTR);
        __nv_bfloat16* vl = vh + TILE*VSTR;
        #pragma unroll
        for (int t = 0; t < 2; t++) {
            int task = tid + t*512;
            int pos = task & 127;
            int jg  = task >> 7;           // 0..7
            int jb = kc*CH + jg*8;
            int c  = jb / 9, k2 = jb - c*9;
            const float* xc = xb + c*HW;
            float v[8];
            #pragma unroll
            for (int u = 0; u < 8; u++) {
                int pk = (k2 << 7) | pos;
                int4   id = pI[pk];
                float4 w  = pW[pk];
                float val;
                val = w.x * xc[id.x];
                val = fmaf(w.y, xc[id.y], val);
                val = fmaf(w.z, xc[id.z], val);
                val = fmaf(w.w, xc[id.w], val);
                v[u] = val;
                if (++k2 == 9) { k2 = 0; xc += HW; }
            }
            uint32_t h4[4], l4[4];
            #pragma unroll
            for (int u = 0; u < 4; u++)
                split2_bf16(v[2*u], v[2*u+1], h4[u], l4[u]);
            *(uint4*)(vh + pos*VSTR + jg*8) = *(uint4*)h4;
            *(uint4*)(vl + pos*VSTR + jg*8) = *(uint4*)l4;
        }
        const uint32_t* src = (const uint32_t*)(&g_wd[kc][0][0]);   // 4096 b32
        uint32_t* wd = (uint32_t*)(smem + S2_W) + buf*(2*64*VSTR/2);
        #pragma unroll
        for (int i = 0; i < 8; i++) {
            int idx = tid + i*512;
            int s = idx >> 11, r = (idx >> 5) & 63, w = idx & 31;
            wd[(s*64 + r)*(VSTR/2) + w] = src[idx];
        }
    };

    const int g = lane >> 2, tig = lane & 3;
    const int R  = (wid >> 1) * 16;
    const int NB = (wid & 1) * 32;
    float acc[4][4] = {};

    stage(0, 0);
    __syncthreads();

    for (int kc = 0; kc < NCH; kc++) {
        int cb = kc & 1;
        if (kc < NCH-1) stage(kc+1, cb ^ 1);
        const __nv_bfloat16* vb = (const __nv_bfloat16*)(smem + S2_V) + cb*(2*TILE*VSTR);
        const __nv_bfloat16* wb = (const __nv_bfloat16*)(smem + S2_W) + cb*(2*64*VSTR);
        #pragma unroll
        for (int ks = 0; ks < 4; ks++) {
            const __nv_bfloat16* ar = vb + (R+g)*VSTR + ks*16 + 2*tig;
            uint32_t ah[4], al[4];
            ah[0] = *(const uint32_t*)ar;
            ah[1] = *(const uint32_t*)(ar + 8*VSTR);
            ah[2] = *(const uint32_t*)(ar + 8);
            ah[3] = *(const uint32_t*)(ar + 8*VSTR + 8);
            const __nv_bfloat16* arl = ar + TILE*VSTR;
            al[0] = *(const uint32_t*)arl;
            al[1] = *(const uint32_t*)(arl + 8*VSTR);
            al[2] = *(const uint32_t*)(arl + 8);
            al[3] = *(const uint32_t*)(arl + 8*VSTR + 8);
            #pragma unroll
            for (int t = 0; t < 4; t++) {
                const __nv_bfloat16* br = wb + (NB + t*8 + g)*VSTR + ks*16 + 2*tig;
                uint32_t bh0 = *(const uint32_t*)br;
                uint32_t bh1 = *(const uint32_t*)(br + 8);
                uint32_t bl0 = *(const uint32_t*)(br + 64*VSTR);
                uint32_t bl1 = *(const uint32_t*)(br + 64*VSTR + 8);
                mma_bf16(acc[t], ah, bh0, bh1);
                mma_bf16(acc[t], ah, bl0, bl1);
                mma_bf16(acc[t], al, bh0, bh1);
            }
        }
        __syncthreads();
    }

    // epilogue: stage [64][pos] f32 in smem, then coalesced float4 stores
    float* obuf = (float*)(smem + S2_V);
    #pragma unroll
    for (int t = 0; t < 4; t++) {
        int n0 = NB + t*8 + 2*tig;
        obuf[(n0    )*OSTR + R+g    ] = acc[t][0];
        obuf[(n0 + 1)*OSTR + R+g    ] = acc[t][1];
        obuf[(n0    )*OSTR + R+g + 8] = acc[t][2];
        obuf[(n0 + 1)*OSTR + R+g + 8] = acc[t][3];
    }
    __syncthreads();
    float* ob = out + (size_t)b*COUT*HW + hw0;
    for (int i = tid; i < COUT*32; i += 512) {
        int co = i >> 5, q = i & 31;
        float4 v = *(float4*)&obuf[co*OSTR + q*4];
        *(float4*)&ob[co*HW + q*4] = v;
    }
}

// ---------------------------------------------------------------------------
extern "C" void kernel_launch(void* const* d_in, const int* in_sizes, int n_in,
                              void* d_out, int out_size) {
    const float* x      = (const float*)d_in[0];
    const float* w_off  = (const float*)d_in[1];
    const float* b_off  = (const float*)d_in[2];
    const float* w_mask = (const float*)d_in[3];
    const float* b_mask = (const float*)d_in[4];
    const float* w_def  = (const float*)d_in[5];
    float* out = (float*)d_out;

    cudaFuncSetAttribute(offmask_conv, cudaFuncAttributeMaxDynamicSharedMemorySize, S1_TOT);
    cudaFuncSetAttribute(deform_main,  cudaFuncAttributeMaxDynamicSharedMemorySize, S2_TOT);

    prep_weights<<<216, 256>>>(w_off, w_mask, w_def);
    offmask_conv<<<dim3(NT, Bn), 512, S1_TOT>>>(x, b_off, b_mask);
    deform_main <<<dim3(NT, Bn), 512, S2_TOT>>>(x, out);
}

// round 8
// speedup vs baseline: 3.1884x; 1.0081x over previous
#include <cuda_runtime.h>
#include <cuda_bf16.h>
#include <cstdint>
#include <math.h>

#define Bn   2
#define Cc   64
#define Hh   224
#define Ww   224
#define HW   (Hh*Ww)
#define NOFF 27
#define COUT 64
#define Jdim 576
#define CH   64
#define NCH  9
#define TILE 128           // kernel1 tile
#define T2   64            // kernel2 tile (2 CTAs/SM)
#define NT   (HW/TILE)     // 392
#define NT2  (HW/T2)       // 784
#define VSTR 72            // padded k-stride (bf16 elems) -> conflict-free
#define OSTR 132           // kernel1 epilogue pos-stride
#define OSTR2 68           // kernel2 epilogue pos-stride

// ---------------- device globals (no allocation allowed) -------------------
__device__ float g_offmask[Bn*NOFF*HW];                     // conv1 out (mask sigmoided)
__device__ __align__(16) __nv_bfloat16 g_wd[NCH][2][COUT*64]; // deform W [chunk][hi/lo][co][k]
__device__ __align__(16) __nv_bfloat16 g_wo[NCH][2][32*64];   // off/mask W (padded to 32 ch)

// ---------------- mma.sync helper (generic PTX, works on compute_103) ------
__device__ __forceinline__ void mma_bf16(float* c, const uint32_t* a,
                                         uint32_t b0, uint32_t b1) {
    asm volatile("mma.sync.aligned.m16n8k16.row.col.f32.bf16.bf16.f32 "
        "{%0,%1,%2,%3},{%4,%5,%6,%7},{%8,%9},{%0,%1,%2,%3};"
        : "+f"(c[0]), "+f"(c[1]), "+f"(c[2]), "+f"(c[3])
        : "r"(a[0]), "r"(a[1]), "r"(a[2]), "r"(a[3]), "r"(b0), "r"(b1));
}

__device__ __forceinline__ void split_bf16(float v, __nv_bfloat16& hi, __nv_bfloat16& lo) {
    hi = __float2bfloat16(v);
    lo = __float2bfloat16(v - __bfloat162float(hi));
}

// pack two floats -> bf16x2 (hi), and residual bf16x2 (lo)
__device__ __forceinline__ void split2_bf16(float v0, float v1,
                                            uint32_t& hp, uint32_t& lp) {
    asm("cvt.rn.bf16x2.f32 %0, %1, %2;" : "=r"(hp) : "f"(v1), "f"(v0));
    float f0 = __uint_as_float(hp << 16);
    float f1 = __uint_as_float(hp & 0xffff0000u);
    float r0 = v0 - f0, r1 = v1 - f1;
    asm("cvt.rn.bf16x2.f32 %0, %1, %2;" : "=r"(lp) : "f"(r1), "f"(r0));
}

// ---------------- prep: split weights to bf16 hi/lo ------------------------
__global__ void prep_weights(const float* __restrict__ w_off,
                             const float* __restrict__ w_mask,
                             const float* __restrict__ w_def) {
    int idx = blockIdx.x * 256 + threadIdx.x;
    if (idx < NCH*COUT*64) {
        int kc = idx / (COUT*64), r = idx % (COUT*64);
        int co = r >> 6, k = r & 63;
        float v = w_def[co*Jdim + kc*CH + k];
        __nv_bfloat16 hi, lo; split_bf16(v, hi, lo);
        g_wd[kc][0][r] = hi;
        g_wd[kc][1][r] = lo;
    } else {
        int i2 = idx - NCH*COUT*64;
        if (i2 < NCH*32*64) {
            int kc = i2 / (32*64), r = i2 % (32*64);
            int co = r >> 6, k = r & 63;
            int j = kc*CH + k;
            float v = 0.f;
            if (co < 18)      v = w_off[co*Jdim + j];
            else if (co < 27) v = w_mask[(co-18)*Jdim + j];
            __nv_bfloat16 hi, lo; split_bf16(v, hi, lo);
            g_wo[kc][0][r] = hi;
            g_wo[kc][1][r] = lo;
        }
    }
}

// ============================================================================
// Kernel 1: offset+mask conv (27ch, padded 32) via mma.sync.  128pos x 32co.
// ============================================================================
#define S1_HO 0
#define S1_WO 512
#define S1_V  1024                       // [2buf][2split][128][VSTR] bf16 = 73728
#define S1_W  (S1_V + 73728)             // [2buf][2split][32][VSTR] bf16 = 18432
#define S1_TOT (S1_W + 18432)            // 93184

__global__ void __launch_bounds__(512, 2) offmask_conv(
        const float* __restrict__ x,
        const float* __restrict__ b_off,
        const float* __restrict__ b_mask) {
    extern __shared__ char smem[];
    const int tid = threadIdx.x, lane = tid & 31, wid = tid >> 5;
    const int hw0 = blockIdx.x * TILE;
    const int b   = blockIdx.y;
    const float* xb = x + (size_t)b * Cc * HW;

    int* sHO = (int*)(smem + S1_HO);
    int* sWO = (int*)(smem + S1_WO);
    if (tid < TILE) {
        int hw = hw0 + tid, ho = hw / Ww;
        sHO[tid] = ho; sWO[tid] = hw - ho*Ww;
    }
    __syncthreads();

    auto stage = [&](int kc, int buf) {
        __nv_bfloat16* vh = (__nv_bfloat16*)(smem + S1_V) + buf*(2*TILE*VSTR);
        __nv_bfloat16* vl = vh + TILE*VSTR;
        #pragma unroll
        for (int t = 0; t < 2; t++) {
            int task = tid + t*512;
            int pos = task & 127;
            int jg  = task >> 7;           // 0..7
            int ho = sHO[pos], wo = sWO[pos];
            int jb = kc*CH + jg*8;
            int c  = jb / 9, k = jb - c*9;
            const float* xc = xb + c*HW;
            float v[8];
            #pragma unroll
            for (int u = 0; u < 8; u++) {
                int ky = k / 3, kx = k - ky*3;
                int iy = ho + ky - 1, ix = wo + kx - 1;
                float val = 0.f;
                if ((unsigned)iy < Hh && (unsigned)ix < Ww)
                    val = xc[iy*Ww + ix];
                v[u] = val;
                if (++k == 9) { k = 0; xc += HW; }
            }
            uint32_t h4[4], l4[4];
            #pragma unroll
            for (int u = 0; u < 4; u++)
                split2_bf16(v[2*u], v[2*u+1], h4[u], l4[u]);
            *(uint4*)(vh + pos*VSTR + jg*8) = *(uint4*)h4;
            *(uint4*)(vl + pos*VSTR + jg*8) = *(uint4*)l4;
        }
        const uint32_t* src = (const uint32_t*)(&g_wo[kc][0][0]);   // 2048 b32
        uint32_t* wd = (uint32_t*)(smem + S1_W) + buf*(2*32*VSTR/2);
        #pragma unroll
        for (int i = 0; i < 4; i++) {
            int idx = tid + i*512;
            int s = idx >> 10, r = (idx >> 5) & 31, w = idx & 31;
            wd[(s*32 + r)*(VSTR/2) + w] = src[idx];
        }
    };

    const int g = lane >> 2, tig = lane & 3;
    const int R  = (wid >> 1) * 16;
    const int NB = (wid & 1) * 16;
    float acc[2][4] = {};

    stage(0, 0);
    __syncthreads();

    for (int kc = 0; kc < NCH; kc++) {
        int cb = kc & 1;
        if (kc < NCH-1) stage(kc+1, cb ^ 1);
        const __nv_bfloat16* vb = (const __nv_bfloat16*)(smem + S1_V) + cb*(2*TILE*VSTR);
        const __nv_bfloat16* wb = (const __nv_bfloat16*)(smem + S1_W) + cb*(2*32*VSTR);
        #pragma unroll
        for (int ks = 0; ks < 4; ks++) {
            const __nv_bfloat16* ar = vb + (R+g)*VSTR + ks*16 + 2*tig;
            uint32_t ah[4], al[4];
            ah[0] = *(const uint32_t*)ar;
            ah[1] = *(const uint32_t*)(ar + 8*VSTR);
            ah[2] = *(const uint32_t*)(ar + 8);
            ah[3] = *(const uint32_t*)(ar + 8*VSTR + 8);
            const __nv_bfloat16* arl = ar + TILE*VSTR;
            al[0] = *(const uint32_t*)arl;
            al[1] = *(const uint32_t*)(arl + 8*VSTR);
            al[2] = *(const uint32_t*)(arl + 8);
            al[3] = *(const uint32_t*)(arl + 8*VSTR + 8);
            #pragma unroll
            for (int t = 0; t < 2; t++) {
                const __nv_bfloat16* br = wb + (NB + t*8 + g)*VSTR + ks*16 + 2*tig;
                uint32_t bh0 = *(const uint32_t*)br;
                uint32_t bh1 = *(const uint32_t*)(br + 8);
                uint32_t bl0 = *(const uint32_t*)(br + 32*VSTR);
                uint32_t bl1 = *(const uint32_t*)(br + 32*VSTR + 8);
                mma_bf16(acc[t], ah, bh0, bh1);
                mma_bf16(acc[t], ah, bl0, bl1);
                mma_bf16(acc[t], al, bh0, bh1);
            }
        }
        __syncthreads();
    }

    float* obuf = (float*)(smem + S1_V);
    #pragma unroll
    for (int t = 0; t < 2; t++) {
        int n0 = NB + t*8 + 2*tig;
        obuf[(n0    )*OSTR + R+g    ] = acc[t][0];
        obuf[(n0 + 1)*OSTR + R+g    ] = acc[t][1];
        obuf[(n0    )*OSTR + R+g + 8] = acc[t][2];
        obuf[(n0 + 1)*OSTR + R+g + 8] = acc[t][3];
    }
    __syncthreads();
    float* ob = g_offmask + (size_t)b*NOFF*HW + hw0;
    for (int i = tid; i < NOFF*TILE; i += 512) {
        int co = i >> 7, pos = i & 127;
        float v = obuf[co*OSTR + pos] + (co < 18 ? b_off[co] : b_mask[co-18]);
        if (co >= 18) v = 1.f / (1.f + __expf(-v));
        ob[co*HW + pos] = v;
    }
}

// ============================================================================
// Kernel 2: bilinear gather + main GEMM via mma.sync. 64pos x 64co, K=576.
// 92KB smem -> 2 CTAs/SM for latency hiding.
// ============================================================================
#define S2_PI 0                          // int4 [9*64]  = 9216
#define S2_PW 9216                       // float4[9*64] = 9216
#define S2_V  18432                      // [2buf][2split][64][VSTR] = 36864
#define S2_W  (S2_V + 36864)             // [2buf][2split][64][VSTR] = 36864
#define S2_TOT (S2_W + 36864)            // 92160

__global__ void __launch_bounds__(512, 2) deform_main(
        const float* __restrict__ x,
        float* __restrict__ out) {
    extern __shared__ char smem[];
    const int tid = threadIdx.x, lane = tid & 31, wid = tid >> 5;
    const int hw0 = blockIdx.x * T2;
    const int b   = blockIdx.y;
    const float* xb = x + (size_t)b * Cc * HW;

    int4*   pI = (int4*)  (smem + S2_PI);
    float4* pW = (float4*)(smem + S2_PW);

    // phase 0: clamped corner indices + validity/mask-folded weights
    for (int i = tid; i < 9*T2; i += 512) {
        int pos = i & 63;
        int k2  = i >> 6;
        int hw  = hw0 + pos;
        int ho  = hw / Ww;
        int wo  = hw - ho*Ww;
        const float* om = g_offmask + (size_t)b*NOFF*HW + hw;
        float dy = om[(2*k2    )*HW];
        float dx = om[(2*k2 + 1)*HW];
        float m  = om[(18 + k2 )*HW];
        int ky = k2 / 3, kx = k2 - ky*3;
        float py = dy + (float)(ho - 1 + ky);
        float px = dx + (float)(wo - 1 + kx);
        float fy = floorf(py), fx = floorf(px);
        float wy1 = py - fy, wx1 = px - fx;
        float wy0 = 1.f - wy1, wx0 = 1.f - wx1;
        int y0 = (int)fy, x0 = (int)fx;
        int y1 = y0 + 1,  x1 = x0 + 1;
        float vy0 = ((unsigned)y0 < Hh) ? 1.f : 0.f;
        float vy1 = ((unsigned)y1 < Hh) ? 1.f : 0.f;
        float vx0 = ((unsigned)x0 < Ww) ? 1.f : 0.f;
        float vx1 = ((unsigned)x1 < Ww) ? 1.f : 0.f;
        int y0c = min(max(y0, 0), Hh-1), y1c = min(max(y1, 0), Hh-1);
        int x0c = min(max(x0, 0), Ww-1), x1c = min(max(x1, 0), Ww-1);
        pI[i] = make_int4(y0c*Ww + x0c, y0c*Ww + x1c,
                          y1c*Ww + x0c, y1c*Ww + x1c);
        pW[i] = make_float4(wy0*wx0*m*vy0*vx0, wy0*wx1*m*vy0*vx1,
                            wy1*wx0*m*vy1*vx0, wy1*wx1*m*vy1*vx1);
    }
    __syncthreads();

    // one task per thread: pos = tid&63, 8 consecutive j
    auto stage = [&](int kc, int buf) {
        __nv_bfloat16* vh = (__nv_bfloat16*)(smem + S2_V) + buf*(2*T2*VSTR);
        __nv_bfloat16* vl = vh + T2*VSTR;
        int pos = tid & 63;
        int jg  = tid >> 6;            // 0..7
        int jb = kc*CH + jg*8;
        int c  = jb / 9, k2 = jb - c*9;
        const float* xc = xb + c*HW;
        float v[8];
        #pragma unroll
        for (int u = 0; u < 8; u++) {
            int pk = (k2 << 6) | pos;
            int4   id = pI[pk];
            float4 w  = pW[pk];
            float val;
            val = w.x * xc[id.x];
            val = fmaf(w.y, xc[id.y], val);
            val = fmaf(w.z, xc[id.z], val);
            val = fmaf(w.w, xc[id.w], val);
            v[u] = val;
            if (++k2 == 9) { k2 = 0; xc += HW; }
        }
        uint32_t h4[4], l4[4];
        #pragma unroll
        for (int u = 0; u < 4; u++)
            split2_bf16(v[2*u], v[2*u+1], h4[u], l4[u]);
        *(uint4*)(vh + pos*VSTR + jg*8) = *(uint4*)h4;
        *(uint4*)(vl + pos*VSTR + jg*8) = *(uint4*)l4;

        const uint32_t* src = (const uint32_t*)(&g_wd[kc][0][0]);   // 4096 b32
        uint32_t* wd = (uint32_t*)(smem + S2_W) + buf*(2*64*VSTR/2);
        #pragma unroll
        for (int i = 0; i < 8; i++) {
            int idx = tid + i*512;
            int s = idx >> 11, r = (idx >> 5) & 63, w = idx & 31;
            wd[(s*64 + r)*(VSTR/2) + w] = src[idx];
        }
    };

    const int g = lane >> 2, tig = lane & 3;
    const int R  = (wid >> 2) * 16;    // 4 m-tiles of 16 pos
    const int NB = (wid & 3) * 16;     // 4 n-tiles of 16 co
    float acc[2][4] = {};

    stage(0, 0);
    __syncthreads();

    for (int kc = 0; kc < NCH; kc++) {
        int cb = kc & 1;
        if (kc < NCH-1) stage(kc+1, cb ^ 1);
        const __nv_bfloat16* vb = (const __nv_bfloat16*)(smem + S2_V) + cb*(2*T2*VSTR);
        const __nv_bfloat16* wb = (const __nv_bfloat16*)(smem + S2_W) + cb*(2*64*VSTR);
        #pragma unroll
        for (int ks = 0; ks < 4; ks++) {
            const __nv_bfloat16* ar = vb + (R+g)*VSTR + ks*16 + 2*tig;
            uint32_t ah[4], al[4];
            ah[0] = *(const uint32_t*)ar;
            ah[1] = *(const uint32_t*)(ar + 8*VSTR);
            ah[2] = *(const uint32_t*)(ar + 8);
            ah[3] = *(const uint32_t*)(ar + 8*VSTR + 8);
            const __nv_bfloat16* arl = ar + T2*VSTR;
            al[0] = *(const uint32_t*)arl;
            al[1] = *(const uint32_t*)(arl + 8*VSTR);
            al[2] = *(const uint32_t*)(arl + 8);
            al[3] = *(const uint32_t*)(arl + 8*VSTR + 8);
            #pragma unroll
            for (int t = 0; t < 2; t++) {
                const __nv_bfloat16* br = wb + (NB + t*8 + g)*VSTR + ks*16 + 2*tig;
                uint32_t bh0 = *(const uint32_t*)br;
                uint32_t bh1 = *(const uint32_t*)(br + 8);
                uint32_t bl0 = *(const uint32_t*)(br + 64*VSTR);
                uint32_t bl1 = *(const uint32_t*)(br + 64*VSTR + 8);
                mma_bf16(acc[t], ah, bh0, bh1);
                mma_bf16(acc[t], ah, bl0, bl1);
                mma_bf16(acc[t], al, bh0, bh1);
            }
        }
        __syncthreads();
    }

    // epilogue: stage [64co][64pos] f32, then coalesced stores
    float* obuf = (float*)(smem + S2_V);
    #pragma unroll
    for (int t = 0; t < 2; t++) {
        int n0 = NB + t*8 + 2*tig;
        obuf[(n0    )*OSTR2 + R+g    ] = acc[t][0];
        obuf[(n0 + 1)*OSTR2 + R+g    ] = acc[t][1];
        obuf[(n0    )*OSTR2 + R+g + 8] = acc[t][2];
        obuf[(n0 + 1)*OSTR2 + R+g + 8] = acc[t][3];
    }
    __syncthreads();
    float* ob = out + (size_t)b*COUT*HW + hw0;
    #pragma unroll
    for (int i = tid; i < COUT*16; i += 512) {
        int co = i >> 4, q = i & 15;
        float4 v = *(float4*)&obuf[co*OSTR2 + q*4];
        *(float4*)&ob[co*HW + q*4] = v;
    }
}

// ---------------------------------------------------------------------------
extern "C" void kernel_launch(void* const* d_in, const int* in_sizes, int n_in,
                              void* d_out, int out_size) {
    const float* x      = (const float*)d_in[0];
    const float* w_off  = (const float*)d_in[1];
    const float* b_off  = (const float*)d_in[2];
    const float* w_mask = (const float*)d_in[3];
    const float* b_mask = (const float*)d_in[4];
    const float* w_def  = (const float*)d_in[5];
    float* out = (float*)d_out;

    cudaFuncSetAttribute(offmask_conv, cudaFuncAttributeMaxDynamicSharedMemorySize, S1_TOT);
    cudaFuncSetAttribute(deform_main,  cudaFuncAttributeMaxDynamicSharedMemorySize, S2_TOT);

    prep_weights<<<216, 256>>>(w_off, w_mask, w_def);
    offmask_conv<<<dim3(NT, Bn), 512, S1_TOT>>>(x, b_off, b_mask);
    deform_main <<<dim3(NT2, Bn), 512, S2_TOT>>>(x, out);
}

// round 9
// speedup vs baseline: 4.1122x; 1.2897x over previous
#include <cuda_runtime.h>
#include <cuda_bf16.h>
#include <cstdint>
#include <math.h>

#define Bn   2
#define Cc   64
#define Hh   224
#define Ww   224
#define HW   (Hh*Ww)
#define NOFF 27
#define COUT 64
#define Jdim 576
#define CH   64
#define NCH  9             // chunks == k2 values (k2-major K ordering)
#define TILE 128           // kernel1 tile
#define T2   64            // kernel2 tile
#define NT   (HW/TILE)     // 392
#define NT2  (HW/T2)       // 784
#define VSTR 72            // padded k-stride (bf16 elems) -> conflict-free
#define OSTR 132           // kernel1 epilogue pos-stride
#define OSTR2 68           // kernel2 epilogue pos-stride

// K ordering: j' = k2*64 + c  (chunk kc == kernel tap k2, inner dim = channel)

// ---------------- device globals (no allocation allowed) -------------------
__device__ float g_offmask[Bn*NOFF*HW];                     // conv1 out (mask sigmoided)
__device__ __align__(16) __nv_bfloat16 g_wd[NCH][2][COUT*64]; // deform W [k2][hi/lo][co][c]
__device__ __align__(16) __nv_bfloat16 g_wo[NCH][2][32*64];   // off/mask W (padded to 32 ch)

// ---------------- mma.sync helper (generic PTX, works on compute_103) ------
__device__ __forceinline__ void mma_bf16(float* c, const uint32_t* a,
                                         uint32_t b0, uint32_t b1) {
    asm volatile("mma.sync.aligned.m16n8k16.row.col.f32.bf16.bf16.f32 "
        "{%0,%1,%2,%3},{%4,%5,%6,%7},{%8,%9},{%0,%1,%2,%3};"
        : "+f"(c[0]), "+f"(c[1]), "+f"(c[2]), "+f"(c[3])
        : "r"(a[0]), "r"(a[1]), "r"(a[2]), "r"(a[3]), "r"(b0), "r"(b1));
}

__device__ __forceinline__ void split_bf16(float v, __nv_bfloat16& hi, __nv_bfloat16& lo) {
    hi = __float2bfloat16(v);
    lo = __float2bfloat16(v - __bfloat162float(hi));
}

// pack two floats -> bf16x2 (hi), and residual bf16x2 (lo)
__device__ __forceinline__ void split2_bf16(float v0, float v1,
                                            uint32_t& hp, uint32_t& lp) {
    asm("cvt.rn.bf16x2.f32 %0, %1, %2;" : "=r"(hp) : "f"(v1), "f"(v0));
    float f0 = __uint_as_float(hp << 16);
    float f1 = __uint_as_float(hp & 0xffff0000u);
    float r0 = v0 - f0, r1 = v1 - f1;
    asm("cvt.rn.bf16x2.f32 %0, %1, %2;" : "=r"(lp) : "f"(r1), "f"(r0));
}

// ---------------- prep: split weights to bf16 hi/lo, k2-major K ------------
__global__ void prep_weights(const float* __restrict__ w_off,
                             const float* __restrict__ w_mask,
                             const float* __restrict__ w_def) {
    int idx = blockIdx.x * 256 + threadIdx.x;
    if (idx < NCH*COUT*64) {
        int kc = idx / (COUT*64), r = idx % (COUT*64);
        int co = r >> 6, c = r & 63;
        float v = w_def[co*Jdim + c*9 + kc];
        __nv_bfloat16 hi, lo; split_bf16(v, hi, lo);
        g_wd[kc][0][r] = hi;
        g_wd[kc][1][r] = lo;
    } else {
        int i2 = idx - NCH*COUT*64;
        if (i2 < NCH*32*64) {
            int kc = i2 / (32*64), r = i2 % (32*64);
            int co = r >> 6, c = r & 63;
            float v = 0.f;
            if (co < 18)      v = w_off[co*Jdim + c*9 + kc];
            else if (co < 27) v = w_mask[(co-18)*Jdim + c*9 + kc];
            __nv_bfloat16 hi, lo; split_bf16(v, hi, lo);
            g_wo[kc][0][r] = hi;
            g_wo[kc][1][r] = lo;
        }
    }
}

// ============================================================================
// Kernel 1: offset+mask conv (27ch, padded 32) via mma.sync.  128pos x 32co.
// Chunk = one k2 tap: one bounds check, 8 channel loads at stride HW.
// ============================================================================
#define S1_HO 0
#define S1_WO 512
#define S1_V  1024                       // [2buf][2split][128][VSTR] bf16 = 73728
#define S1_W  (S1_V + 73728)             // [2buf][2split][32][VSTR] bf16 = 18432
#define S1_TOT (S1_W + 18432)            // 93184

__global__ void __launch_bounds__(512, 2) offmask_conv(
        const float* __restrict__ x,
        const float* __restrict__ b_off,
        const float* __restrict__ b_mask) {
    extern __shared__ char smem[];
    const int tid = threadIdx.x, lane = tid & 31, wid = tid >> 5;
    const int hw0 = blockIdx.x * TILE;
    const int b   = blockIdx.y;
    const float* xb = x + (size_t)b * Cc * HW;

    int* sHO = (int*)(smem + S1_HO);
    int* sWO = (int*)(smem + S1_WO);
    if (tid < TILE) {
        int hw = hw0 + tid, ho = hw / Ww;
        sHO[tid] = ho; sWO[tid] = hw - ho*Ww;
    }
    __syncthreads();

    auto stage = [&](int kc, int buf) {
        __nv_bfloat16* vh = (__nv_bfloat16*)(smem + S1_V) + buf*(2*TILE*VSTR);
        __nv_bfloat16* vl = vh + TILE*VSTR;
        const int ky = kc / 3, kx = kc - ky*3;
        #pragma unroll
        for (int t = 0; t < 2; t++) {
            int task = tid + t*512;
            int pos = task & 127;
            int cg  = task >> 7;           // 0..7 channel groups of 8
            int iy = sHO[pos] + ky - 1;
            int ix = sWO[pos] + kx - 1;
            bool inb = ((unsigned)iy < Hh) && ((unsigned)ix < Ww);
            const float* xp = xb + (size_t)(cg*8)*HW + iy*Ww + ix;
            float v[8];
            #pragma unroll
            for (int u = 0; u < 8; u++) {
                v[u] = inb ? *xp : 0.f;
                xp += HW;
            }
            uint32_t h4[4], l4[4];
            #pragma unroll
            for (int u = 0; u < 4; u++)
                split2_bf16(v[2*u], v[2*u+1], h4[u], l4[u]);
            *(uint4*)(vh + pos*VSTR + cg*8) = *(uint4*)h4;
            *(uint4*)(vl + pos*VSTR + cg*8) = *(uint4*)l4;
        }
        const uint32_t* src = (const uint32_t*)(&g_wo[kc][0][0]);   // 2048 b32
        uint32_t* wd = (uint32_t*)(smem + S1_W) + buf*(2*32*VSTR/2);
        #pragma unroll
        for (int i = 0; i < 4; i++) {
            int idx = tid + i*512;
            int s = idx >> 10, r = (idx >> 5) & 31, w = idx & 31;
            wd[(s*32 + r)*(VSTR/2) + w] = src[idx];
        }
    };

    const int g = lane >> 2, tig = lane & 3;
    const int R  = (wid >> 1) * 16;
    const int NB = (wid & 1) * 16;
    float acc[2][4] = {};

    stage(0, 0);
    __syncthreads();

    for (int kc = 0; kc < NCH; kc++) {
        int cb = kc & 1;
        if (kc < NCH-1) stage(kc+1, cb ^ 1);
        const __nv_bfloat16* vb = (const __nv_bfloat16*)(smem + S1_V) + cb*(2*TILE*VSTR);
        const __nv_bfloat16* wb = (const __nv_bfloat16*)(smem + S1_W) + cb*(2*32*VSTR);
        #pragma unroll
        for (int ks = 0; ks < 4; ks++) {
            const __nv_bfloat16* ar = vb + (R+g)*VSTR + ks*16 + 2*tig;
            uint32_t ah[4], al[4];
            ah[0] = *(const uint32_t*)ar;
            ah[1] = *(const uint32_t*)(ar + 8*VSTR);
            ah[2] = *(const uint32_t*)(ar + 8);
            ah[3] = *(const uint32_t*)(ar + 8*VSTR + 8);
            const __nv_bfloat16* arl = ar + TILE*VSTR;
            al[0] = *(const uint32_t*)arl;
            al[1] = *(const uint32_t*)(arl + 8*VSTR);
            al[2] = *(const uint32_t*)(arl + 8);
            al[3] = *(const uint32_t*)(arl + 8*VSTR + 8);
            #pragma unroll
            for (int t = 0; t < 2; t++) {
                const __nv_bfloat16* br = wb + (NB + t*8 + g)*VSTR + ks*16 + 2*tig;
                uint32_t bh0 = *(const uint32_t*)br;
                uint32_t bh1 = *(const uint32_t*)(br + 8);
                uint32_t bl0 = *(const uint32_t*)(br + 32*VSTR);
                uint32_t bl1 = *(const uint32_t*)(br + 32*VSTR + 8);
                mma_bf16(acc[t], ah, bh0, bh1);
                mma_bf16(acc[t], ah, bl0, bl1);
                mma_bf16(acc[t], al, bh0, bh1);
            }
        }
        __syncthreads();
    }

    float* obuf = (float*)(smem + S1_V);
    #pragma unroll
    for (int t = 0; t < 2; t++) {
        int n0 = NB + t*8 + 2*tig;
        obuf[(n0    )*OSTR + R+g    ] = acc[t][0];
        obuf[(n0 + 1)*OSTR + R+g    ] = acc[t][1];
        obuf[(n0    )*OSTR + R+g + 8] = acc[t][2];
        obuf[(n0 + 1)*OSTR + R+g + 8] = acc[t][3];
    }
    __syncthreads();
    float* ob = g_offmask + (size_t)b*NOFF*HW + hw0;
    for (int i = tid; i < NOFF*TILE; i += 512) {
        int co = i >> 7, pos = i & 127;
        float v = obuf[co*OSTR + pos] + (co < 18 ? b_off[co] : b_mask[co-18]);
        if (co >= 18) v = 1.f / (1.f + __expf(-v));
        ob[co*HW + pos] = v;
    }
}

// ============================================================================
// Kernel 2: bilinear gather + main GEMM via mma.sync. 64pos x 64co, K=576.
// Chunk = one k2 tap: one pI/pW read per thread, 8 channels share corners.
// ============================================================================
#define S2_PI 0                          // int4 [9*64]  = 9216
#define S2_PW 9216                       // float4[9*64] = 9216
#define S2_V  18432                      // [2buf][2split][64][VSTR] = 36864
#define S2_W  (S2_V + 36864)             // [2buf][2split][64][VSTR] = 36864
#define S2_TOT (S2_W + 36864)            // 92160

__global__ void __launch_bounds__(512, 2) deform_main(
        const float* __restrict__ x,
        float* __restrict__ out) {
    extern __shared__ char smem[];
    const int tid = threadIdx.x, lane = tid & 31, wid = tid >> 5;
    const int hw0 = blockIdx.x * T2;
    const int b   = blockIdx.y;
    const float* xb = x + (size_t)b * Cc * HW;

    int4*   pI = (int4*)  (smem + S2_PI);
    float4* pW = (float4*)(smem + S2_PW);

    // phase 0: clamped corner indices + validity/mask-folded weights
    for (int i = tid; i < 9*T2; i += 512) {
        int pos = i & 63;
        int k2  = i >> 6;
        int hw  = hw0 + pos;
        int ho  = hw / Ww;
        int wo  = hw - ho*Ww;
        const float* om = g_offmask + (size_t)b*NOFF*HW + hw;
        float dy = om[(2*k2    )*HW];
        float dx = om[(2*k2 + 1)*HW];
        float m  = om[(18 + k2 )*HW];
        int ky = k2 / 3, kx = k2 - ky*3;
        float py = dy + (float)(ho - 1 + ky);
        float px = dx + (float)(wo - 1 + kx);
        float fy = floorf(py), fx = floorf(px);
        float wy1 = py - fy, wx1 = px - fx;
        float wy0 = 1.f - wy1, wx0 = 1.f - wx1;
        int y0 = (int)fy, x0 = (int)fx;
        int y1 = y0 + 1,  x1 = x0 + 1;
        float vy0 = ((unsigned)y0 < Hh) ? 1.f : 0.f;
        float vy1 = ((unsigned)y1 < Hh) ? 1.f : 0.f;
        float vx0 = ((unsigned)x0 < Ww) ? 1.f : 0.f;
        float vx1 = ((unsigned)x1 < Ww) ? 1.f : 0.f;
        int y0c = min(max(y0, 0), Hh-1), y1c = min(max(y1, 0), Hh-1);
        int x0c = min(max(x0, 0), Ww-1), x1c = min(max(x1, 0), Ww-1);
        pI[i] = make_int4(y0c*Ww + x0c, y0c*Ww + x1c,
                          y1c*Ww + x0c, y1c*Ww + x1c);
        pW[i] = make_float4(wy0*wx0*m*vy0*vx0, wy0*wx1*m*vy0*vx1,
                            wy1*wx0*m*vy1*vx0, wy1*wx1*m*vy1*vx1);
    }
    __syncthreads();

    // one task per thread: pos = tid&63, 8 consecutive channels, fixed k2=kc
    auto stage = [&](int kc, int buf) {
        __nv_bfloat16* vh = (__nv_bfloat16*)(smem + S2_V) + buf*(2*T2*VSTR);
        __nv_bfloat16* vl = vh + T2*VSTR;
        int pos = tid & 63;
        int cg  = tid >> 6;            // 0..7
        int pk = (kc << 6) | pos;
        int4   id = pI[pk];
        float4 w  = pW[pk];
        const float* xc = xb + (size_t)(cg*8)*HW;
        float v[8];
        #pragma unroll
        for (int u = 0; u < 8; u++) {
            float val;
            val = w.x * xc[id.x];
            val = fmaf(w.y, xc[id.y], val);
            val = fmaf(w.z, xc[id.z], val);
            val = fmaf(w.w, xc[id.w], val);
            v[u] = val;
            xc += HW;
        }
        uint32_t h4[4], l4[4];
        #pragma unroll
        for (int u = 0; u < 4; u++)
            split2_bf16(v[2*u], v[2*u+1], h4[u], l4[u]);
        *(uint4*)(vh + pos*VSTR + cg*8) = *(uint4*)h4;
        *(uint4*)(vl + pos*VSTR + cg*8) = *(uint4*)l4;

        const uint32_t* src = (const uint32_t*)(&g_wd[kc][0][0]);   // 4096 b32
        uint32_t* wd = (uint32_t*)(smem + S2_W) + buf*(2*64*VSTR/2);
        #pragma unroll
        for (int i = 0; i < 8; i++) {
            int idx = tid + i*512;
            int s = idx >> 11, r = (idx >> 5) & 63, w2 = idx & 31;
            wd[(s*64 + r)*(VSTR/2) + w2] = src[idx];
        }
    };

    const int g = lane >> 2, tig = lane & 3;
    const int R  = (wid >> 2) * 16;    // 4 m-tiles of 16 pos
    const int NB = (wid & 3) * 16;     // 4 n-tiles of 16 co
    float acc[2][4] = {};

    stage(0, 0);
    __syncthreads();

    for (int kc = 0; kc < NCH; kc++) {
        int cb = kc & 1;
        if (kc < NCH-1) stage(kc+1, cb ^ 1);
        const __nv_bfloat16* vb = (const __nv_bfloat16*)(smem + S2_V) + cb*(2*T2*VSTR);
        const __nv_bfloat16* wb = (const __nv_bfloat16*)(smem + S2_W) + cb*(2*64*VSTR);
        #pragma unroll
        for (int ks = 0; ks < 4; ks++) {
            const __nv_bfloat16* ar = vb + (R+g)*VSTR + ks*16 + 2*tig;
            uint32_t ah[4], al[4];
            ah[0] = *(const uint32_t*)ar;
            ah[1] = *(const uint32_t*)(ar + 8*VSTR);
            ah[2] = *(const uint32_t*)(ar + 8);
            ah[3] = *(const uint32_t*)(ar + 8*VSTR + 8);
            const __nv_bfloat16* arl = ar + T2*VSTR;
            al[0] = *(const uint32_t*)arl;
            al[1] = *(const uint32_t*)(arl + 8*VSTR);
            al[2] = *(const uint32_t*)(arl + 8);
            al[3] = *(const uint32_t*)(arl + 8*VSTR + 8);
            #pragma unroll
            for (int t = 0; t < 2; t++) {
                const __nv_bfloat16* br = wb + (NB + t*8 + g)*VSTR + ks*16 + 2*tig;
                uint32_t bh0 = *(const uint32_t*)br;
                uint32_t bh1 = *(const uint32_t*)(br + 8);
                uint32_t bl0 = *(const uint32_t*)(br + 64*VSTR);
                uint32_t bl1 = *(const uint32_t*)(br + 64*VSTR + 8);
                mma_bf16(acc[t], ah, bh0, bh1);
                mma_bf16(acc[t], ah, bl0, bl1);
                mma_bf16(acc[t], al, bh0, bh1);
            }
        }
        __syncthreads();
    }

    // epilogue: stage [64co][64pos] f32, then coalesced stores
    float* obuf = (float*)(smem + S2_V);
    #pragma unroll
    for (int t = 0; t < 2; t++) {
        int n0 = NB + t*8 + 2*tig;
        obuf[(n0    )*OSTR2 + R+g    ] = acc[t][0];
        obuf[(n0 + 1)*OSTR2 + R+g    ] = acc[t][1];
        obuf[(n0    )*OSTR2 + R+g + 8] = acc[t][2];
        obuf[(n0 + 1)*OSTR2 + R+g + 8] = acc[t][3];
    }
    __syncthreads();
    float* ob = out + (size_t)b*COUT*HW + hw0;
    #pragma unroll
    for (int i = tid; i < COUT*16; i += 512) {
        int co = i >> 4, q = i & 15;
        float4 v = *(float4*)&obuf[co*OSTR2 + q*4];
        *(float4*)&ob[co*HW + q*4] = v;
    }
}

// ---------------------------------------------------------------------------
extern "C" void kernel_launch(void* const* d_in, const int* in_sizes, int n_in,
                              void* d_out, int out_size) {
    const float* x      = (const float*)d_in[0];
    const float* w_off  = (const float*)d_in[1];
    const float* b_off  = (const float*)d_in[2];
    const float* w_mask = (const float*)d_in[3];
    const float* b_mask = (const float*)d_in[4];
    const float* w_def  = (const float*)d_in[5];
    float* out = (float*)d_out;

    cudaFuncSetAttribute(offmask_conv, cudaFuncAttributeMaxDynamicSharedMemorySize, S1_TOT);
    cudaFuncSetAttribute(deform_main,  cudaFuncAttributeMaxDynamicSharedMemorySize, S2_TOT);

    prep_weights<<<216, 256>>>(w_off, w_mask, w_def);
    offmask_conv<<<dim3(NT, Bn), 512, S1_TOT>>>(x, b_off, b_mask);
    deform_main <<<dim3(NT2, Bn), 512, S2_TOT>>>(x, out);
}

// round 10
// speedup vs baseline: 4.3177x; 1.0500x over previous
#include <cuda_runtime.h>
#include <cuda_bf16.h>
#include <cstdint>
#include <math.h>

#define Bn   2
#define Cc   64
#define Hh   224
#define Ww   224
#define HW   (Hh*Ww)
#define NOFF 27
#define COUT 64
#define Jdim 576
#define CH   64
#define NCH  9             // chunks == k2 values (k2-major K ordering)
#define TILE 128           // kernel1 tile
#define T2   64            // kernel2 tile
#define NT   (HW/TILE)     // 392
#define NT2  (HW/T2)       // 784
#define VSTR 72            // padded k-stride (bf16 elems) -> conflict-free
#define OSTR 132           // kernel1 epilogue pos-stride
#define OSTR2 68           // kernel2 epilogue pos-stride

// K ordering: j' = k2*64 + c  (chunk kc == kernel tap k2, inner dim = channel)

// ---------------- device globals (no allocation allowed) -------------------
__device__ float g_offmask[Bn*NOFF*HW];                     // conv1 out (mask sigmoided)
__device__ __align__(16) float g_xt[(size_t)Bn*HW*Cc];      // x transposed: [b][hw][c]
__device__ __align__(16) __nv_bfloat16 g_wd[NCH][2][COUT*64]; // deform W [k2][hi/lo][co][c]
__device__ __align__(16) __nv_bfloat16 g_wo[NCH][2][32*64];   // off/mask W (padded to 32 ch)

// ---------------- mma.sync helper (generic PTX, works on compute_103) ------
__device__ __forceinline__ void mma_bf16(float* c, const uint32_t* a,
                                         uint32_t b0, uint32_t b1) {
    asm volatile("mma.sync.aligned.m16n8k16.row.col.f32.bf16.bf16.f32 "
        "{%0,%1,%2,%3},{%4,%5,%6,%7},{%8,%9},{%0,%1,%2,%3};"
        : "+f"(c[0]), "+f"(c[1]), "+f"(c[2]), "+f"(c[3])
        : "r"(a[0]), "r"(a[1]), "r"(a[2]), "r"(a[3]), "r"(b0), "r"(b1));
}

__device__ __forceinline__ void split_bf16(float v, __nv_bfloat16& hi, __nv_bfloat16& lo) {
    hi = __float2bfloat16(v);
    lo = __float2bfloat16(v - __bfloat162float(hi));
}

// pack two floats -> bf16x2 (hi), and residual bf16x2 (lo)
__device__ __forceinline__ void split2_bf16(float v0, float v1,
                                            uint32_t& hp, uint32_t& lp) {
    asm("cvt.rn.bf16x2.f32 %0, %1, %2;" : "=r"(hp) : "f"(v1), "f"(v0));
    float f0 = __uint_as_float(hp << 16);
    float f1 = __uint_as_float(hp & 0xffff0000u);
    float r0 = v0 - f0, r1 = v1 - f1;
    asm("cvt.rn.bf16x2.f32 %0, %1, %2;" : "=r"(lp) : "f"(r1), "f"(r0));
}

// ---------------- prep: split weights to bf16 hi/lo, k2-major K ------------
__global__ void prep_weights(const float* __restrict__ w_off,
                             const float* __restrict__ w_mask,
                             const float* __restrict__ w_def) {
    int idx = blockIdx.x * 256 + threadIdx.x;
    if (idx < NCH*COUT*64) {
        int kc = idx / (COUT*64), r = idx % (COUT*64);
        int co = r >> 6, c = r & 63;
        float v = w_def[co*Jdim + c*9 + kc];
        __nv_bfloat16 hi, lo; split_bf16(v, hi, lo);
        g_wd[kc][0][r] = hi;
        g_wd[kc][1][r] = lo;
    } else {
        int i2 = idx - NCH*COUT*64;
        if (i2 < NCH*32*64) {
            int kc = i2 / (32*64), r = i2 % (32*64);
            int co = r >> 6, c = r & 63;
            float v = 0.f;
            if (co < 18)      v = w_off[co*Jdim + c*9 + kc];
            else if (co < 27) v = w_mask[(co-18)*Jdim + c*9 + kc];
            __nv_bfloat16 hi, lo; split_bf16(v, hi, lo);
            g_wo[kc][0][r] = hi;
            g_wo[kc][1][r] = lo;
        }
    }
}

// ---------------- transpose x: [b][c][hw] -> [b][hw][c] ---------------------
__global__ void __launch_bounds__(512) transpose_x(const float* __restrict__ x) {
    __shared__ float tile[64][33];
    const int hw0 = blockIdx.x * 32;
    const int b   = blockIdx.y;
    const int l = threadIdx.x & 31, w = threadIdx.x >> 5;   // w 0..15
    const float* xb = x + (size_t)b*Cc*HW;
    #pragma unroll
    for (int i = 0; i < 4; i++) {
        int c = w + 16*i;
        tile[c][l] = xb[(size_t)c*HW + hw0 + l];
    }
    __syncthreads();
    const int c  = threadIdx.x & 63;
    const int hq = threadIdx.x >> 6;    // 0..7
    float* xt = g_xt + (size_t)b*HW*64;
    #pragma unroll
    for (int i = 0; i < 4; i++) {
        int hw = hq + 8*i;
        xt[(size_t)(hw0 + hw)*64 + c] = tile[c][hw];
    }
}

// ============================================================================
// Kernel 1: offset+mask conv (27ch, padded 32) via mma.sync.  128pos x 32co.
// ============================================================================
#define S1_HO 0
#define S1_WO 512
#define S1_V  1024                       // [2buf][2split][128][VSTR] bf16 = 73728
#define S1_W  (S1_V + 73728)             // [2buf][2split][32][VSTR] bf16 = 18432
#define S1_TOT (S1_W + 18432)            // 93184

__global__ void __launch_bounds__(512, 2) offmask_conv(
        const float* __restrict__ x,
        const float* __restrict__ b_off,
        const float* __restrict__ b_mask) {
    extern __shared__ char smem[];
    const int tid = threadIdx.x, lane = tid & 31, wid = tid >> 5;
    const int hw0 = blockIdx.x * TILE;
    const int b   = blockIdx.y;
    const float* xb = x + (size_t)b * Cc * HW;

    int* sHO = (int*)(smem + S1_HO);
    int* sWO = (int*)(smem + S1_WO);
    if (tid < TILE) {
        int hw = hw0 + tid, ho = hw / Ww;
        sHO[tid] = ho; sWO[tid] = hw - ho*Ww;
    }
    __syncthreads();

    auto stage = [&](int kc, int buf) {
        __nv_bfloat16* vh = (__nv_bfloat16*)(smem + S1_V) + buf*(2*TILE*VSTR);
        __nv_bfloat16* vl = vh + TILE*VSTR;
        const int ky = kc / 3, kx = kc - ky*3;
        #pragma unroll
        for (int t = 0; t < 2; t++) {
            int task = tid + t*512;
            int pos = task & 127;
            int cg  = task >> 7;           // 0..7 channel groups of 8
            int iy = sHO[pos] + ky - 1;
            int ix = sWO[pos] + kx - 1;
            bool inb = ((unsigned)iy < Hh) && ((unsigned)ix < Ww);
            const float* xp = xb + (size_t)(cg*8)*HW + iy*Ww + ix;
            float v[8];
            #pragma unroll
            for (int u = 0; u < 8; u++) {
                v[u] = inb ? *xp : 0.f;
                xp += HW;
            }
            uint32_t h4[4], l4[4];
            #pragma unroll
            for (int u = 0; u < 4; u++)
                split2_bf16(v[2*u], v[2*u+1], h4[u], l4[u]);
            *(uint4*)(vh + pos*VSTR + cg*8) = *(uint4*)h4;
            *(uint4*)(vl + pos*VSTR + cg*8) = *(uint4*)l4;
        }
        const uint32_t* src = (const uint32_t*)(&g_wo[kc][0][0]);   // 2048 b32
        uint32_t* wd = (uint32_t*)(smem + S1_W) + buf*(2*32*VSTR/2);
        #pragma unroll
        for (int i = 0; i < 4; i++) {
            int idx = tid + i*512;
            int s = idx >> 10, r = (idx >> 5) & 31, w = idx & 31;
            wd[(s*32 + r)*(VSTR/2) + w] = src[idx];
        }
    };

    const int g = lane >> 2, tig = lane & 3;
    const int R  = (wid >> 1) * 16;
    const int NB = (wid & 1) * 16;
    float acc[2][4] = {};

    stage(0, 0);
    __syncthreads();

    for (int kc = 0; kc < NCH; kc++) {
        int cb = kc & 1;
        if (kc < NCH-1) stage(kc+1, cb ^ 1);
        const __nv_bfloat16* vb = (const __nv_bfloat16*)(smem + S1_V) + cb*(2*TILE*VSTR);
        const __nv_bfloat16* wb = (const __nv_bfloat16*)(smem + S1_W) + cb*(2*32*VSTR);
        #pragma unroll
        for (int ks = 0; ks < 4; ks++) {
            const __nv_bfloat16* ar = vb + (R+g)*VSTR + ks*16 + 2*tig;
            uint32_t ah[4], al[4];
            ah[0] = *(const uint32_t*)ar;
            ah[1] = *(const uint32_t*)(ar + 8*VSTR);
            ah[2] = *(const uint32_t*)(ar + 8);
            ah[3] = *(const uint32_t*)(ar + 8*VSTR + 8);
            const __nv_bfloat16* arl = ar + TILE*VSTR;
            al[0] = *(const uint32_t*)arl;
            al[1] = *(const uint32_t*)(arl + 8*VSTR);
            al[2] = *(const uint32_t*)(arl + 8);
            al[3] = *(const uint32_t*)(arl + 8*VSTR + 8);
            #pragma unroll
            for (int t = 0; t < 2; t++) {
                const __nv_bfloat16* br = wb + (NB + t*8 + g)*VSTR + ks*16 + 2*tig;
                uint32_t bh0 = *(const uint32_t*)br;
                uint32_t bh1 = *(const uint32_t*)(br + 8);
                uint32_t bl0 = *(const uint32_t*)(br + 32*VSTR);
                uint32_t bl1 = *(const uint32_t*)(br + 32*VSTR + 8);
                mma_bf16(acc[t], ah, bh0, bh1);
                mma_bf16(acc[t], ah, bl0, bl1);
                mma_bf16(acc[t], al, bh0, bh1);
            }
        }
        __syncthreads();
    }

    float* obuf = (float*)(smem + S1_V);
    #pragma unroll
    for (int t = 0; t < 2; t++) {
        int n0 = NB + t*8 + 2*tig;
        obuf[(n0    )*OSTR + R+g    ] = acc[t][0];
        obuf[(n0 + 1)*OSTR + R+g    ] = acc[t][1];
        obuf[(n0    )*OSTR + R+g + 8] = acc[t][2];
        obuf[(n0 + 1)*OSTR + R+g + 8] = acc[t][3];
    }
    __syncthreads();
    float* ob = g_offmask + (size_t)b*NOFF*HW + hw0;
    for (int i = tid; i < NOFF*TILE; i += 512) {
        int co = i >> 7, pos = i & 127;
        float v = obuf[co*OSTR + pos] + (co < 18 ? b_off[co] : b_mask[co-18]);
        if (co >= 18) v = 1.f / (1.f + __expf(-v));
        ob[co*HW + pos] = v;
    }
}

// ============================================================================
// Kernel 2: bilinear gather + main GEMM via mma.sync. 64pos x 64co, K=576.
// Gather from channel-major x_t: per corner one LDG.64 of consecutive channels.
// ============================================================================
#define S2_PI 0                          // int4 [9*64]  = 9216
#define S2_PW 9216                       // float4[9*64] = 9216
#define S2_V  18432                      // [2buf][2split][64][VSTR] = 36864
#define S2_W  (S2_V + 36864)             // [2buf][2split][64][VSTR] = 36864
#define S2_TOT (S2_W + 36864)            // 92160

__global__ void __launch_bounds__(512, 2) deform_main(
        float* __restrict__ out) {
    extern __shared__ char smem[];
    const int tid = threadIdx.x, lane = tid & 31, wid = tid >> 5;
    const int hw0 = blockIdx.x * T2;
    const int b   = blockIdx.y;
    const float* xt = g_xt + (size_t)b * HW * 64;

    int4*   pI = (int4*)  (smem + S2_PI);
    float4* pW = (float4*)(smem + S2_PW);

    // phase 0: clamped corner indices + validity/mask-folded weights
    for (int i = tid; i < 9*T2; i += 512) {
        int pos = i & 63;
        int k2  = i >> 6;
        int hw  = hw0 + pos;
        int ho  = hw / Ww;
        int wo  = hw - ho*Ww;
        const float* om = g_offmask + (size_t)b*NOFF*HW + hw;
        float dy = om[(2*k2    )*HW];
        float dx = om[(2*k2 + 1)*HW];
        float m  = om[(18 + k2 )*HW];
        int ky = k2 / 3, kx = k2 - ky*3;
        float py = dy + (float)(ho - 1 + ky);
        float px = dx + (float)(wo - 1 + kx);
        float fy = floorf(py), fx = floorf(px);
        float wy1 = py - fy, wx1 = px - fx;
        float wy0 = 1.f - wy1, wx0 = 1.f - wx1;
        int y0 = (int)fy, x0 = (int)fx;
        int y1 = y0 + 1,  x1 = x0 + 1;
        float vy0 = ((unsigned)y0 < Hh) ? 1.f : 0.f;
        float vy1 = ((unsigned)y1 < Hh) ? 1.f : 0.f;
        float vx0 = ((unsigned)x0 < Ww) ? 1.f : 0.f;
        float vx1 = ((unsigned)x1 < Ww) ? 1.f : 0.f;
        int y0c = min(max(y0, 0), Hh-1), y1c = min(max(y1, 0), Hh-1);
        int x0c = min(max(x0, 0), Ww-1), x1c = min(max(x1, 0), Ww-1);
        pI[i] = make_int4(y0c*Ww + x0c, y0c*Ww + x1c,
                          y1c*Ww + x0c, y1c*Ww + x1c);
        pW[i] = make_float4(wy0*wx0*m*vy0*vx0, wy0*wx1*m*vy0*vx1,
                            wy1*wx0*m*vy1*vx0, wy1*wx1*m*vy1*vx1);
    }
    __syncthreads();

    // gather: warp-task = one pos, lanes = channel pairs (LDG.64 per corner)
    auto stage = [&](int kc, int buf) {
        __nv_bfloat16* vh = (__nv_bfloat16*)(smem + S2_V) + buf*(2*T2*VSTR);
        __nv_bfloat16* vl = vh + T2*VSTR;
        const int c0 = lane * 2;
        #pragma unroll
        for (int tp = 0; tp < 4; tp++) {
            int pos = (wid << 2) + tp;
            int pk = (kc << 6) | pos;
            int4   id = pI[pk];     // warp-uniform -> broadcast LDS
            float4 w  = pW[pk];
            float2 a0 = *(const float2*)(xt + (size_t)id.x*64 + c0);
            float2 a1 = *(const float2*)(xt + (size_t)id.y*64 + c0);
            float2 a2 = *(const float2*)(xt + (size_t)id.z*64 + c0);
            float2 a3 = *(const float2*)(xt + (size_t)id.w*64 + c0);
            float v0 = w.x * a0.x;
            v0 = fmaf(w.y, a1.x, v0);
            v0 = fmaf(w.z, a2.x, v0);
            v0 = fmaf(w.w, a3.x, v0);
            float v1 = w.x * a0.y;
            v1 = fmaf(w.y, a1.y, v1);
            v1 = fmaf(w.z, a2.y, v1);
            v1 = fmaf(w.w, a3.y, v1);
            uint32_t hp, lp;
            split2_bf16(v0, v1, hp, lp);
            *(uint32_t*)(vh + pos*VSTR + c0) = hp;
            *(uint32_t*)(vl + pos*VSTR + c0) = lp;
        }
        const uint32_t* src = (const uint32_t*)(&g_wd[kc][0][0]);   // 4096 b32
        uint32_t* wd = (uint32_t*)(smem + S2_W) + buf*(2*64*VSTR/2);
        #pragma unroll
        for (int i = 0; i < 8; i++) {
            int idx = tid + i*512;
            int s = idx >> 11, r = (idx >> 5) & 63, w2 = idx & 31;
            wd[(s*64 + r)*(VSTR/2) + w2] = src[idx];
        }
    };

    const int g = lane >> 2, tig = lane & 3;
    const int R  = (wid >> 2) * 16;    // 4 m-tiles of 16 pos
    const int NB = (wid & 3) * 16;     // 4 n-tiles of 16 co
    float acc[2][4] = {};

    stage(0, 0);
    __syncthreads();

    for (int kc = 0; kc < NCH; kc++) {
        int cb = kc & 1;
        if (kc < NCH-1) stage(kc+1, cb ^ 1);
        const __nv_bfloat16* vb = (const __nv_bfloat16*)(smem + S2_V) + cb*(2*T2*VSTR);
        const __nv_bfloat16* wb = (const __nv_bfloat16*)(smem + S2_W) + cb*(2*64*VSTR);
        #pragma unroll
        for (int ks = 0; ks < 4; ks++) {
            const __nv_bfloat16* ar = vb + (R+g)*VSTR + ks*16 + 2*tig;
            uint32_t ah[4], al[4];
            ah[0] = *(const uint32_t*)ar;
            ah[1] = *(const uint32_t*)(ar + 8*VSTR);
            ah[2] = *(const uint32_t*)(ar + 8);
            ah[3] = *(const uint32_t*)(ar + 8*VSTR + 8);
            const __nv_bfloat16* arl = ar + T2*VSTR;
            al[0] = *(const uint32_t*)arl;
            al[1] = *(const uint32_t*)(arl + 8*VSTR);
            al[2] = *(const uint32_t*)(arl + 8);
            al[3] = *(const uint32_t*)(arl + 8*VSTR + 8);
            #pragma unroll
            for (int t = 0; t < 2; t++) {
                const __nv_bfloat16* br = wb + (NB + t*8 + g)*VSTR + ks*16 + 2*tig;
                uint32_t bh0 = *(const uint32_t*)br;
                uint32_t bh1 = *(const uint32_t*)(br + 8);
                uint32_t bl0 = *(const uint32_t*)(br + 64*VSTR);
                uint32_t bl1 = *(const uint32_t*)(br + 64*VSTR + 8);
                mma_bf16(acc[t], ah, bh0, bh1);
                mma_bf16(acc[t], ah, bl0, bl1);
                mma_bf16(acc[t], al, bh0, bh1);
            }
        }
        __syncthreads();
    }

    // epilogue: stage [64co][64pos] f32, then coalesced stores
    float* obuf = (float*)(smem + S2_V);
    #pragma unroll
    for (int t = 0; t < 2; t++) {
        int n0 = NB + t*8 + 2*tig;
        obuf[(n0    )*OSTR2 + R+g    ] = acc[t][0];
        obuf[(n0 + 1)*OSTR2 + R+g    ] = acc[t][1];
        obuf[(n0    )*OSTR2 + R+g + 8] = acc[t][2];
        obuf[(n0 + 1)*OSTR2 + R+g + 8] = acc[t][3];
    }
    __syncthreads();
    float* ob = out + (size_t)b*COUT*HW + hw0;
    #pragma unroll
    for (int i = tid; i < COUT*16; i += 512) {
        int co = i >> 4, q = i & 15;
        float4 v = *(float4*)&obuf[co*OSTR2 + q*4];
        *(float4*)&ob[co*HW + q*4] = v;
    }
}

// ---------------------------------------------------------------------------
extern "C" void kernel_launch(void* const* d_in, const int* in_sizes, int n_in,
                              void* d_out, int out_size) {
    const float* x      = (const float*)d_in[0];
    const float* w_off  = (const float*)d_in[1];
    const float* b_off  = (const float*)d_in[2];
    const float* w_mask = (const float*)d_in[3];
    const float* b_mask = (const float*)d_in[4];
    const float* w_def  = (const float*)d_in[5];
    float* out = (float*)d_out;

    cudaFuncSetAttribute(offmask_conv, cudaFuncAttributeMaxDynamicSharedMemorySize, S1_TOT);
    cudaFuncSetAttribute(deform_main,  cudaFuncAttributeMaxDynamicSharedMemorySize, S2_TOT);

    prep_weights<<<216, 256>>>(w_off, w_mask, w_def);
    transpose_x<<<dim3(HW/32, Bn), 512>>>(x);
    offmask_conv<<<dim3(NT, Bn), 512, S1_TOT>>>(x, b_off, b_mask);
    deform_main <<<dim3(NT2, Bn), 512, S2_TOT>>>(out);
}

// round 11
// speedup vs baseline: 4.3517x; 1.0079x over previous
#include <cuda_runtime.h>
#include <cuda_bf16.h>
#include <cuda_fp16.h>
#include <cstdint>
#include <math.h>

#define Bn   2
#define Cc   64
#define Hh   224
#define Ww   224
#define HW   (Hh*Ww)
#define NOFF 27
#define COUT 64
#define Jdim 576
#define CH   64
#define NCH  9             // chunks == k2 values (k2-major K ordering)
#define TILE 128           // kernel1 tile
#define M2   128           // kernel2 tile
#define NT   (HW/TILE)     // 392
#define NT2  (HW/M2)       // 392
#define VSTR 72            // padded k-stride (elems) -> conflict-free
#define OSTR 132           // epilogue pos-stride

// K ordering: j' = k2*64 + c  (chunk kc == kernel tap k2, inner dim = channel)

// ---------------- device globals (no allocation allowed) -------------------
__device__ float g_offmask[Bn*NOFF*HW];                     // conv1 out (mask sigmoided)
__device__ __align__(16) float g_xt[(size_t)Bn*HW*Cc];      // x transposed: [b][hw][c]
__device__ __align__(16) __half g_wd[NCH][2][COUT*64];      // deform W fp16 [k2][hi/lo][co][c]
__device__ __align__(16) __nv_bfloat16 g_wo[NCH][2][32*64]; // off/mask W bf16 (padded 32 ch)

// ---------------- mma.sync helpers (generic PTX) ----------------------------
__device__ __forceinline__ void mma_bf16(float* c, const uint32_t* a,
                                         uint32_t b0, uint32_t b1) {
    asm volatile("mma.sync.aligned.m16n8k16.row.col.f32.bf16.bf16.f32 "
        "{%0,%1,%2,%3},{%4,%5,%6,%7},{%8,%9},{%0,%1,%2,%3};"
        : "+f"(c[0]), "+f"(c[1]), "+f"(c[2]), "+f"(c[3])
        : "r"(a[0]), "r"(a[1]), "r"(a[2]), "r"(a[3]), "r"(b0), "r"(b1));
}
__device__ __forceinline__ void mma_f16(float* c, const uint32_t* a,
                                        uint32_t b0, uint32_t b1) {
    asm volatile("mma.sync.aligned.m16n8k16.row.col.f32.f16.f16.f32 "
        "{%0,%1,%2,%3},{%4,%5,%6,%7},{%8,%9},{%0,%1,%2,%3};"
        : "+f"(c[0]), "+f"(c[1]), "+f"(c[2]), "+f"(c[3])
        : "r"(a[0]), "r"(a[1]), "r"(a[2]), "r"(a[3]), "r"(b0), "r"(b1));
}

__device__ __forceinline__ void split_bf16(float v, __nv_bfloat16& hi, __nv_bfloat16& lo) {
    hi = __float2bfloat16(v);
    lo = __float2bfloat16(v - __bfloat162float(hi));
}

// pack two floats -> bf16x2 (hi), and residual bf16x2 (lo)
__device__ __forceinline__ void split2_bf16(float v0, float v1,
                                            uint32_t& hp, uint32_t& lp) {
    asm("cvt.rn.bf16x2.f32 %0, %1, %2;" : "=r"(hp) : "f"(v1), "f"(v0));
    float f0 = __uint_as_float(hp << 16);
    float f1 = __uint_as_float(hp & 0xffff0000u);
    float r0 = v0 - f0, r1 = v1 - f1;
    asm("cvt.rn.bf16x2.f32 %0, %1, %2;" : "=r"(lp) : "f"(r1), "f"(r0));
}

// ---------------- prep: weights (fp16 hi/lo for deform; bf16 for off/mask) --
__global__ void prep_weights(const float* __restrict__ w_off,
                             const float* __restrict__ w_mask,
                             const float* __restrict__ w_def) {
    int idx = blockIdx.x * 256 + threadIdx.x;
    if (idx < NCH*COUT*64) {
        int kc = idx / (COUT*64), r = idx % (COUT*64);
        int co = r >> 6, c = r & 63;
        float v = w_def[co*Jdim + c*9 + kc];
        __half hi = __float2half(v);
        __half lo = __float2half(v - __half2float(hi));
        g_wd[kc][0][r] = hi;
        g_wd[kc][1][r] = lo;
    } else {
        int i2 = idx - NCH*COUT*64;
        if (i2 < NCH*32*64) {
            int kc = i2 / (32*64), r = i2 % (32*64);
            int co = r >> 6, c = r & 63;
            float v = 0.f;
            if (co < 18)      v = w_off[co*Jdim + c*9 + kc];
            else if (co < 27) v = w_mask[(co-18)*Jdim + c*9 + kc];
            __nv_bfloat16 hi, lo; split_bf16(v, hi, lo);
            g_wo[kc][0][r] = hi;
            g_wo[kc][1][r] = lo;
        }
    }
}

// ---------------- transpose x: [b][c][hw] -> [b][hw][c] ---------------------
__global__ void __launch_bounds__(512) transpose_x(const float* __restrict__ x) {
    __shared__ float tile[64][33];
    const int hw0 = blockIdx.x * 32;
    const int b   = blockIdx.y;
    const int l = threadIdx.x & 31, w = threadIdx.x >> 5;   // w 0..15
    const float* xb = x + (size_t)b*Cc*HW;
    #pragma unroll
    for (int i = 0; i < 4; i++) {
        int c = w + 16*i;
        tile[c][l] = xb[(size_t)c*HW + hw0 + l];
    }
    __syncthreads();
    const int c  = threadIdx.x & 63;
    const int hq = threadIdx.x >> 6;    // 0..7
    float* xt = g_xt + (size_t)b*HW*64;
    #pragma unroll
    for (int i = 0; i < 4; i++) {
        int hw = hq + 8*i;
        xt[(size_t)(hw0 + hw)*64 + c] = tile[c][hw];
    }
}

// ============================================================================
// Kernel 1: offset+mask conv (27ch, padded 32), bf16 3-product mma.sync.
// 128pos x 32co. Gather from channel-major x_t: 1 LDG.64 per pos per warp.
// ============================================================================
#define S1_HO 0
#define S1_WO 512
#define S1_V  1024                       // [2buf][2split][128][VSTR] bf16 = 73728
#define S1_W  (S1_V + 73728)             // [2buf][2split][32][VSTR] bf16 = 18432
#define S1_TOT (S1_W + 18432)            // 93184

__global__ void __launch_bounds__(512, 2) offmask_conv(
        const float* __restrict__ b_off,
        const float* __restrict__ b_mask) {
    extern __shared__ char smem[];
    const int tid = threadIdx.x, lane = tid & 31, wid = tid >> 5;
    const int hw0 = blockIdx.x * TILE;
    const int b   = blockIdx.y;
    const float* xt = g_xt + (size_t)b * HW * 64;

    int* sHO = (int*)(smem + S1_HO);
    int* sWO = (int*)(smem + S1_WO);
    if (tid < TILE) {
        int hw = hw0 + tid, ho = hw / Ww;
        sHO[tid] = ho; sWO[tid] = hw - ho*Ww;
    }
    __syncthreads();

    auto stage = [&](int kc, int buf) {
        __nv_bfloat16* vh = (__nv_bfloat16*)(smem + S1_V) + buf*(2*TILE*VSTR);
        __nv_bfloat16* vl = vh + TILE*VSTR;
        const int ky = kc / 3, kx = kc - ky*3;
        const int c0 = lane * 2;
        #pragma unroll
        for (int tp = 0; tp < 8; tp++) {
            int pos = (wid << 3) + tp;
            int iy = sHO[pos] + ky - 1;
            int ix = sWO[pos] + kx - 1;
            float2 a = make_float2(0.f, 0.f);
            if (((unsigned)iy < Hh) && ((unsigned)ix < Ww))
                a = *(const float2*)(xt + (size_t)(iy*Ww + ix)*64 + c0);
            uint32_t hp, lp;
            split2_bf16(a.x, a.y, hp, lp);
            *(uint32_t*)(vh + pos*VSTR + c0) = hp;
            *(uint32_t*)(vl + pos*VSTR + c0) = lp;
        }
        const uint32_t* src = (const uint32_t*)(&g_wo[kc][0][0]);   // 2048 b32
        uint32_t* wd = (uint32_t*)(smem + S1_W) + buf*(2*32*VSTR/2);
        #pragma unroll
        for (int i = 0; i < 4; i++) {
            int idx = tid + i*512;
            int s = idx >> 10, r = (idx >> 5) & 31, w = idx & 31;
            wd[(s*32 + r)*(VSTR/2) + w] = src[idx];
        }
    };

    const int g = lane >> 2, tig = lane & 3;
    const int R  = (wid >> 1) * 16;
    const int NB = (wid & 1) * 16;
    float acc[2][4] = {};

    stage(0, 0);
    __syncthreads();

    for (int kc = 0; kc < NCH; kc++) {
        int cb = kc & 1;
        if (kc < NCH-1) stage(kc+1, cb ^ 1);
        const __nv_bfloat16* vb = (const __nv_bfloat16*)(smem + S1_V) + cb*(2*TILE*VSTR);
        const __nv_bfloat16* wb = (const __nv_bfloat16*)(smem + S1_W) + cb*(2*32*VSTR);
        #pragma unroll
        for (int ks = 0; ks < 4; ks++) {
            const __nv_bfloat16* ar = vb + (R+g)*VSTR + ks*16 + 2*tig;
            uint32_t ah[4], al[4];
            ah[0] = *(const uint32_t*)ar;
            ah[1] = *(const uint32_t*)(ar + 8*VSTR);
            ah[2] = *(const uint32_t*)(ar + 8);
            ah[3] = *(const uint32_t*)(ar + 8*VSTR + 8);
            const __nv_bfloat16* arl = ar + TILE*VSTR;
            al[0] = *(const uint32_t*)arl;
            al[1] = *(const uint32_t*)(arl + 8*VSTR);
            al[2] = *(const uint32_t*)(arl + 8);
            al[3] = *(const uint32_t*)(arl + 8*VSTR + 8);
            #pragma unroll
            for (int t = 0; t < 2; t++) {
                const __nv_bfloat16* br = wb + (NB + t*8 + g)*VSTR + ks*16 + 2*tig;
                uint32_t bh0 = *(const uint32_t*)br;
                uint32_t bh1 = *(const uint32_t*)(br + 8);
                uint32_t bl0 = *(const uint32_t*)(br + 32*VSTR);
                uint32_t bl1 = *(const uint32_t*)(br + 32*VSTR + 8);
                mma_bf16(acc[t], ah, bh0, bh1);
                mma_bf16(acc[t], ah, bl0, bl1);
                mma_bf16(acc[t], al, bh0, bh1);
            }
        }
        __syncthreads();
    }

    float* obuf = (float*)(smem + S1_V);
    #pragma unroll
    for (int t = 0; t < 2; t++) {
        int n0 = NB + t*8 + 2*tig;
        obuf[(n0    )*OSTR + R+g    ] = acc[t][0];
        obuf[(n0 + 1)*OSTR + R+g    ] = acc[t][1];
        obuf[(n0    )*OSTR + R+g + 8] = acc[t][2];
        obuf[(n0 + 1)*OSTR + R+g + 8] = acc[t][3];
    }
    __syncthreads();
    float* ob = g_offmask + (size_t)b*NOFF*HW + hw0;
    for (int i = tid; i < NOFF*TILE; i += 512) {
        int co = i >> 7, pos = i & 127;
        float v = obuf[co*OSTR + pos] + (co < 18 ? b_off[co] : b_mask[co-18]);
        if (co >= 18) v = 1.f / (1.f + __expf(-v));
        ob[co*HW + pos] = v;
    }
}

// ============================================================================
// Kernel 2: bilinear gather + main GEMM, fp16 2-product mma.sync.
// 128pos x 64co, 16 warps as 4m x 4n (warp tile 32x16). 108KB smem, 2 CTA/SM.
// ============================================================================
#define S2_PI 0                          // int4 [9*128]  = 18432
#define S2_PW 18432                      // float4[9*128] = 18432
#define S2_V  36864                      // [2buf][128][VSTR] fp16 = 36864
#define S2_W  73728                      // [2buf][2split][64][VSTR] fp16 = 36864
#define S2_TOT 110592

__global__ void __launch_bounds__(512, 2) deform_main(
        float* __restrict__ out) {
    extern __shared__ char smem[];
    const int tid = threadIdx.x, lane = tid & 31, wid = tid >> 5;
    const int hw0 = blockIdx.x * M2;
    const int b   = blockIdx.y;
    const float* xt = g_xt + (size_t)b * HW * 64;

    int4*   pI = (int4*)  (smem + S2_PI);
    float4* pW = (float4*)(smem + S2_PW);

    // phase 0: clamped corner indices + validity/mask-folded weights
    for (int i = tid; i < 9*M2; i += 512) {
        int pos = i & 127;
        int k2  = i >> 7;
        int hw  = hw0 + pos;
        int ho  = hw / Ww;
        int wo  = hw - ho*Ww;
        const float* om = g_offmask + (size_t)b*NOFF*HW + hw;
        float dy = om[(2*k2    )*HW];
        float dx = om[(2*k2 + 1)*HW];
        float m  = om[(18 + k2 )*HW];
        int ky = k2 / 3, kx = k2 - ky*3;
        float py = dy + (float)(ho - 1 + ky);
        float px = dx + (float)(wo - 1 + kx);
        float fy = floorf(py), fx = floorf(px);
        float wy1 = py - fy, wx1 = px - fx;
        float wy0 = 1.f - wy1, wx0 = 1.f - wx1;
        int y0 = (int)fy, x0 = (int)fx;
        int y1 = y0 + 1,  x1 = x0 + 1;
        float vy0 = ((unsigned)y0 < Hh) ? 1.f : 0.f;
        float vy1 = ((unsigned)y1 < Hh) ? 1.f : 0.f;
        float vx0 = ((unsigned)x0 < Ww) ? 1.f : 0.f;
        float vx1 = ((unsigned)x1 < Ww) ? 1.f : 0.f;
        int y0c = min(max(y0, 0), Hh-1), y1c = min(max(y1, 0), Hh-1);
        int x0c = min(max(x0, 0), Ww-1), x1c = min(max(x1, 0), Ww-1);
        pI[i] = make_int4(y0c*Ww + x0c, y0c*Ww + x1c,
                          y1c*Ww + x0c, y1c*Ww + x1c);
        pW[i] = make_float4(wy0*wx0*m*vy0*vx0, wy0*wx1*m*vy0*vx1,
                            wy1*wx0*m*vy1*vx0, wy1*wx1*m*vy1*vx1);
    }
    __syncthreads();

    // gather: warp-task = one pos, lanes = channel pairs; single fp16 value
    auto stage = [&](int kc, int buf) {
        __half* vh = (__half*)(smem + S2_V) + buf*(M2*VSTR);
        const int c0 = lane * 2;
        #pragma unroll
        for (int tp = 0; tp < 8; tp++) {
            int pos = (wid << 3) + tp;
            int pk = (kc << 7) | pos;
            int4   id = pI[pk];     // warp-uniform -> broadcast LDS
            float4 w  = pW[pk];
            float2 a0 = *(const float2*)(xt + (size_t)id.x*64 + c0);
            float2 a1 = *(const float2*)(xt + (size_t)id.y*64 + c0);
            float2 a2 = *(const float2*)(xt + (size_t)id.z*64 + c0);
            float2 a3 = *(const float2*)(xt + (size_t)id.w*64 + c0);
            float v0 = w.x * a0.x;
            v0 = fmaf(w.y, a1.x, v0);
            v0 = fmaf(w.z, a2.x, v0);
            v0 = fmaf(w.w, a3.x, v0);
            float v1 = w.x * a0.y;
            v1 = fmaf(w.y, a1.y, v1);
            v1 = fmaf(w.z, a2.y, v1);
            v1 = fmaf(w.w, a3.y, v1);
            uint32_t hp;
            asm("cvt.rn.f16x2.f32 %0, %1, %2;" : "=r"(hp) : "f"(v1), "f"(v0));
            *(uint32_t*)(vh + pos*VSTR + c0) = hp;
        }
        const uint32_t* src = (const uint32_t*)(&g_wd[kc][0][0]);   // 4096 b32
        uint32_t* wd = (uint32_t*)(smem + S2_W) + buf*(2*64*VSTR/2);
        #pragma unroll
        for (int i = 0; i < 8; i++) {
            int idx = tid + i*512;
            int s = idx >> 11, r = (idx >> 5) & 63, w2 = idx & 31;
            wd[(s*64 + r)*(VSTR/2) + w2] = src[idx];
        }
    };

    const int g = lane >> 2, tig = lane & 3;
    const int R  = (wid >> 2) * 32;    // 4 m-tiles of 32 pos
    const int NB = (wid & 3) * 16;     // 4 n-tiles of 16 co
    float acc[2][2][4] = {};

    stage(0, 0);
    __syncthreads();

    for (int kc = 0; kc < NCH; kc++) {
        int cb = kc & 1;
        if (kc < NCH-1) stage(kc+1, cb ^ 1);
        const __half* vb = (const __half*)(smem + S2_V) + cb*(M2*VSTR);
        const __half* wb = (const __half*)(smem + S2_W) + cb*(2*64*VSTR);
        #pragma unroll
        for (int ks = 0; ks < 4; ks++) {
            uint32_t ah[2][4];
            #pragma unroll
            for (int mi = 0; mi < 2; mi++) {
                const __half* ar = vb + (R + mi*16 + g)*VSTR + ks*16 + 2*tig;
                ah[mi][0] = *(const uint32_t*)ar;
                ah[mi][1] = *(const uint32_t*)(ar + 8*VSTR);
                ah[mi][2] = *(const uint32_t*)(ar + 8);
                ah[mi][3] = *(const uint32_t*)(ar + 8*VSTR + 8);
            }
            #pragma unroll
            for (int ni = 0; ni < 2; ni++) {
                const __half* br = wb + (NB + ni*8 + g)*VSTR + ks*16 + 2*tig;
                uint32_t bh0 = *(const uint32_t*)br;
                uint32_t bh1 = *(const uint32_t*)(br + 8);
                uint32_t bl0 = *(const uint32_t*)(br + 64*VSTR);
                uint32_t bl1 = *(const uint32_t*)(br + 64*VSTR + 8);
                #pragma unroll
                for (int mi = 0; mi < 2; mi++) {
                    mma_f16(acc[mi][ni], ah[mi], bh0, bh1);
                    mma_f16(acc[mi][ni], ah[mi], bl0, bl1);
                }
            }
        }
        __syncthreads();
    }

    // epilogue: stage [64co][128pos] f32, then coalesced stores
    float* obuf = (float*)(smem + S2_V);
    #pragma unroll
    for (int mi = 0; mi < 2; mi++) {
        #pragma unroll
        for (int ni = 0; ni < 2; ni++) {
            int n0 = NB + ni*8 + 2*tig;
            int po = R + mi*16 + g;
            obuf[(n0    )*OSTR + po    ] = acc[mi][ni][0];
            obuf[(n0 + 1)*OSTR + po    ] = acc[mi][ni][1];
            obuf[(n0    )*OSTR + po + 8] = acc[mi][ni][2];
            obuf[(n0 + 1)*OSTR + po + 8] = acc[mi][ni][3];
        }
    }
    __syncthreads();
    float* ob = out + (size_t)b*COUT*HW + hw0;
    #pragma unroll
    for (int i = tid; i < COUT*32; i += 512) {
        int co = i >> 5, q = i & 31;
        float4 v = *(float4*)&obuf[co*OSTR + q*4];
        *(float4*)&ob[co*HW + q*4] = v;
    }
}

// ---------------------------------------------------------------------------
extern "C" void kernel_launch(void* const* d_in, const int* in_sizes, int n_in,
                              void* d_out, int out_size) {
    const float* x      = (const float*)d_in[0];
    const float* w_off  = (const float*)d_in[1];
    const float* b_off  = (const float*)d_in[2];
    const float* w_mask = (const float*)d_in[3];
    const float* b_mask = (const float*)d_in[4];
    const float* w_def  = (const float*)d_in[5];
    float* out = (float*)d_out;

    cudaFuncSetAttribute(offmask_conv, cudaFuncAttributeMaxDynamicSharedMemorySize, S1_TOT);
    cudaFuncSetAttribute(deform_main,  cudaFuncAttributeMaxDynamicSharedMemorySize, S2_TOT);

    prep_weights<<<216, 256>>>(w_off, w_mask, w_def);
    transpose_x<<<dim3(HW/32, Bn), 512>>>(x);
    offmask_conv<<<dim3(NT, Bn), 512, S1_TOT>>>(b_off, b_mask);
    deform_main <<<dim3(NT2, Bn), 512, S2_TOT>>>(out);
}

// round 12
// speedup vs baseline: 4.9883x; 1.1463x over previous
#include <cuda_runtime.h>
#include <cuda_bf16.h>
#include <cuda_fp16.h>
#include <cstdint>
#include <math.h>

#define Bn   2
#define Cc   64
#define Hh   224
#define Ww   224
#define HW   (Hh*Ww)
#define NOFF 27
#define COUT 64
#define Jdim 576
#define NCH  9             // chunks == k2 values (k2-major K ordering)
#define TILE 128           // kernel1 tile
#define M2   128           // kernel2 tile
#define NT   (HW/TILE)     // 392
#define NT2  (HW/M2)       // 392
#define VSTR 72            // padded k-stride (elems) -> conflict-free
#define OSTR 132           // epilogue pos-stride

// K ordering: j' = k2*64 + c  (chunk kc == kernel tap k2, inner dim = channel)

// ---------------- device globals (no allocation allowed) -------------------
__device__ float g_offmask[Bn*NOFF*HW];                 // conv1 out (mask sigmoided)
__device__ __align__(16) float g_xt[(size_t)Bn*HW*Cc];  // x transposed: [b][hw][c]
__device__ __align__(16) __half g_wd[NCH][2][COUT*64];  // deform W fp16 [k2][hi/lo][co][c]
__device__ __align__(16) __half g_wo[NCH][2][32*64];    // off/mask W fp16 (padded 32 ch)

// ---------------- mma.sync helper (generic PTX, works on compute_103) ------
__device__ __forceinline__ void mma_f16(float* c, const uint32_t* a,
                                        uint32_t b0, uint32_t b1) {
    asm volatile("mma.sync.aligned.m16n8k16.row.col.f32.f16.f16.f32 "
        "{%0,%1,%2,%3},{%4,%5,%6,%7},{%8,%9},{%0,%1,%2,%3};"
        : "+f"(c[0]), "+f"(c[1]), "+f"(c[2]), "+f"(c[3])
        : "r"(a[0]), "r"(a[1]), "r"(a[2]), "r"(a[3]), "r"(b0), "r"(b1));
}

// ---------------- prep: weights fp16 hi/lo, k2-major K ---------------------
__global__ void prep_weights(const float* __restrict__ w_off,
                             const float* __restrict__ w_mask,
                             const float* __restrict__ w_def) {
    int idx = blockIdx.x * 256 + threadIdx.x;
    if (idx < NCH*COUT*64) {
        int kc = idx / (COUT*64), r = idx % (COUT*64);
        int co = r >> 6, c = r & 63;
        float v = w_def[co*Jdim + c*9 + kc];
        __half hi = __float2half(v);
        __half lo = __float2half(v - __half2float(hi));
        g_wd[kc][0][r] = hi;
        g_wd[kc][1][r] = lo;
    } else {
        int i2 = idx - NCH*COUT*64;
        if (i2 < NCH*32*64) {
            int kc = i2 / (32*64), r = i2 % (32*64);
            int co = r >> 6, c = r & 63;
            float v = 0.f;
            if (co < 18)      v = w_off[co*Jdim + c*9 + kc];
            else if (co < 27) v = w_mask[(co-18)*Jdim + c*9 + kc];
            __half hi = __float2half(v);
            __half lo = __float2half(v - __half2float(hi));
            g_wo[kc][0][r] = hi;
            g_wo[kc][1][r] = lo;
        }
    }
}

// ---------------- transpose x: [b][c][hw] -> [b][hw][c] ---------------------
__global__ void __launch_bounds__(512) transpose_x(const float* __restrict__ x) {
    __shared__ float tile[64][33];
    const int hw0 = blockIdx.x * 32;
    const int b   = blockIdx.y;
    const int l = threadIdx.x & 31, w = threadIdx.x >> 5;   // w 0..15
    const float* xb = x + (size_t)b*Cc*HW;
    #pragma unroll
    for (int i = 0; i < 4; i++) {
        int c = w + 16*i;
        tile[c][l] = xb[(size_t)c*HW + hw0 + l];
    }
    __syncthreads();
    const int c  = threadIdx.x & 63;
    const int hq = threadIdx.x >> 6;    // 0..7
    float* xt = g_xt + (size_t)b*HW*64;
    #pragma unroll
    for (int i = 0; i < 4; i++) {
        int hw = hq + 8*i;
        xt[(size_t)(hw0 + hw)*64 + c] = tile[c][hw];
    }
}

// ============================================================================
// Kernel 1: offset+mask conv (27ch, padded 32), fp16 2-product mma.sync.
// 128pos x 32co, 16 warps 8m x 2n. 55KB smem -> 3-4 CTA/SM.
// ============================================================================
#define S1_HO 0
#define S1_WO 512
#define S1_V  1024                       // [2buf][128][VSTR] fp16 = 36864
#define S1_W  (S1_V + 36864)             // [2buf][2split][32][VSTR] fp16 = 18432
#define S1_TOT (S1_W + 18432)            // 56320

__global__ void __launch_bounds__(512, 2) offmask_conv(
        const float* __restrict__ b_off,
        const float* __restrict__ b_mask) {
    extern __shared__ char smem[];
    const int tid = threadIdx.x, lane = tid & 31, wid = tid >> 5;
    const int hw0 = blockIdx.x * TILE;
    const int b   = blockIdx.y;
    const float* xt = g_xt + (size_t)b * HW * 64;

    int* sHO = (int*)(smem + S1_HO);
    int* sWO = (int*)(smem + S1_WO);
    if (tid < TILE) {
        int hw = hw0 + tid, ho = hw / Ww;
        sHO[tid] = ho; sWO[tid] = hw - ho*Ww;
    }
    __syncthreads();

    auto stage = [&](int kc, int buf) {
        __half* vh = (__half*)(smem + S1_V) + buf*(TILE*VSTR);
        const int ky = kc / 3, kx = kc - ky*3;
        const int c0 = lane * 2;
        #pragma unroll
        for (int tp = 0; tp < 8; tp++) {
            int pos = (wid << 3) + tp;
            int iy = sHO[pos] + ky - 1;
            int ix = sWO[pos] + kx - 1;
            float2 a = make_float2(0.f, 0.f);
            if (((unsigned)iy < Hh) && ((unsigned)ix < Ww))
                a = *(const float2*)(xt + (size_t)(iy*Ww + ix)*64 + c0);
            uint32_t hp;
            asm("cvt.rn.f16x2.f32 %0, %1, %2;" : "=r"(hp) : "f"(a.y), "f"(a.x));
            *(uint32_t*)(vh + pos*VSTR + c0) = hp;
        }
        const uint32_t* src = (const uint32_t*)(&g_wo[kc][0][0]);   // 2048 b32
        uint32_t* wd = (uint32_t*)(smem + S1_W) + buf*(2*32*VSTR/2);
        #pragma unroll
        for (int i = 0; i < 4; i++) {
            int idx = tid + i*512;
            int s = idx >> 10, r = (idx >> 5) & 31, w = idx & 31;
            wd[(s*32 + r)*(VSTR/2) + w] = src[idx];
        }
    };

    const int g = lane >> 2, tig = lane & 3;
    const int R  = (wid >> 1) * 16;
    const int NB = (wid & 1) * 16;
    float acc[2][4] = {};

    stage(0, 0);
    __syncthreads();

    for (int kc = 0; kc < NCH; kc++) {
        int cb = kc & 1;
        if (kc < NCH-1) stage(kc+1, cb ^ 1);
        const __half* vb = (const __half*)(smem + S1_V) + cb*(TILE*VSTR);
        const __half* wb = (const __half*)(smem + S1_W) + cb*(2*32*VSTR);
        #pragma unroll
        for (int ks = 0; ks < 4; ks++) {
            const __half* ar = vb + (R+g)*VSTR + ks*16 + 2*tig;
            uint32_t ah[4];
            ah[0] = *(const uint32_t*)ar;
            ah[1] = *(const uint32_t*)(ar + 8*VSTR);
            ah[2] = *(const uint32_t*)(ar + 8);
            ah[3] = *(const uint32_t*)(ar + 8*VSTR + 8);
            #pragma unroll
            for (int t = 0; t < 2; t++) {
                const __half* br = wb + (NB + t*8 + g)*VSTR + ks*16 + 2*tig;
                uint32_t bh0 = *(const uint32_t*)br;
                uint32_t bh1 = *(const uint32_t*)(br + 8);
                uint32_t bl0 = *(const uint32_t*)(br + 32*VSTR);
                uint32_t bl1 = *(const uint32_t*)(br + 32*VSTR + 8);
                mma_f16(acc[t], ah, bh0, bh1);
                mma_f16(acc[t], ah, bl0, bl1);
            }
        }
        __syncthreads();
    }

    float* obuf = (float*)(smem + S1_V);
    #pragma unroll
    for (int t = 0; t < 2; t++) {
        int n0 = NB + t*8 + 2*tig;
        obuf[(n0    )*OSTR + R+g    ] = acc[t][0];
        obuf[(n0 + 1)*OSTR + R+g    ] = acc[t][1];
        obuf[(n0    )*OSTR + R+g + 8] = acc[t][2];
        obuf[(n0 + 1)*OSTR + R+g + 8] = acc[t][3];
    }
    __syncthreads();
    float* ob = g_offmask + (size_t)b*NOFF*HW + hw0;
    for (int i = tid; i < NOFF*TILE; i += 512) {
        int co = i >> 7, pos = i & 127;
        float v = obuf[co*OSTR + pos] + (co < 18 ? b_off[co] : b_mask[co-18]);
        if (co >= 18) v = 1.f / (1.f + __expf(-v));
        ob[co*HW + pos] = v;
    }
}

// ============================================================================
// Kernel 2: bilinear gather + main GEMM, fp16 2-product mma.sync.
// 128pos x 64co, 16 warps 4m x 4n. Vectorized LDG.128 gather.
// ============================================================================
#define S2_PI 0                          // int4 [9*128]  = 18432
#define S2_PW 18432                      // float4[9*128] = 18432
#define S2_V  36864                      // [2buf][128][VSTR] fp16 = 36864
#define S2_W  73728                      // [2buf][2split][64][VSTR] fp16 = 36864
#define S2_TOT 110592

__global__ void __launch_bounds__(512, 2) deform_main(
        float* __restrict__ out) {
    extern __shared__ char smem[];
    const int tid = threadIdx.x, lane = tid & 31, wid = tid >> 5;
    const int hw0 = blockIdx.x * M2;
    const int b   = blockIdx.y;
    const float* xt = g_xt + (size_t)b * HW * 64;

    int4*   pI = (int4*)  (smem + S2_PI);
    float4* pW = (float4*)(smem + S2_PW);

    // phase 0: clamped corner indices + validity/mask-folded weights
    for (int i = tid; i < 9*M2; i += 512) {
        int pos = i & 127;
        int k2  = i >> 7;
        int hw  = hw0 + pos;
        int ho  = hw / Ww;
        int wo  = hw - ho*Ww;
        const float* om = g_offmask + (size_t)b*NOFF*HW + hw;
        float dy = om[(2*k2    )*HW];
        float dx = om[(2*k2 + 1)*HW];
        float m  = om[(18 + k2 )*HW];
        int ky = k2 / 3, kx = k2 - ky*3;
        float py = dy + (float)(ho - 1 + ky);
        float px = dx + (float)(wo - 1 + kx);
        float fy = floorf(py), fx = floorf(px);
        float wy1 = py - fy, wx1 = px - fx;
        float wy0 = 1.f - wy1, wx0 = 1.f - wx1;
        int y0 = (int)fy, x0 = (int)fx;
        int y1 = y0 + 1,  x1 = x0 + 1;
        float vy0 = ((unsigned)y0 < Hh) ? 1.f : 0.f;
        float vy1 = ((unsigned)y1 < Hh) ? 1.f : 0.f;
        float vx0 = ((unsigned)x0 < Ww) ? 1.f : 0.f;
        float vx1 = ((unsigned)x1 < Ww) ? 1.f : 0.f;
        int y0c = min(max(y0, 0), Hh-1), y1c = min(max(y1, 0), Hh-1);
        int x0c = min(max(x0, 0), Ww-1), x1c = min(max(x1, 0), Ww-1);
        pI[i] = make_int4(y0c*Ww + x0c, y0c*Ww + x1c,
                          y1c*Ww + x0c, y1c*Ww + x1c);
        pW[i] = make_float4(wy0*wx0*m*vy0*vx0, wy0*wx1*m*vy0*vx1,
                            wy1*wx0*m*vy1*vx0, wy1*wx1*m*vy1*vx1);
    }
    __syncthreads();

    // gather: half-warp per pos, lanes = channel quads (LDG.128 per corner)
    auto stage = [&](int kc, int buf) {
        __half* vh = (__half*)(smem + S2_V) + buf*(M2*VSTR);
        const int h  = lane >> 4;          // 0..1
        const int c0 = (lane & 15) * 4;    // 0..60
        #pragma unroll
        for (int tp = 0; tp < 4; tp++) {
            int pos = (wid << 3) + tp*2 + h;
            int pk = (kc << 7) | pos;
            int4   id = pI[pk];
            float4 w  = pW[pk];
            float4 a0 = *(const float4*)(xt + (size_t)id.x*64 + c0);
            float4 a1 = *(const float4*)(xt + (size_t)id.y*64 + c0);
            float4 a2 = *(const float4*)(xt + (size_t)id.z*64 + c0);
            float4 a3 = *(const float4*)(xt + (size_t)id.w*64 + c0);
            float v0 = fmaf(w.w, a3.x, fmaf(w.z, a2.x, fmaf(w.y, a1.x, w.x*a0.x)));
            float v1 = fmaf(w.w, a3.y, fmaf(w.z, a2.y, fmaf(w.y, a1.y, w.x*a0.y)));
            float v2 = fmaf(w.w, a3.z, fmaf(w.z, a2.z, fmaf(w.y, a1.z, w.x*a0.z)));
            float v3 = fmaf(w.w, a3.w, fmaf(w.z, a2.w, fmaf(w.y, a1.w, w.x*a0.w)));
            uint2 hp;
            asm("cvt.rn.f16x2.f32 %0, %1, %2;" : "=r"(hp.x) : "f"(v1), "f"(v0));
            asm("cvt.rn.f16x2.f32 %0, %1, %2;" : "=r"(hp.y) : "f"(v3), "f"(v2));
            *(uint2*)(vh + pos*VSTR + c0) = hp;
        }
        const uint32_t* src = (const uint32_t*)(&g_wd[kc][0][0]);   // 4096 b32
        uint32_t* wd = (uint32_t*)(smem + S2_W) + buf*(2*64*VSTR/2);
        #pragma unroll
        for (int i = 0; i < 8; i++) {
            int idx = tid + i*512;
            int s = idx >> 11, r = (idx >> 5) & 63, w2 = idx & 31;
            wd[(s*64 + r)*(VSTR/2) + w2] = src[idx];
        }
    };

    const int g = lane >> 2, tig = lane & 3;
    const int R  = (wid >> 2) * 32;    // 4 m-tiles of 32 pos
    const int NB = (wid & 3) * 16;     // 4 n-tiles of 16 co
    float acc[2][2][4] = {};

    stage(0, 0);
    __syncthreads();

    for (int kc = 0; kc < NCH; kc++) {
        int cb = kc & 1;
        if (kc < NCH-1) stage(kc+1, cb ^ 1);
        const __half* vb = (const __half*)(smem + S2_V) + cb*(M2*VSTR);
        const __half* wb = (const __half*)(smem + S2_W) + cb*(2*64*VSTR);
        #pragma unroll
        for (int ks = 0; ks < 4; ks++) {
            uint32_t ah[2][4];
            #pragma unroll
            for (int mi = 0; mi < 2; mi++) {
                const __half* ar = vb + (R + mi*16 + g)*VSTR + ks*16 + 2*tig;
                ah[mi][0] = *(const uint32_t*)ar;
                ah[mi][1] = *(const uint32_t*)(ar + 8*VSTR);
                ah[mi][2] = *(const uint32_t*)(ar + 8);
                ah[mi][3] = *(const uint32_t*)(ar + 8*VSTR + 8);
            }
            #pragma unroll
            for (int ni = 0; ni < 2; ni++) {
                const __half* br = wb + (NB + ni*8 + g)*VSTR + ks*16 + 2*tig;
                uint32_t bh0 = *(const uint32_t*)br;
                uint32_t bh1 = *(const uint32_t*)(br + 8);
                uint32_t bl0 = *(const uint32_t*)(br + 64*VSTR);
                uint32_t bl1 = *(const uint32_t*)(br + 64*VSTR + 8);
                #pragma unroll
                for (int mi = 0; mi < 2; mi++) {
                    mma_f16(acc[mi][ni], ah[mi], bh0, bh1);
                    mma_f16(acc[mi][ni], ah[mi], bl0, bl1);
                }
            }
        }
        __syncthreads();
    }

    // epilogue: stage [64co][128pos] f32, then coalesced stores
    float* obuf = (float*)(smem + S2_V);
    #pragma unroll
    for (int mi = 0; mi < 2; mi++) {
        #pragma unroll
        for (int ni = 0; ni < 2; ni++) {
            int n0 = NB + ni*8 + 2*tig;
            int po = R + mi*16 + g;
            obuf[(n0    )*OSTR + po    ] = acc[mi][ni][0];
            obuf[(n0 + 1)*OSTR + po    ] = acc[mi][ni][1];
            obuf[(n0    )*OSTR + po + 8] = acc[mi][ni][2];
            obuf[(n0 + 1)*OSTR + po + 8] = acc[mi][ni][3];
        }
    }
    __syncthreads();
    float* ob = out + (size_t)b*COUT*HW + hw0;
    #pragma unroll
    for (int i = tid; i < COUT*32; i += 512) {
        int co = i >> 5, q = i & 31;
        float4 v = *(float4*)&obuf[co*OSTR + q*4];
        *(float4*)&ob[co*HW + q*4] = v;
    }
}

// ---------------------------------------------------------------------------
extern "C" void kernel_launch(void* const* d_in, const int* in_sizes, int n_in,
                              void* d_out, int out_size) {
    const float* x      = (const float*)d_in[0];
    const float* w_off  = (const float*)d_in[1];
    const float* b_off  = (const float*)d_in[2];
    const float* w_mask = (const float*)d_in[3];
    const float* b_mask = (const float*)d_in[4];
    const float* w_def  = (const float*)d_in[5];
    float* out = (float*)d_out;

    cudaFuncSetAttribute(offmask_conv, cudaFuncAttributeMaxDynamicSharedMemorySize, S1_TOT);
    cudaFuncSetAttribute(deform_main,  cudaFuncAttributeMaxDynamicSharedMemorySize, S2_TOT);

    prep_weights<<<216, 256>>>(w_off, w_mask, w_def);
    transpose_x<<<dim3(HW/32, Bn), 512>>>(x);
    offmask_conv<<<dim3(NT, Bn), 512, S1_TOT>>>(b_off, b_mask);
    deform_main <<<dim3(NT2, Bn), 512, S2_TOT>>>(out);
}

// round 13
// speedup vs baseline: 7.6053x; 1.5246x over previous
#include <cuda_runtime.h>
#include <cuda_fp16.h>
#include <cstdint>
#include <math.h>

#define Bn   2
#define Cc   64
#define Hh   224
#define Ww   224
#define HW   (Hh*Ww)
#define NOFF 27
#define COUT 64
#define Jdim 576
#define NCH  9             // chunks == k2 values (k2-major K ordering)
#define TILE 128           // kernel1 tile
#define M2   128           // kernel2 tile
#define NT   (HW/TILE)     // 392
#define NT2  (HW/M2)       // 392
#define VSTR 72            // padded k-stride (elems) -> conflict-free
#define OSTR 132           // epilogue pos-stride

// K ordering: j' = k2*64 + c  (chunk kc == kernel tap k2, inner dim = channel)

// ---------------- device globals (no allocation allowed) -------------------
__device__ float g_offmask[Bn*NOFF*HW];                 // conv1 out (mask sigmoided)
__device__ __align__(16) __half g_xt[(size_t)Bn*HW*Cc]; // x transposed fp16: [b][hw][c]
__device__ __align__(16) __half g_wd[NCH][COUT*64];     // deform W fp16 [k2][co][c]
__device__ __align__(16) __half g_wo[NCH][32*64];       // off/mask W fp16 (padded 32 ch)

// ---------------- mma.sync helper (generic PTX, works on compute_103) ------
__device__ __forceinline__ void mma_f16(float* c, const uint32_t* a,
                                        uint32_t b0, uint32_t b1) {
    asm volatile("mma.sync.aligned.m16n8k16.row.col.f32.f16.f16.f32 "
        "{%0,%1,%2,%3},{%4,%5,%6,%7},{%8,%9},{%0,%1,%2,%3};"
        : "+f"(c[0]), "+f"(c[1]), "+f"(c[2]), "+f"(c[3])
        : "r"(a[0]), "r"(a[1]), "r"(a[2]), "r"(a[3]), "r"(b0), "r"(b1));
}

// ---------------- prep: weights fp16, k2-major K ----------------------------
__global__ void prep_weights(const float* __restrict__ w_off,
                             const float* __restrict__ w_mask,
                             const float* __restrict__ w_def) {
    int idx = blockIdx.x * 256 + threadIdx.x;
    if (idx < NCH*COUT*64) {
        int kc = idx / (COUT*64), r = idx % (COUT*64);
        int co = r >> 6, c = r & 63;
        g_wd[kc][r] = __float2half(w_def[co*Jdim + c*9 + kc]);
    } else {
        int i2 = idx - NCH*COUT*64;
        if (i2 < NCH*32*64) {
            int kc = i2 / (32*64), r = i2 % (32*64);
            int co = r >> 6, c = r & 63;
            float v = 0.f;
            if (co < 18)      v = w_off[co*Jdim + c*9 + kc];
            else if (co < 27) v = w_mask[(co-18)*Jdim + c*9 + kc];
            g_wo[kc][r] = __float2half(v);
        }
    }
}

// ---------------- transpose x: [b][c][hw] fp32 -> [b][hw][c] fp16 -----------
__global__ void __launch_bounds__(512) transpose_x(const float* __restrict__ x) {
    __shared__ float tile[64][33];
    const int hw0 = blockIdx.x * 32;
    const int b   = blockIdx.y;
    const int l = threadIdx.x & 31, w = threadIdx.x >> 5;   // w 0..15
    const float* xb = x + (size_t)b*Cc*HW;
    #pragma unroll
    for (int i = 0; i < 4; i++) {
        int c = w + 16*i;
        tile[c][l] = xb[(size_t)c*HW + hw0 + l];
    }
    __syncthreads();
    const int c2 = (threadIdx.x & 31) * 2;
    const int hq = threadIdx.x >> 5;    // 0..15
    __half* xt = g_xt + (size_t)b*HW*64;
    #pragma unroll
    for (int i = 0; i < 2; i++) {
        int hw = hq + 16*i;
        __half2 hh = __floats2half2_rn(tile[c2][hw], tile[c2+1][hw]);
        *(__half2*)(xt + (size_t)(hw0 + hw)*64 + c2) = hh;
    }
}

// ============================================================================
// Kernel 1: offset+mask conv (27ch, padded 32), fp16 single-product mma.sync.
// 128pos x 32co, 16 warps 8m x 2n. Gather = fp16 copy from x_t.
// ============================================================================
#define S1_HO 0
#define S1_WO 512
#define S1_V  1024                       // [2buf][128][VSTR] fp16 = 36864
#define S1_W  (S1_V + 36864)             // [2buf][32][VSTR] fp16 = 9216
#define S1_TOT (S1_W + 9216)             // 47104

__global__ void __launch_bounds__(512, 2) offmask_conv(
        const float* __restrict__ b_off,
        const float* __restrict__ b_mask) {
    extern __shared__ char smem[];
    const int tid = threadIdx.x, lane = tid & 31, wid = tid >> 5;
    const int hw0 = blockIdx.x * TILE;
    const int b   = blockIdx.y;
    const __half* xt = g_xt + (size_t)b * HW * 64;

    int* sHO = (int*)(smem + S1_HO);
    int* sWO = (int*)(smem + S1_WO);
    if (tid < TILE) {
        int hw = hw0 + tid, ho = hw / Ww;
        sHO[tid] = ho; sWO[tid] = hw - ho*Ww;
    }
    __syncthreads();

    auto stage = [&](int kc, int buf) {
        __half* vh = (__half*)(smem + S1_V) + buf*(TILE*VSTR);
        const int ky = kc / 3, kx = kc - ky*3;
        const int h  = lane >> 4;          // 0..1
        const int c0 = (lane & 15) * 4;    // channel quad
        #pragma unroll
        for (int tp = 0; tp < 4; tp++) {
            int pos = (wid << 3) + tp*2 + h;
            int iy = sHO[pos] + ky - 1;
            int ix = sWO[pos] + kx - 1;
            uint2 a = make_uint2(0u, 0u);
            if (((unsigned)iy < Hh) && ((unsigned)ix < Ww))
                a = *(const uint2*)(xt + (size_t)(iy*Ww + ix)*64 + c0);
            *(uint2*)(vh + pos*VSTR + c0) = a;
        }
        const uint32_t* src = (const uint32_t*)(&g_wo[kc][0]);   // 1024 b32
        uint32_t* wd = (uint32_t*)(smem + S1_W) + buf*(32*VSTR/2);
        #pragma unroll
        for (int i = 0; i < 2; i++) {
            int idx = tid + i*512;
            int r = idx >> 5, w = idx & 31;
            wd[r*(VSTR/2) + w] = src[idx];
        }
    };

    const int g = lane >> 2, tig = lane & 3;
    const int R  = (wid >> 1) * 16;
    const int NB = (wid & 1) * 16;
    float acc[2][4] = {};

    stage(0, 0);
    __syncthreads();

    for (int kc = 0; kc < NCH; kc++) {
        int cb = kc & 1;
        if (kc < NCH-1) stage(kc+1, cb ^ 1);
        const __half* vb = (const __half*)(smem + S1_V) + cb*(TILE*VSTR);
        const __half* wb = (const __half*)(smem + S1_W) + cb*(32*VSTR);
        #pragma unroll
        for (int ks = 0; ks < 4; ks++) {
            const __half* ar = vb + (R+g)*VSTR + ks*16 + 2*tig;
            uint32_t ah[4];
            ah[0] = *(const uint32_t*)ar;
            ah[1] = *(const uint32_t*)(ar + 8*VSTR);
            ah[2] = *(const uint32_t*)(ar + 8);
            ah[3] = *(const uint32_t*)(ar + 8*VSTR + 8);
            #pragma unroll
            for (int t = 0; t < 2; t++) {
                const __half* br = wb + (NB + t*8 + g)*VSTR + ks*16 + 2*tig;
                uint32_t bh0 = *(const uint32_t*)br;
                uint32_t bh1 = *(const uint32_t*)(br + 8);
                mma_f16(acc[t], ah, bh0, bh1);
            }
        }
        __syncthreads();
    }

    float* obuf = (float*)(smem + S1_V);
    #pragma unroll
    for (int t = 0; t < 2; t++) {
        int n0 = NB + t*8 + 2*tig;
        obuf[(n0    )*OSTR + R+g    ] = acc[t][0];
        obuf[(n0 + 1)*OSTR + R+g    ] = acc[t][1];
        obuf[(n0    )*OSTR + R+g + 8] = acc[t][2];
        obuf[(n0 + 1)*OSTR + R+g + 8] = acc[t][3];
    }
    __syncthreads();
    float* ob = g_offmask + (size_t)b*NOFF*HW + hw0;
    for (int i = tid; i < NOFF*TILE; i += 512) {
        int co = i >> 7, pos = i & 127;
        float v = obuf[co*OSTR + pos] + (co < 18 ? b_off[co] : b_mask[co-18]);
        if (co >= 18) v = 1.f / (1.f + __expf(-v));
        ob[co*HW + pos] = v;
    }
}

// ============================================================================
// Kernel 2: bilinear gather + main GEMM, fp16 single-product mma.sync.
// 128pos x 64co, 16 warps 4m x 4n. fp16 x_t: one 128B line per corner.
// ============================================================================
#define S2_PI 0                          // int4 [9*128]  = 18432
#define S2_PW 18432                      // float4[9*128] = 18432
#define S2_V  36864                      // [2buf][128][VSTR] fp16 = 36864
#define S2_W  73728                      // [2buf][64][VSTR] fp16 = 18432
#define S2_TOT 92160

__global__ void __launch_bounds__(512, 2) deform_main(
        float* __restrict__ out) {
    extern __shared__ char smem[];
    const int tid = threadIdx.x, lane = tid & 31, wid = tid >> 5;
    const int hw0 = blockIdx.x * M2;
    const int b   = blockIdx.y;
    const __half* xt = g_xt + (size_t)b * HW * 64;

    int4*   pI = (int4*)  (smem + S2_PI);
    float4* pW = (float4*)(smem + S2_PW);

    // phase 0: clamped corner indices + validity/mask-folded weights
    for (int i = tid; i < 9*M2; i += 512) {
        int pos = i & 127;
        int k2  = i >> 7;
        int hw  = hw0 + pos;
        int ho  = hw / Ww;
        int wo  = hw - ho*Ww;
        const float* om = g_offmask + (size_t)b*NOFF*HW + hw;
        float dy = om[(2*k2    )*HW];
        float dx = om[(2*k2 + 1)*HW];
        float m  = om[(18 + k2 )*HW];
        int ky = k2 / 3, kx = k2 - ky*3;
        float py = dy + (float)(ho - 1 + ky);
        float px = dx + (float)(wo - 1 + kx);
        float fy = floorf(py), fx = floorf(px);
        float wy1 = py - fy, wx1 = px - fx;
        float wy0 = 1.f - wy1, wx0 = 1.f - wx1;
        int y0 = (int)fy, x0 = (int)fx;
        int y1 = y0 + 1,  x1 = x0 + 1;
        float vy0 = ((unsigned)y0 < Hh) ? 1.f : 0.f;
        float vy1 = ((unsigned)y1 < Hh) ? 1.f : 0.f;
        float vx0 = ((unsigned)x0 < Ww) ? 1.f : 0.f;
        float vx1 = ((unsigned)x1 < Ww) ? 1.f : 0.f;
        int y0c = min(max(y0, 0), Hh-1), y1c = min(max(y1, 0), Hh-1);
        int x0c = min(max(x0, 0), Ww-1), x1c = min(max(x1, 0), Ww-1);
        pI[i] = make_int4(y0c*Ww + x0c, y0c*Ww + x1c,
                          y1c*Ww + x0c, y1c*Ww + x1c);
        pW[i] = make_float4(wy0*wx0*m*vy0*vx0, wy0*wx1*m*vy0*vx1,
                            wy1*wx0*m*vy1*vx0, wy1*wx1*m*vy1*vx1);
    }
    __syncthreads();

    // gather: half-warp per pos, lanes = channel quads; fp32 bilinear
    auto stage = [&](int kc, int buf) {
        __half* vh = (__half*)(smem + S2_V) + buf*(M2*VSTR);
        const int h  = lane >> 4;          // 0..1
        const int c0 = (lane & 15) * 4;    // 0..60
        #pragma unroll
        for (int tp = 0; tp < 4; tp++) {
            int pos = (wid << 3) + tp*2 + h;
            int pk = (kc << 7) | pos;
            int4   id = pI[pk];
            float4 w  = pW[pk];
            uint2 r0 = *(const uint2*)(xt + (size_t)id.x*64 + c0);
            uint2 r1 = *(const uint2*)(xt + (size_t)id.y*64 + c0);
            uint2 r2 = *(const uint2*)(xt + (size_t)id.z*64 + c0);
            uint2 r3 = *(const uint2*)(xt + (size_t)id.w*64 + c0);
            float2 a0l = __half22float2(*(__half2*)&r0.x), a0h = __half22float2(*(__half2*)&r0.y);
            float2 a1l = __half22float2(*(__half2*)&r1.x), a1h = __half22float2(*(__half2*)&r1.y);
            float2 a2l = __half22float2(*(__half2*)&r2.x), a2h = __half22float2(*(__half2*)&r2.y);
            float2 a3l = __half22float2(*(__half2*)&r3.x), a3h = __half22float2(*(__half2*)&r3.y);
            float v0 = fmaf(w.w, a3l.x, fmaf(w.z, a2l.x, fmaf(w.y, a1l.x, w.x*a0l.x)));
            float v1 = fmaf(w.w, a3l.y, fmaf(w.z, a2l.y, fmaf(w.y, a1l.y, w.x*a0l.y)));
            float v2 = fmaf(w.w, a3h.x, fmaf(w.z, a2h.x, fmaf(w.y, a1h.x, w.x*a0h.x)));
            float v3 = fmaf(w.w, a3h.y, fmaf(w.z, a2h.y, fmaf(w.y, a1h.y, w.x*a0h.y)));
            uint2 hp;
            asm("cvt.rn.f16x2.f32 %0, %1, %2;" : "=r"(hp.x) : "f"(v1), "f"(v0));
            asm("cvt.rn.f16x2.f32 %0, %1, %2;" : "=r"(hp.y) : "f"(v3), "f"(v2));
            *(uint2*)(vh + pos*VSTR + c0) = hp;
        }
        const uint32_t* src = (const uint32_t*)(&g_wd[kc][0]);   // 2048 b32
        uint32_t* wd = (uint32_t*)(smem + S2_W) + buf*(64*VSTR/2);
        #pragma unroll
        for (int i = 0; i < 4; i++) {
            int idx = tid + i*512;
            int r = idx >> 5, w2 = idx & 31;
            wd[r*(VSTR/2) + w2] = src[idx];
        }
    };

    const int g = lane >> 2, tig = lane & 3;
    const int R  = (wid >> 2) * 32;    // 4 m-tiles of 32 pos
    const int NB = (wid & 3) * 16;     // 4 n-tiles of 16 co
    float acc[2][2][4] = {};

    stage(0, 0);
    __syncthreads();

    for (int kc = 0; kc < NCH; kc++) {
        int cb = kc & 1;
        if (kc < NCH-1) stage(kc+1, cb ^ 1);
        const __half* vb = (const __half*)(smem + S2_V) + cb*(M2*VSTR);
        const __half* wb = (const __half*)(smem + S2_W) + cb*(64*VSTR);
        #pragma unroll
        for (int ks = 0; ks < 4; ks++) {
            uint32_t ah[2][4];
            #pragma unroll
            for (int mi = 0; mi < 2; mi++) {
                const __half* ar = vb + (R + mi*16 + g)*VSTR + ks*16 + 2*tig;
                ah[mi][0] = *(const uint32_t*)ar;
                ah[mi][1] = *(const uint32_t*)(ar + 8*VSTR);
                ah[mi][2] = *(const uint32_t*)(ar + 8);
                ah[mi][3] = *(const uint32_t*)(ar + 8*VSTR + 8);
            }
            #pragma unroll
            for (int ni = 0; ni < 2; ni++) {
                const __half* br = wb + (NB + ni*8 + g)*VSTR + ks*16 + 2*tig;
                uint32_t bh0 = *(const uint32_t*)br;
                uint32_t bh1 = *(const uint32_t*)(br + 8);
                #pragma unroll
                for (int mi = 0; mi < 2; mi++)
                    mma_f16(acc[mi][ni], ah[mi], bh0, bh1);
            }
        }
        __syncthreads();
    }

    // epilogue: stage [64co][128pos] f32, then coalesced stores
    float* obuf = (float*)(smem + S2_V);
    #pragma unroll
    for (int mi = 0; mi < 2; mi++) {
        #pragma unroll
        for (int ni = 0; ni < 2; ni++) {
            int n0 = NB + ni*8 + 2*tig;
            int po = R + mi*16 + g;
            obuf[(n0    )*OSTR + po    ] = acc[mi][ni][0];
            obuf[(n0 + 1)*OSTR + po    ] = acc[mi][ni][1];
            obuf[(n0    )*OSTR + po + 8] = acc[mi][ni][2];
            obuf[(n0 + 1)*OSTR + po + 8] = acc[mi][ni][3];
        }
    }
    __syncthreads();
    float* ob = out + (size_t)b*COUT*HW + hw0;
    #pragma unroll
    for (int i = tid; i < COUT*32; i += 512) {
        int co = i >> 5, q = i & 31;
        float4 v = *(float4*)&obuf[co*OSTR + q*4];
        *(float4*)&ob[co*HW + q*4] = v;
    }
}

// ---------------------------------------------------------------------------
extern "C" void kernel_launch(void* const* d_in, const int* in_sizes, int n_in,
                              void* d_out, int out_size) {
    const float* x      = (const float*)d_in[0];
    const float* w_off  = (const float*)d_in[1];
    const float* b_off  = (const float*)d_in[2];
    const float* w_mask = (const float*)d_in[3];
    const float* b_mask = (const float*)d_in[4];
    const float* w_def  = (const float*)d_in[5];
    float* out = (float*)d_out;

    cudaFuncSetAttribute(offmask_conv, cudaFuncAttributeMaxDynamicSharedMemorySize, S1_TOT);
    cudaFuncSetAttribute(deform_main,  cudaFuncAttributeMaxDynamicSharedMemorySize, S2_TOT);

    prep_weights<<<216, 256>>>(w_off, w_mask, w_def);
    transpose_x<<<dim3(HW/32, Bn), 512>>>(x);
    offmask_conv<<<dim3(NT, Bn), 512, S1_TOT>>>(b_off, b_mask);
    deform_main <<<dim3(NT2, Bn), 512, S2_TOT>>>(out);
}

// round 14
// speedup vs baseline: 8.7817x; 1.1547x over previous
#include <cuda_runtime.h>
#include <cuda_fp16.h>
#include <cstdint>
#include <math.h>

#define Bn   2
#define Cc   64
#define Hh   224
#define Ww   224
#define HW   (Hh*Ww)
#define NOFF 27
#define COUT 64
#define Jdim 576
#define NCH  9             // chunks == k2 values (k2-major K ordering)
#define TILE 128           // kernel1 tile
#define M2   128           // kernel2 tile
#define NT   (HW/TILE)     // 392
#define NT2  (HW/M2)       // 392
#define VSTR 72            // padded k-stride (elems); 144B rows -> LDSM conflict-free
#define OSTR 132           // epilogue pos-stride

// ---------------- device globals (no allocation allowed) -------------------
__device__ float g_offmask[Bn*NOFF*HW];                 // conv1 out (mask sigmoided)
__device__ __align__(16) __half g_xt[(size_t)Bn*HW*Cc]; // x transposed fp16: [b][hw][c]
__device__ __align__(16) __half g_wd[NCH][COUT*64];     // deform W fp16 [k2][co][c]
__device__ __align__(16) __half g_wo[NCH][32*64];       // off/mask W fp16 (padded 32 ch)

// ---------------- PTX helpers ------------------------------------------------
__device__ __forceinline__ void mma_f16(float* c, const uint32_t* a,
                                        uint32_t b0, uint32_t b1) {
    asm volatile("mma.sync.aligned.m16n8k16.row.col.f32.f16.f16.f32 "
        "{%0,%1,%2,%3},{%4,%5,%6,%7},{%8,%9},{%0,%1,%2,%3};"
        : "+f"(c[0]), "+f"(c[1]), "+f"(c[2]), "+f"(c[3])
        : "r"(a[0]), "r"(a[1]), "r"(a[2]), "r"(a[3]), "r"(b0), "r"(b1));
}
#define LDSM_X4(r, addr) \
    asm volatile("ldmatrix.sync.aligned.m8n8.x4.shared.b16 {%0,%1,%2,%3}, [%4];" \
        : "=r"((r)[0]), "=r"((r)[1]), "=r"((r)[2]), "=r"((r)[3]) : "r"(addr))

__device__ __forceinline__ uint32_t smem_u32(const void* p) {
    uint32_t a;
    asm("{ .reg .u64 t; cvta.to.shared.u64 t, %1; cvt.u32.u64 %0, t; }" : "=r"(a) : "l"(p));
    return a;
}

// ---------------- prep: weights fp16, k2-major K ----------------------------
__global__ void prep_weights(const float* __restrict__ w_off,
                             const float* __restrict__ w_mask,
                             const float* __restrict__ w_def) {
    int idx = blockIdx.x * 256 + threadIdx.x;
    if (idx < NCH*COUT*64) {
        int kc = idx / (COUT*64), r = idx % (COUT*64);
        int co = r >> 6, c = r & 63;
        g_wd[kc][r] = __float2half(w_def[co*Jdim + c*9 + kc]);
    } else {
        int i2 = idx - NCH*COUT*64;
        if (i2 < NCH*32*64) {
            int kc = i2 / (32*64), r = i2 % (32*64);
            int co = r >> 6, c = r & 63;
            float v = 0.f;
            if (co < 18)      v = w_off[co*Jdim + c*9 + kc];
            else if (co < 27) v = w_mask[(co-18)*Jdim + c*9 + kc];
            g_wo[kc][r] = __float2half(v);
        }
    }
}

// ---------------- transpose x: [b][c][hw] fp32 -> [b][hw][c] fp16 -----------
__global__ void __launch_bounds__(512) transpose_x(const float* __restrict__ x) {
    __shared__ float tile[64][33];
    const int hw0 = blockIdx.x * 32;
    const int b   = blockIdx.y;
    const int l = threadIdx.x & 31, w = threadIdx.x >> 5;   // w 0..15
    const float* xb = x + (size_t)b*Cc*HW;
    #pragma unroll
    for (int i = 0; i < 4; i++) {
        int c = w + 16*i;
        tile[c][l] = xb[(size_t)c*HW + hw0 + l];
    }
    __syncthreads();
    const int c2 = (threadIdx.x & 31) * 2;
    const int hq = threadIdx.x >> 5;    // 0..15
    __half* xt = g_xt + (size_t)b*HW*64;
    #pragma unroll
    for (int i = 0; i < 2; i++) {
        int hw = hq + 16*i;
        __half2 hh = __floats2half2_rn(tile[c2][hw], tile[c2+1][hw]);
        *(__half2*)(xt + (size_t)(hw0 + hw)*64 + c2) = hh;
    }
}

// ============================================================================
// Kernel 1: offset+mask conv (27ch, padded 32), fp16 mma.sync + ldmatrix.
// 128pos x 32co, 16 warps 8m x 2n. Gather = uint4 copy from x_t.
// ============================================================================
#define S1_HO 0
#define S1_WO 512
#define S1_V  1024                       // [2buf][128][VSTR] fp16 = 36864
#define S1_W  (S1_V + 36864)             // [2buf][32][VSTR] fp16 = 9216
#define S1_TOT (S1_W + 9216)             // 47104

__global__ void __launch_bounds__(512, 2) offmask_conv(
        const float* __restrict__ b_off,
        const float* __restrict__ b_mask) {
    extern __shared__ char smem[];
    const int tid = threadIdx.x, lane = tid & 31, wid = tid >> 5;
    const int hw0 = blockIdx.x * TILE;
    const int b   = blockIdx.y;
    const __half* xt = g_xt + (size_t)b * HW * 64;
    const uint32_t sb = smem_u32(smem);

    int* sHO = (int*)(smem + S1_HO);
    int* sWO = (int*)(smem + S1_WO);
    if (tid < TILE) {
        int hw = hw0 + tid, ho = hw / Ww;
        sHO[tid] = ho; sWO[tid] = hw - ho*Ww;
    }
    __syncthreads();

    const int q  = lane >> 3;           // 0..3 pos group
    const int c0 = (lane & 7) * 8;      // 8-channel group

    auto stage = [&](int kc, int buf) {
        __half* vh = (__half*)(smem + S1_V) + buf*(TILE*VSTR);
        const int ky = kc / 3, kx = kc - ky*3;
        #pragma unroll
        for (int tp = 0; tp < 2; tp++) {
            int pos = (wid << 3) + tp*4 + q;
            int iy = sHO[pos] + ky - 1;
            int ix = sWO[pos] + kx - 1;
            uint4 a = make_uint4(0u, 0u, 0u, 0u);
            if (((unsigned)iy < Hh) && ((unsigned)ix < Ww))
                a = *(const uint4*)(xt + (size_t)(iy*Ww + ix)*64 + c0);
            *(uint4*)(vh + pos*VSTR + c0) = a;
        }
        const uint32_t* src = (const uint32_t*)(&g_wo[kc][0]);   // 1024 b32
        uint32_t* wd = (uint32_t*)(smem + S1_W) + buf*(32*VSTR/2);
        #pragma unroll
        for (int i = 0; i < 2; i++) {
            int idx = tid + i*512;
            int r = idx >> 5, w = idx & 31;
            wd[r*(VSTR/2) + w] = src[idx];
        }
    };

    const int R  = (wid >> 1) * 16;
    const int NB = (wid & 1) * 16;
    // ldmatrix per-lane byte offsets (element*2)
    const uint32_t aoff = ((R + (lane & 15))*VSTR + ((lane >> 4) << 3)) * 2;
    const uint32_t boff = ((NB + ((lane >> 4) << 3) + (lane & 7))*VSTR
                           + (((lane >> 3) & 1) << 3)) * 2;
    float acc[2][4] = {};

    stage(0, 0);
    __syncthreads();

    for (int kc = 0; kc < NCH; kc++) {
        int cb = kc & 1;
        if (kc < NCH-1) stage(kc+1, cb ^ 1);
        uint32_t vB = sb + S1_V + cb*(TILE*VSTR*2);
        uint32_t wB = sb + S1_W + cb*(32*VSTR*2);
        #pragma unroll
        for (int ks = 0; ks < 4; ks++) {
            uint32_t ah[4], bb[4];
            LDSM_X4(ah, vB + aoff + ks*32);
            LDSM_X4(bb, wB + boff + ks*32);
            mma_f16(acc[0], ah, bb[0], bb[1]);
            mma_f16(acc[1], ah, bb[2], bb[3]);
        }
        __syncthreads();
    }

    const int g = lane >> 2, tig = lane & 3;
    float* obuf = (float*)(smem + S1_V);
    #pragma unroll
    for (int t = 0; t < 2; t++) {
        int n0 = NB + t*8 + 2*tig;
        obuf[(n0    )*OSTR + R+g    ] = acc[t][0];
        obuf[(n0 + 1)*OSTR + R+g    ] = acc[t][1];
        obuf[(n0    )*OSTR + R+g + 8] = acc[t][2];
        obuf[(n0 + 1)*OSTR + R+g + 8] = acc[t][3];
    }
    __syncthreads();
    float* ob = g_offmask + (size_t)b*NOFF*HW + hw0;
    for (int i = tid; i < NOFF*TILE; i += 512) {
        int co = i >> 7, pos = i & 127;
        float v = obuf[co*OSTR + pos] + (co < 18 ? b_off[co] : b_mask[co-18]);
        if (co >= 18) v = 1.f / (1.f + __expf(-v));
        ob[co*HW + pos] = v;
    }
}

// ============================================================================
// Kernel 2: bilinear gather (half2 math) + main GEMM, fp16 mma.sync + ldmatrix.
// 128pos x 64co, 16 warps 4m x 4n.
// ============================================================================
#define S2_PI 0                          // int4 [9*128]  = 18432
#define S2_PW 18432                      // uint4 half2-packed weights = 18432
#define S2_V  36864                      // [2buf][128][VSTR] fp16 = 36864
#define S2_W  73728                      // [2buf][64][VSTR] fp16 = 18432
#define S2_TOT 92160

__global__ void __launch_bounds__(512, 2) deform_main(
        float* __restrict__ out) {
    extern __shared__ char smem[];
    const int tid = threadIdx.x, lane = tid & 31, wid = tid >> 5;
    const int hw0 = blockIdx.x * M2;
    const int b   = blockIdx.y;
    const __half* xt = g_xt + (size_t)b * HW * 64;
    const uint32_t sb = smem_u32(smem);

    int4*  pI  = (int4*) (smem + S2_PI);
    uint4* pWh = (uint4*)(smem + S2_PW);

    // phase 0: clamped corner indices + half2-packed validity/mask weights
    for (int i = tid; i < 9*M2; i += 512) {
        int pos = i & 127;
        int k2  = i >> 7;
        int hw  = hw0 + pos;
        int ho  = hw / Ww;
        int wo  = hw - ho*Ww;
        const float* om = g_offmask + (size_t)b*NOFF*HW + hw;
        float dy = om[(2*k2    )*HW];
        float dx = om[(2*k2 + 1)*HW];
        float m  = om[(18 + k2 )*HW];
        int ky = k2 / 3, kx = k2 - ky*3;
        float py = dy + (float)(ho - 1 + ky);
        float px = dx + (float)(wo - 1 + kx);
        float fy = floorf(py), fx = floorf(px);
        float wy1 = py - fy, wx1 = px - fx;
        float wy0 = 1.f - wy1, wx0 = 1.f - wx1;
        int y0 = (int)fy, x0 = (int)fx;
        int y1 = y0 + 1,  x1 = x0 + 1;
        float vy0 = ((unsigned)y0 < Hh) ? 1.f : 0.f;
        float vy1 = ((unsigned)y1 < Hh) ? 1.f : 0.f;
        float vx0 = ((unsigned)x0 < Ww) ? 1.f : 0.f;
        float vx1 = ((unsigned)x1 < Ww) ? 1.f : 0.f;
        int y0c = min(max(y0, 0), Hh-1), y1c = min(max(y1, 0), Hh-1);
        int x0c = min(max(x0, 0), Ww-1), x1c = min(max(x1, 0), Ww-1);
        pI[i] = make_int4(y0c*Ww + x0c, y0c*Ww + x1c,
                          y1c*Ww + x0c, y1c*Ww + x1c);
        __half2 h0 = __float2half2_rn(wy0*wx0*m*vy0*vx0);
        __half2 h1 = __float2half2_rn(wy0*wx1*m*vy0*vx1);
        __half2 h2 = __float2half2_rn(wy1*wx0*m*vy1*vx0);
        __half2 h3 = __float2half2_rn(wy1*wx1*m*vy1*vx1);
        uint4 wp;
        wp.x = *(uint32_t*)&h0; wp.y = *(uint32_t*)&h1;
        wp.z = *(uint32_t*)&h2; wp.w = *(uint32_t*)&h3;
        pWh[i] = wp;
    }
    __syncthreads();

    const int q  = lane >> 3;          // 0..3 pos group
    const int c0 = (lane & 7) * 8;     // 8-channel group

    // gather: quarter-warp per pos; LDG.128 per corner; half2 bilinear
    auto stage = [&](int kc, int buf) {
        __half* vh = (__half*)(smem + S2_V) + buf*(M2*VSTR);
        #pragma unroll
        for (int tp = 0; tp < 2; tp++) {
            int pos = (wid << 3) + tp*4 + q;
            int pk = (kc << 7) | pos;
            int4  id = pI[pk];
            uint4 wp = pWh[pk];
            __half2 w0 = *(__half2*)&wp.x, w1 = *(__half2*)&wp.y;
            __half2 w2 = *(__half2*)&wp.z, w3 = *(__half2*)&wp.w;
            uint4 r0 = *(const uint4*)(xt + (size_t)id.x*64 + c0);
            uint4 r1 = *(const uint4*)(xt + (size_t)id.y*64 + c0);
            uint4 r2 = *(const uint4*)(xt + (size_t)id.z*64 + c0);
            uint4 r3 = *(const uint4*)(xt + (size_t)id.w*64 + c0);
            uint4 o;
            #pragma unroll
            for (int j = 0; j < 4; j++) {
                __half2 v = __hmul2(w0, ((__half2*)&r0)[j]);
                v = __hfma2(w1, ((__half2*)&r1)[j], v);
                v = __hfma2(w2, ((__half2*)&r2)[j], v);
                v = __hfma2(w3, ((__half2*)&r3)[j], v);
                ((__half2*)&o)[j] = v;
            }
            *(uint4*)(vh + pos*VSTR + c0) = o;
        }
        const uint32_t* src = (const uint32_t*)(&g_wd[kc][0]);   // 2048 b32
        uint32_t* wd = (uint32_t*)(smem + S2_W) + buf*(64*VSTR/2);
        #pragma unroll
        for (int i = 0; i < 4; i++) {
            int idx = tid + i*512;
            int r = idx >> 5, w2i = idx & 31;
            wd[r*(VSTR/2) + w2i] = src[idx];
        }
    };

    const int R  = (wid >> 2) * 32;    // 4 m-tiles of 32 pos
    const int NB = (wid & 3) * 16;     // 4 n-tiles of 16 co
    const uint32_t aoff0 = ((R + (lane & 15))*VSTR + ((lane >> 4) << 3)) * 2;
    const uint32_t aoff1 = aoff0 + 16*VSTR*2;
    const uint32_t boff  = ((NB + ((lane >> 4) << 3) + (lane & 7))*VSTR
                            + (((lane >> 3) & 1) << 3)) * 2;
    float acc[2][2][4] = {};

    stage(0, 0);
    __syncthreads();

    for (int kc = 0; kc < NCH; kc++) {
        int cb = kc & 1;
        if (kc < NCH-1) stage(kc+1, cb ^ 1);
        uint32_t vB = sb + S2_V + cb*(M2*VSTR*2);
        uint32_t wB = sb + S2_W + cb*(64*VSTR*2);
        #pragma unroll
        for (int ks = 0; ks < 4; ks++) {
            uint32_t ah0[4], ah1[4], bb[4];
            LDSM_X4(ah0, vB + aoff0 + ks*32);
            LDSM_X4(ah1, vB + aoff1 + ks*32);
            LDSM_X4(bb,  wB + boff  + ks*32);
            mma_f16(acc[0][0], ah0, bb[0], bb[1]);
            mma_f16(acc[0][1], ah0, bb[2], bb[3]);
            mma_f16(acc[1][0], ah1, bb[0], bb[1]);
            mma_f16(acc[1][1], ah1, bb[2], bb[3]);
        }
        __syncthreads();
    }

    // epilogue: stage [64co][128pos] f32, then coalesced stores
    const int g = lane >> 2, tig = lane & 3;
    float* obuf = (float*)(smem + S2_V);
    #pragma unroll
    for (int mi = 0; mi < 2; mi++) {
        #pragma unroll
        for (int ni = 0; ni < 2; ni++) {
            int n0 = NB + ni*8 + 2*tig;
            int po = R + mi*16 + g;
            obuf[(n0    )*OSTR + po    ] = acc[mi][ni][0];
            obuf[(n0 + 1)*OSTR + po    ] = acc[mi][ni][1];
            obuf[(n0    )*OSTR + po + 8] = acc[mi][ni][2];
            obuf[(n0 + 1)*OSTR + po + 8] = acc[mi][ni][3];
        }
    }
    __syncthreads();
    float* ob = out + (size_t)b*COUT*HW + hw0;
    #pragma unroll
    for (int i = tid; i < COUT*32; i += 512) {
        int co = i >> 5, q2 = i & 31;
        float4 v = *(float4*)&obuf[co*OSTR + q2*4];
        *(float4*)&ob[co*HW + q2*4] = v;
    }
}

// ---------------------------------------------------------------------------
extern "C" void kernel_launch(void* const* d_in, const int* in_sizes, int n_in,
                              void* d_out, int out_size) {
    const float* x      = (const float*)d_in[0];
    const float* w_off  = (const float*)d_in[1];
    const float* b_off  = (const float*)d_in[2];
    const float* w_mask = (const float*)d_in[3];
    const float* b_mask = (const float*)d_in[4];
    const float* w_def  = (const float*)d_in[5];
    float* out = (float*)d_out;

    cudaFuncSetAttribute(offmask_conv, cudaFuncAttributeMaxDynamicSharedMemorySize, S1_TOT);
    cudaFuncSetAttribute(deform_main,  cudaFuncAttributeMaxDynamicSharedMemorySize, S2_TOT);

    prep_weights<<<216, 256>>>(w_off, w_mask, w_def);
    transpose_x<<<dim3(HW/32, Bn), 512>>>(x);
    offmask_conv<<<dim3(NT, Bn), 512, S1_TOT>>>(b_off, b_mask);
    deform_main <<<dim3(NT2, Bn), 512, S2_TOT>>>(out);
}

// round 15
// speedup vs baseline: 8.8970x; 1.0131x over previous
#include <cuda_runtime.h>
#include <cuda_fp16.h>
#include <cstdint>
#include <math.h>

#define Bn   2
#define Cc   64
#define Hh   224
#define Ww   224
#define HW   (Hh*Ww)
#define NOFF 27
#define COUT 64
#define Jdim 576
#define NCH  9             // chunks == k2 values (k2-major K ordering)
#define TILE 128
#define NT   (HW/TILE)     // 392
#define VSTR 72            // padded k-stride (elems); 144B rows -> LDSM conflict-free
#define OSTR 132           // staging pos-stride

// ---------------- device globals (no allocation allowed) -------------------
__device__ __align__(16) __half g_xt[(size_t)Bn*HW*Cc]; // x transposed fp16: [b][hw][c]
__device__ __align__(16) __half g_wd[NCH][COUT*64];     // deform W fp16 [k2][co][c]
__device__ __align__(16) __half g_wo[NCH][32*64];       // off/mask W fp16 (padded 32 ch)

// ---------------- PTX helpers ------------------------------------------------
__device__ __forceinline__ void mma_f16(float* c, const uint32_t* a,
                                        uint32_t b0, uint32_t b1) {
    asm volatile("mma.sync.aligned.m16n8k16.row.col.f32.f16.f16.f32 "
        "{%0,%1,%2,%3},{%4,%5,%6,%7},{%8,%9},{%0,%1,%2,%3};"
        : "+f"(c[0]), "+f"(c[1]), "+f"(c[2]), "+f"(c[3])
        : "r"(a[0]), "r"(a[1]), "r"(a[2]), "r"(a[3]), "r"(b0), "r"(b1));
}
#define LDSM_X4(r, addr) \
    asm volatile("ldmatrix.sync.aligned.m8n8.x4.shared.b16 {%0,%1,%2,%3}, [%4];" \
        : "=r"((r)[0]), "=r"((r)[1]), "=r"((r)[2]), "=r"((r)[3]) : "r"(addr))

__device__ __forceinline__ uint32_t smem_u32(const void* p) {
    uint32_t a;
    asm("{ .reg .u64 t; cvta.to.shared.u64 t, %1; cvt.u32.u64 %0, t; }" : "=r"(a) : "l"(p));
    return a;
}

// ---------------- transpose x (+ fold in weight prep on b==0 blocks) --------
__global__ void __launch_bounds__(512) transpose_x(
        const float* __restrict__ x,
        const float* __restrict__ w_off,
        const float* __restrict__ w_mask,
        const float* __restrict__ w_def) {
    __shared__ float tile[64][33];
    const int hw0 = blockIdx.x * 32;
    const int b   = blockIdx.y;

    // weight prep folded in (total items 9*64*64 + 9*32*64 = 55296 = 108*512)
    if (b == 0 && blockIdx.x < 108) {
        int idx = blockIdx.x * 512 + threadIdx.x;
        if (idx < NCH*COUT*64) {
            int kc = idx / (COUT*64), r = idx % (COUT*64);
            int co = r >> 6, c = r & 63;
            g_wd[kc][r] = __float2half(w_def[co*Jdim + c*9 + kc]);
        } else {
            int i2 = idx - NCH*COUT*64;
            int kc = i2 / (32*64), r = i2 % (32*64);
            int co = r >> 6, c = r & 63;
            float v = 0.f;
            if (co < 18)      v = w_off[co*Jdim + c*9 + kc];
            else if (co < 27) v = w_mask[(co-18)*Jdim + c*9 + kc];
            g_wo[kc][r] = __float2half(v);
        }
    }

    const int l = threadIdx.x & 31, w = threadIdx.x >> 5;   // w 0..15
    const float* xb = x + (size_t)b*Cc*HW;
    #pragma unroll
    for (int i = 0; i < 4; i++) {
        int c = w + 16*i;
        tile[c][l] = xb[(size_t)c*HW + hw0 + l];
    }
    __syncthreads();
    const int c2 = (threadIdx.x & 31) * 2;
    const int hq = threadIdx.x >> 5;    // 0..15
    __half* xt = g_xt + (size_t)b*HW*64;
    #pragma unroll
    for (int i = 0; i < 2; i++) {
        int hw = hq + 16*i;
        __half2 hh = __floats2half2_rn(tile[c2][hw], tile[c2+1][hw]);
        *(__half2*)(xt + (size_t)(hw0 + hw)*64 + c2) = hh;
    }
}

// ============================================================================
// Fused kernel: offset/mask conv (phase A) -> bilinear params (phase B)
//               -> gather + main GEMM (phase C).  128 pos per CTA.
// ============================================================================
#define F_HO  0
#define F_WO  512
#define F_OM  1024                      // float [32][OSTR]      = 16896
#define F_PI  17920                     // int4  [9*128]         = 18432
#define F_PW  36352                     // uint4 half2 weights   = 18432
#define F_V   54784                     // [2buf][128][VSTR] f16 = 36864
#define F_W   91648                     // [2buf][64][VSTR] f16  = 18432
#define F_TOT 110080

__global__ void __launch_bounds__(512, 2) fused_deform(
        const float* __restrict__ b_off,
        const float* __restrict__ b_mask,
        float* __restrict__ out) {
    extern __shared__ char smem[];
    const int tid = threadIdx.x, lane = tid & 31, wid = tid >> 5;
    const int hw0 = blockIdx.x * TILE;
    const int b   = blockIdx.y;
    const __half* xt = g_xt + (size_t)b * HW * 64;
    const uint32_t sb = smem_u32(smem);

    int* sHO = (int*)(smem + F_HO);
    int* sWO = (int*)(smem + F_WO);
    if (tid < TILE) {
        int hw = hw0 + tid, ho = hw / Ww;
        sHO[tid] = ho; sWO[tid] = hw - ho*Ww;
    }
    __syncthreads();

    const int q  = lane >> 3;           // 0..3 pos group
    const int c0 = (lane & 7) * 8;      // 8-channel group

    // ======================= PHASE A: offset/mask conv ======================
    {
        auto stageA = [&](int kc, int buf) {
            __half* vh = (__half*)(smem + F_V) + buf*(TILE*VSTR);
            const int ky = kc / 3, kx = kc - ky*3;
            #pragma unroll
            for (int tp = 0; tp < 2; tp++) {
                int pos = (wid << 3) + tp*4 + q;
                int iy = sHO[pos] + ky - 1;
                int ix = sWO[pos] + kx - 1;
                uint4 a = make_uint4(0u, 0u, 0u, 0u);
                if (((unsigned)iy < Hh) && ((unsigned)ix < Ww))
                    a = *(const uint4*)(xt + (size_t)(iy*Ww + ix)*64 + c0);
                *(uint4*)(vh + pos*VSTR + c0) = a;
            }
            const uint32_t* src = (const uint32_t*)(&g_wo[kc][0]);   // 1024 b32
            uint32_t* wd = (uint32_t*)(smem + F_W) + buf*(32*VSTR/2);
            #pragma unroll
            for (int i = 0; i < 2; i++) {
                int idx = tid + i*512;
                int r = idx >> 5, w = idx & 31;
                wd[r*(VSTR/2) + w] = src[idx];
            }
        };

        const int R  = (wid >> 1) * 16;
        const int NB = (wid & 1) * 16;
        const uint32_t aoff = ((R + (lane & 15))*VSTR + ((lane >> 4) << 3)) * 2;
        const uint32_t boff = ((NB + ((lane >> 4) << 3) + (lane & 7))*VSTR
                               + (((lane >> 3) & 1) << 3)) * 2;
        float acc[2][4] = {};

        stageA(0, 0);
        __syncthreads();

        for (int kc = 0; kc < NCH; kc++) {
            int cb = kc & 1;
            if (kc < NCH-1) stageA(kc+1, cb ^ 1);
            uint32_t vB = sb + F_V + cb*(TILE*VSTR*2);
            uint32_t wB = sb + F_W + cb*(32*VSTR*2);
            #pragma unroll
            for (int ks = 0; ks < 4; ks++) {
                uint32_t ah[4], bb[4];
                LDSM_X4(ah, vB + aoff + ks*32);
                LDSM_X4(bb, wB + boff + ks*32);
                mma_f16(acc[0], ah, bb[0], bb[1]);
                mma_f16(acc[1], ah, bb[2], bb[3]);
            }
            __syncthreads();
        }

        // stage conv result into OM (smem-resident)
        const int g = lane >> 2, tig = lane & 3;
        float* OM = (float*)(smem + F_OM);
        #pragma unroll
        for (int t = 0; t < 2; t++) {
            int n0 = NB + t*8 + 2*tig;
            OM[(n0    )*OSTR + R+g    ] = acc[t][0];
            OM[(n0 + 1)*OSTR + R+g    ] = acc[t][1];
            OM[(n0    )*OSTR + R+g + 8] = acc[t][2];
            OM[(n0 + 1)*OSTR + R+g + 8] = acc[t][3];
        }
        __syncthreads();
        // bias + sigmoid in place
        for (int i = tid; i < NOFF*TILE; i += 512) {
            int co = i >> 7, pos = i & 127;
            float v = OM[co*OSTR + pos] + (co < 18 ? b_off[co] : b_mask[co-18]);
            if (co >= 18) v = 1.f / (1.f + __expf(-v));
            OM[co*OSTR + pos] = v;
        }
        __syncthreads();
    }

    // ======================= PHASE B: bilinear params =======================
    {
        const float* OM = (const float*)(smem + F_OM);
        int4*  pI  = (int4*) (smem + F_PI);
        uint4* pWh = (uint4*)(smem + F_PW);
        for (int i = tid; i < 9*TILE; i += 512) {
            int pos = i & 127;
            int k2  = i >> 7;
            float dy = OM[(2*k2    )*OSTR + pos];
            float dx = OM[(2*k2 + 1)*OSTR + pos];
            float m  = OM[(18 + k2 )*OSTR + pos];
            int ky = k2 / 3, kx = k2 - ky*3;
            float py = dy + (float)(sHO[pos] - 1 + ky);
            float px = dx + (float)(sWO[pos] - 1 + kx);
            float fy = floorf(py), fx = floorf(px);
            float wy1 = py - fy, wx1 = px - fx;
            float wy0 = 1.f - wy1, wx0 = 1.f - wx1;
            int y0 = (int)fy, x0 = (int)fx;
            int y1 = y0 + 1,  x1 = x0 + 1;
            float vy0 = ((unsigned)y0 < Hh) ? 1.f : 0.f;
            float vy1 = ((unsigned)y1 < Hh) ? 1.f : 0.f;
            float vx0 = ((unsigned)x0 < Ww) ? 1.f : 0.f;
            float vx1 = ((unsigned)x1 < Ww) ? 1.f : 0.f;
            int y0c = min(max(y0, 0), Hh-1), y1c = min(max(y1, 0), Hh-1);
            int x0c = min(max(x0, 0), Ww-1), x1c = min(max(x1, 0), Ww-1);
            pI[i] = make_int4(y0c*Ww + x0c, y0c*Ww + x1c,
                              y1c*Ww + x0c, y1c*Ww + x1c);
            __half2 h0 = __float2half2_rn(wy0*wx0*m*vy0*vx0);
            __half2 h1 = __float2half2_rn(wy0*wx1*m*vy0*vx1);
            __half2 h2 = __float2half2_rn(wy1*wx0*m*vy1*vx0);
            __half2 h3 = __float2half2_rn(wy1*wx1*m*vy1*vx1);
            uint4 wp;
            wp.x = *(uint32_t*)&h0; wp.y = *(uint32_t*)&h1;
            wp.z = *(uint32_t*)&h2; wp.w = *(uint32_t*)&h3;
            pWh[i] = wp;
        }
        __syncthreads();
    }

    // ======================= PHASE C: gather + main GEMM ====================
    int4*  pI  = (int4*) (smem + F_PI);
    uint4* pWh = (uint4*)(smem + F_PW);

    auto stageC = [&](int kc, int buf) {
        __half* vh = (__half*)(smem + F_V) + buf*(TILE*VSTR);
        #pragma unroll
        for (int tp = 0; tp < 2; tp++) {
            int pos = (wid << 3) + tp*4 + q;
            int pk = (kc << 7) | pos;
            int4  id = pI[pk];
            uint4 wp = pWh[pk];
            __half2 w0 = *(__half2*)&wp.x, w1 = *(__half2*)&wp.y;
            __half2 w2 = *(__half2*)&wp.z, w3 = *(__half2*)&wp.w;
            uint4 r0 = *(const uint4*)(xt + (size_t)id.x*64 + c0);
            uint4 r1 = *(const uint4*)(xt + (size_t)id.y*64 + c0);
            uint4 r2 = *(const uint4*)(xt + (size_t)id.z*64 + c0);
            uint4 r3 = *(const uint4*)(xt + (size_t)id.w*64 + c0);
            uint4 o;
            #pragma unroll
            for (int j = 0; j < 4; j++) {
                __half2 v = __hmul2(w0, ((__half2*)&r0)[j]);
                v = __hfma2(w1, ((__half2*)&r1)[j], v);
                v = __hfma2(w2, ((__half2*)&r2)[j], v);
                v = __hfma2(w3, ((__half2*)&r3)[j], v);
                ((__half2*)&o)[j] = v;
            }
            *(uint4*)(vh + pos*VSTR + c0) = o;
        }
        const uint32_t* src = (const uint32_t*)(&g_wd[kc][0]);   // 2048 b32
        uint32_t* wd = (uint32_t*)(smem + F_W) + buf*(64*VSTR/2);
        #pragma unroll
        for (int i = 0; i < 4; i++) {
            int idx = tid + i*512;
            int r = idx >> 5, w2i = idx & 31;
            wd[r*(VSTR/2) + w2i] = src[idx];
        }
    };

    const int R  = (wid >> 2) * 32;    // 4 m-tiles of 32 pos
    const int NB = (wid & 3) * 16;     // 4 n-tiles of 16 co
    const uint32_t aoff0 = ((R + (lane & 15))*VSTR + ((lane >> 4) << 3)) * 2;
    const uint32_t aoff1 = aoff0 + 16*VSTR*2;
    const uint32_t boff  = ((NB + ((lane >> 4) << 3) + (lane & 7))*VSTR
                            + (((lane >> 3) & 1) << 3)) * 2;
    float acc[2][2][4] = {};

    stageC(0, 0);
    __syncthreads();

    for (int kc = 0; kc < NCH; kc++) {
        int cb = kc & 1;
        if (kc < NCH-1) stageC(kc+1, cb ^ 1);
        uint32_t vB = sb + F_V + cb*(TILE*VSTR*2);
        uint32_t wB = sb + F_W + cb*(64*VSTR*2);
        #pragma unroll
        for (int ks = 0; ks < 4; ks++) {
            uint32_t ah0[4], ah1[4], bb[4];
            LDSM_X4(ah0, vB + aoff0 + ks*32);
            LDSM_X4(ah1, vB + aoff1 + ks*32);
            LDSM_X4(bb,  wB + boff  + ks*32);
            mma_f16(acc[0][0], ah0, bb[0], bb[1]);
            mma_f16(acc[0][1], ah0, bb[2], bb[3]);
            mma_f16(acc[1][0], ah1, bb[0], bb[1]);
            mma_f16(acc[1][1], ah1, bb[2], bb[3]);
        }
        __syncthreads();
    }

    // epilogue: stage [64co][128pos] f32, then coalesced stores
    const int g = lane >> 2, tig = lane & 3;
    float* obuf = (float*)(smem + F_V);
    #pragma unroll
    for (int mi = 0; mi < 2; mi++) {
        #pragma unroll
        for (int ni = 0; ni < 2; ni++) {
            int n0 = NB + ni*8 + 2*tig;
            int po = R + mi*16 + g;
            obuf[(n0    )*OSTR + po    ] = acc[mi][ni][0];
            obuf[(n0 + 1)*OSTR + po    ] = acc[mi][ni][1];
            obuf[(n0    )*OSTR + po + 8] = acc[mi][ni][2];
            obuf[(n0 + 1)*OSTR + po + 8] = acc[mi][ni][3];
        }
    }
    __syncthreads();
    float* ob = out + (size_t)b*COUT*HW + hw0;
    #pragma unroll
    for (int i = tid; i < COUT*32; i += 512) {
        int co = i >> 5, q2 = i & 31;
        float4 v = *(float4*)&obuf[co*OSTR + q2*4];
        *(float4*)&ob[co*HW + q2*4] = v;
    }
}

// ---------------------------------------------------------------------------
extern "C" void kernel_launch(void* const* d_in, const int* in_sizes, int n_in,
                              void* d_out, int out_size) {
    const float* x      = (const float*)d_in[0];
    const float* w_off  = (const float*)d_in[1];
    const float* b_off  = (const float*)d_in[2];
    const float* w_mask = (const float*)d_in[3];
    const float* b_mask = (const float*)d_in[4];
    const float* w_def  = (const float*)d_in[5];
    float* out = (float*)d_out;

    cudaFuncSetAttribute(fused_deform, cudaFuncAttributeMaxDynamicSharedMemorySize, F_TOT);

    transpose_x<<<dim3(HW/32, Bn), 512>>>(x, w_off, w_mask, w_def);
    fused_deform<<<dim3(NT, Bn), 512, F_TOT>>>(b_off, b_mask, out);
}